// round 1
// baseline (speedup 1.0000x reference)
#include <cuda_runtime.h>
#include <math.h>

// ---------------------------------------------------------------------------
// GPNN_VCOCO forward, fp32 baseline.
// B=16, N=64, D=E=MSG=LINK_H=512, P=2, HOI=26, ROLES=2.
//
// Pipeline (all on default stream, graph-capturable, no allocations):
//   init_pa                      : pa1 = blo, out[0:65536] = blo (atomic dot targets)
//   gemm<BIAS>   (1024x512)      : Hn = NF @ Wm[:, :512]^T + bm
//   gemm<MFUSE>  (65536x512)     : M  = relu(EF @ Wm[:,512:]^T + Hn[b,w])
//   gemm<RELU>   (65536x512)     : T1 = relu(EF @ Wl1^T + bl1)
//   gemm<DOT>    (65536x512)     : pa1 += dot(relu(T1 @ Wl2^T + bl2), Wlo)  [atomic]
//   gemm<RELU,PERM>(65536x512)   : T1 = relu( (sig(pa1[b,w,v]) * M[b,w,v,:]) @ Wl1^T + bl1)
//   gemm<DOT>    (65536x512)     : out[pred_adj] += dot(relu(T1 @ Wl2^T + bl2), Wlo)
//   msum                         : msum[b,v,:] = sum_w sig(pa2[b,v,w]) * M[b,v,w,:]
//   gemm<BIAS>   (1024x1536)     : GI = msum @ W_ih^T + b_ih
//   gemm<BIAS>   (1024x1536)     : GH = NF   @ W_hh^T + b_hh
//   gru_readout                  : gates -> h_new -> labels/roles
// ---------------------------------------------------------------------------

namespace {

constexpr int Bb   = 16;
constexpr int Nn   = 64;
constexpr int Cc   = 512;
constexpr int Rr   = Bb * Nn * Nn;   // 65536 edge rows

enum { EPI_BIAS = 0, EPI_RELU = 1, EPI_MFUSE = 2, EPI_DOT = 3 };

// Scratch (static device globals: allocation-free at launch time)
__device__ float g_M  [Rr * Cc];          // messages  [ (b,v,w), m ]
__device__ float g_T1 [Rr * Cc];          // link hidden
__device__ float g_Hn [Bb * Nn * Cc];     // node part of message preact (incl. bm)
__device__ float g_pa1[Rr];               // link round-1 logits
__device__ float g_ms [Bb * Nn * Cc];     // msum (GRU input)
__device__ float g_GI [Bb * Nn * 3 * Cc];
__device__ float g_GH [Bb * Nn * 3 * Cc];

__device__ __forceinline__ float sigmoidf_(float x) {
    return 1.0f / (1.0f + __expf(-x));
}

// C[r,n] = epilogue( sum_k A[r,k] * W[n, koff+k] ),  K = 512 fixed.
// A: rows x 512 row-major. W: Ncols rows, leading dim ldW.
// PERM: A row r=(b,v,w) is read from row (b,w,v), scaled by sig(pa1[(b,w,v)]).
// Tiles: 128x128x16, 256 threads, 8x8 per thread.
template<int EPI, bool PERM>
__global__ void __launch_bounds__(256)
gemm512(const float* __restrict__ A,
        const float* __restrict__ W, int ldW, int koff,
        const float* __restrict__ bias,
        const float* __restrict__ extra,     // Hn (MFUSE) or Wlo (DOT)
        const float* __restrict__ scale_pa,  // pa1 logits (PERM)
        float* __restrict__ Cout,
        float* __restrict__ dotOut,          // atomic target (DOT)
        int Ncols)
{
    __shared__ float As[16][128];
    __shared__ float Bs[16][128];
    __shared__ float red[128];

    const int tid = threadIdx.x;
    const int tn  = tid & 15;
    const int tm  = tid >> 4;
    const int rowBase = blockIdx.y << 7;
    const int colBase = blockIdx.x << 7;

    const int lm  = tid >> 2;   // 0..63  (row/col within tile for loads)
    const int lkq = tid & 3;    // which float4 of the 16-wide k slice

    const int gr0 = rowBase + lm;
    const int gr1 = gr0 + 64;
    int ar0, ar1;               // float4 base index of the A source rows
    float s0 = 1.0f, s1 = 1.0f;
    if (PERM) {
        int r0  = gr0 & 4095;
        int pr0 = (gr0 & ~4095) | ((r0 & 63) << 6) | (r0 >> 6);
        int r1  = gr1 & 4095;
        int pr1 = (gr1 & ~4095) | ((r1 & 63) << 6) | (r1 >> 6);
        ar0 = pr0 << 7;
        ar1 = pr1 << 7;
        s0 = sigmoidf_(scale_pa[pr0]);
        s1 = sigmoidf_(scale_pa[pr1]);
    } else {
        ar0 = gr0 << 7;
        ar1 = gr1 << 7;
    }

    const float4* A4  = reinterpret_cast<const float4*>(A);
    const float*  Wp0 = W + (size_t)(colBase + lm) * ldW + koff + (lkq << 2);
    const float*  Wp1 = Wp0 + (size_t)64 * ldW;

    float acc[8][8];
#pragma unroll
    for (int i = 0; i < 8; i++)
#pragma unroll
        for (int j = 0; j < 8; j++) acc[i][j] = 0.0f;

#pragma unroll 1
    for (int kt = 0; kt < 32; kt++) {
        float4 a0 = A4[ar0 + (kt << 2) + lkq];
        float4 a1 = A4[ar1 + (kt << 2) + lkq];
        if (PERM) {
            a0.x *= s0; a0.y *= s0; a0.z *= s0; a0.w *= s0;
            a1.x *= s1; a1.y *= s1; a1.z *= s1; a1.w *= s1;
        }
        float4 b0 = *reinterpret_cast<const float4*>(Wp0 + (kt << 4));
        float4 b1 = *reinterpret_cast<const float4*>(Wp1 + (kt << 4));

        __syncthreads();
        const int kq = lkq << 2;
        As[kq + 0][lm]      = a0.x; As[kq + 1][lm]      = a0.y;
        As[kq + 2][lm]      = a0.z; As[kq + 3][lm]      = a0.w;
        As[kq + 0][lm + 64] = a1.x; As[kq + 1][lm + 64] = a1.y;
        As[kq + 2][lm + 64] = a1.z; As[kq + 3][lm + 64] = a1.w;
        Bs[kq + 0][lm]      = b0.x; Bs[kq + 1][lm]      = b0.y;
        Bs[kq + 2][lm]      = b0.z; Bs[kq + 3][lm]      = b0.w;
        Bs[kq + 0][lm + 64] = b1.x; Bs[kq + 1][lm + 64] = b1.y;
        Bs[kq + 2][lm + 64] = b1.z; Bs[kq + 3][lm + 64] = b1.w;
        __syncthreads();

#pragma unroll
        for (int k = 0; k < 16; k++) {
            float av[8], bv[8];
            *reinterpret_cast<float4*>(&av[0]) =
                *reinterpret_cast<const float4*>(&As[k][tm << 3]);
            *reinterpret_cast<float4*>(&av[4]) =
                *reinterpret_cast<const float4*>(&As[k][(tm << 3) + 4]);
            *reinterpret_cast<float4*>(&bv[0]) =
                *reinterpret_cast<const float4*>(&Bs[k][tn << 3]);
            *reinterpret_cast<float4*>(&bv[4]) =
                *reinterpret_cast<const float4*>(&Bs[k][(tn << 3) + 4]);
#pragma unroll
            for (int i = 0; i < 8; i++)
#pragma unroll
                for (int j = 0; j < 8; j++)
                    acc[i][j] = fmaf(av[i], bv[j], acc[i][j]);
        }
    }

    if (EPI == EPI_DOT) {
        float part[8];
#pragma unroll
        for (int i = 0; i < 8; i++) part[i] = 0.0f;
#pragma unroll
        for (int j = 0; j < 8; j++) {
            const int gc = colBase + (tn << 3) + j;
            const float bj = bias[gc];
            const float wj = extra[gc];
#pragma unroll
            for (int i = 0; i < 8; i++)
                part[i] += fmaxf(acc[i][j] + bj, 0.0f) * wj;
        }
        if (tid < 128) red[tid] = 0.0f;
        __syncthreads();
#pragma unroll
        for (int i = 0; i < 8; i++)
            atomicAdd(&red[(tm << 3) + i], part[i]);
        __syncthreads();
        if (tid < 128) atomicAdd(&dotOut[rowBase + tid], red[tid]);
    } else {
#pragma unroll
        for (int i = 0; i < 8; i++) {
            const int gr = rowBase + (tm << 3) + i;
            const float* hnrow = nullptr;
            if (EPI == EPI_MFUSE) {
                const int b = gr >> 12, w = gr & 63;
                hnrow = extra + (size_t)(((b << 6) | w) * Cc) + colBase + (tn << 3);
            }
            float v[8];
#pragma unroll
            for (int j = 0; j < 8; j++) {
                const int gc = colBase + (tn << 3) + j;
                float x = acc[i][j];
                if (EPI == EPI_BIAS)  x += bias[gc];
                if (EPI == EPI_RELU)  x = fmaxf(x + bias[gc], 0.0f);
                if (EPI == EPI_MFUSE) x = fmaxf(x + hnrow[j], 0.0f);
                v[j] = x;
            }
            float4* crow = reinterpret_cast<float4*>(
                Cout + (size_t)gr * Ncols + colBase + (tn << 3));
            crow[0] = make_float4(v[0], v[1], v[2], v[3]);
            crow[1] = make_float4(v[4], v[5], v[6], v[7]);
        }
    }
}

__global__ void init_pa(float* __restrict__ pa1, float* __restrict__ pa2,
                        const float* __restrict__ blo)
{
    const int i = blockIdx.x * blockDim.x + threadIdx.x;
    if (i < Rr) {
        const float v = blo[0];
        pa1[i] = v;
        pa2[i] = v;
    }
}

// msum[b,v,m] = sum_w sig(pa2[b,v,w]) * M[(b,v,w), m]
__global__ void msum_kernel(const float* __restrict__ M,
                            const float* __restrict__ pa2,
                            float* __restrict__ msum)
{
    const int bv = blockIdx.x;          // 0..1023
    const int t  = threadIdx.x;         // 128
    const float* Mb = M + (size_t)bv * 64 * 512;
    const float* pb = pa2 + bv * 64;
    float a0 = 0.f, a1 = 0.f, a2 = 0.f, a3 = 0.f;
    for (int w = 0; w < 64; w++) {
        const float s = sigmoidf_(pb[w]);
        const float* r = Mb + w * 512;
        a0 = fmaf(s, r[t],       a0);
        a1 = fmaf(s, r[t + 128], a1);
        a2 = fmaf(s, r[t + 256], a2);
        a3 = fmaf(s, r[t + 384], a3);
    }
    float* o = msum + (size_t)bv * 512;
    o[t] = a0; o[t + 128] = a1; o[t + 256] = a2; o[t + 384] = a3;
}

// GRU gates (torch order r,z,n) + readout FCs
__global__ void gru_readout(const float* __restrict__ GI,
                            const float* __restrict__ GH,
                            const float* __restrict__ NF,
                            const float* __restrict__ Wr1, const float* __restrict__ br1,
                            const float* __restrict__ Wr2, const float* __restrict__ br2,
                            float* __restrict__ out)
{
    const int row = blockIdx.x;         // 0..1023
    __shared__ float hn[512];
    const int t = threadIdx.x;          // 256
    const float* gi = GI + (size_t)row * 1536;
    const float* gh = GH + (size_t)row * 1536;
    const float* h  = NF + (size_t)row * 512;
    for (int d = t; d < 512; d += 256) {
        const float r = sigmoidf_(gi[d] + gh[d]);
        const float z = sigmoidf_(gi[512 + d] + gh[512 + d]);
        const float n = tanhf(gi[1024 + d] + r * gh[1024 + d]);
        hn[d] = (1.0f - z) * n + z * h[d];
    }
    __syncthreads();
    const int warp = t >> 5, lane = t & 31;
    for (int o = warp; o < 28; o += 8) {
        const float* Wr = (o < 26) ? (Wr1 + o * 512) : (Wr2 + (o - 26) * 512);
        float acc = 0.0f;
        for (int k = lane; k < 512; k += 32) acc = fmaf(hn[k], Wr[k], acc);
#pragma unroll
        for (int off = 16; off; off >>= 1)
            acc += __shfl_down_sync(0xffffffffu, acc, off);
        if (lane == 0) {
            if (o < 26) out[65536 + row * 26 + o]              = acc + br1[o];
            else        out[65536 + 26624 + row * 2 + (o - 26)] = acc + br2[o - 26];
        }
    }
}

} // namespace

extern "C" void kernel_launch(void* const* d_in, const int* /*in_sizes*/, int /*n_in*/,
                              void* d_out, int /*out_size*/)
{
    const float* EF  = (const float*)d_in[0];
    const float* NF  = (const float*)d_in[1];
    // d_in[2] node_labels, d_in[3] node_roles: unused by the reference math
    const float* Wm  = (const float*)d_in[4];
    const float* bm  = (const float*)d_in[5];
    const float* Wl1 = (const float*)d_in[6];
    const float* bl1 = (const float*)d_in[7];
    const float* Wl2 = (const float*)d_in[8];
    const float* bl2 = (const float*)d_in[9];
    const float* Wlo = (const float*)d_in[10];
    const float* blo = (const float*)d_in[11];
    const float* Wih = (const float*)d_in[12];
    const float* bih = (const float*)d_in[13];
    const float* Whh = (const float*)d_in[14];
    const float* bhh = (const float*)d_in[15];
    const float* Wr1 = (const float*)d_in[16];
    const float* br1 = (const float*)d_in[17];
    const float* Wr2 = (const float*)d_in[18];
    const float* br2 = (const float*)d_in[19];
    float* out = (float*)d_out;

    float *pM, *pT1, *pHn, *pPa1, *pMs, *pGI, *pGH;
    cudaGetSymbolAddress((void**)&pM,   g_M);
    cudaGetSymbolAddress((void**)&pT1,  g_T1);
    cudaGetSymbolAddress((void**)&pHn,  g_Hn);
    cudaGetSymbolAddress((void**)&pPa1, g_pa1);
    cudaGetSymbolAddress((void**)&pMs,  g_ms);
    cudaGetSymbolAddress((void**)&pGI,  g_GI);
    cudaGetSymbolAddress((void**)&pGH,  g_GH);

    const dim3 blk(256);
    const dim3 gBig(4, 512);   // 65536 x 512
    const dim3 gHn(4, 8);      // 1024 x 512
    const dim3 gGru(12, 8);    // 1024 x 1536

    // pa1 / pred_adj accumulators start at blo
    init_pa<<<(Rr + 255) / 256, 256>>>(pPa1, out, blo);

    // Hn = NF @ Wm[:, :512]^T + bm
    gemm512<EPI_BIAS, false><<<gHn, blk>>>(NF, Wm, 1024, 0, bm,
                                           nullptr, nullptr, pHn, nullptr, Cc);
    // M = relu(EF @ Wm[:,512:]^T + Hn)
    gemm512<EPI_MFUSE, false><<<gBig, blk>>>(EF, Wm, 1024, 512, nullptr,
                                             pHn, nullptr, pM, nullptr, Cc);
    // link round 1
    gemm512<EPI_RELU, false><<<gBig, blk>>>(EF, Wl1, 512, 0, bl1,
                                            nullptr, nullptr, pT1, nullptr, Cc);
    gemm512<EPI_DOT, false><<<gBig, blk>>>(pT1, Wl2, 512, 0, bl2,
                                           Wlo, nullptr, nullptr, pPa1, Cc);
    // link round 2 (A = sig(pa1)^T-scaled, (v,w)-transposed M)
    gemm512<EPI_RELU, true><<<gBig, blk>>>(pM, Wl1, 512, 0, bl1,
                                           nullptr, pPa1, pT1, nullptr, Cc);
    gemm512<EPI_DOT, false><<<gBig, blk>>>(pT1, Wl2, 512, 0, bl2,
                                           Wlo, nullptr, nullptr, out, Cc);
    // weighted message sum -> GRU input
    msum_kernel<<<Bb * Nn, 128>>>(pM, out, pMs);
    // GRU gate GEMMs
    gemm512<EPI_BIAS, false><<<gGru, blk>>>(pMs, Wih, 512, 0, bih,
                                            nullptr, nullptr, pGI, nullptr, 3 * Cc);
    gemm512<EPI_BIAS, false><<<gGru, blk>>>(NF, Whh, 512, 0, bhh,
                                            nullptr, nullptr, pGH, nullptr, 3 * Cc);
    // gates + readouts
    gru_readout<<<Bb * Nn, 256>>>(pGI, pGH, NF, Wr1, br1, Wr2, br2, out);
}

// round 3
// speedup vs baseline: 2.0456x; 2.0456x over previous
#include <cuda_runtime.h>
#include <cuda_bf16.h>
#include <math.h>
#include <stdint.h>

// ---------------------------------------------------------------------------
// GPNN_VCOCO forward — bf16 split-precision GEMMs on warp-level mma.sync
// (HMMA; the harness ptxas target is sm_103 without the 'a' suffix, so
// tcgen05 is unavailable). Five 65536x512x512 GEMMs, effective K = 3*512
// planes (hi*hi + lo*hi + hi*lo), rel_err ~1e-5.
// ---------------------------------------------------------------------------

namespace {

constexpr int Bb = 16;
constexpr int Nn = 64;
constexpr int Cc = 512;
constexpr int Rr = Bb * Nn * Nn;   // 65536

// ---------------- scratch (static device globals) ----------------
__device__ __nv_bfloat16 g_EFh[Rr * Cc], g_EFl[Rr * Cc];
__device__ __nv_bfloat16 g_Mh [Rr * Cc], g_Ml [Rr * Cc];
__device__ __nv_bfloat16 g_Th [Rr * Cc], g_Tl [Rr * Cc];
__device__ __nv_bfloat16 g_Wmh[Cc * Cc], g_Wml[Cc * Cc];
__device__ __nv_bfloat16 g_W1h[Cc * Cc], g_W1l[Cc * Cc];
__device__ __nv_bfloat16 g_W2h[Cc * Cc], g_W2l[Cc * Cc];
__device__ float g_Hn [Bb * Nn * Cc];
__device__ float g_pa1[Rr];
__device__ float g_ms [Bb * Nn * Cc];
__device__ float g_GI [Bb * Nn * 3 * Cc];
__device__ float g_GH [Bb * Nn * 3 * Cc];

__device__ __forceinline__ float sigmoidf_(float x) {
    return 1.0f / (1.0f + __expf(-x));
}
__device__ __forceinline__ int permrow(int gr) {
    return (gr & ~4095) | ((gr & 63) << 6) | ((gr >> 6) & 63);
}
__device__ __forceinline__ uint32_t smem_u32(const void* p) {
    uint32_t a;
    asm("{ .reg .u64 t; cvta.to.shared.u64 t, %1; cvt.u32.u64 %0, t; }"
        : "=r"(a) : "l"(p));
    return a;
}
__device__ __forceinline__ uint32_t swz(uint32_t o) {   // 128B-row xor swizzle
    return o ^ ((o >> 3) & 0x70);
}
__device__ __forceinline__ void cp16(uint32_t saddr, const void* g) {
    asm volatile("cp.async.cg.shared.global [%0], [%1], 16;"
                 :: "r"(saddr), "l"(g) : "memory");
}
__device__ __forceinline__ void cp_commit() {
    asm volatile("cp.async.commit_group;" ::: "memory");
}
template<int N>
__device__ __forceinline__ void cp_wait() {
    asm volatile("cp.async.wait_group %0;" :: "n"(N) : "memory");
}
__device__ __forceinline__ void ldm_x4(uint32_t* r, uint32_t addr) {
    asm volatile("ldmatrix.sync.aligned.m8n8.x4.shared.b16 {%0,%1,%2,%3}, [%4];"
                 : "=r"(r[0]), "=r"(r[1]), "=r"(r[2]), "=r"(r[3]) : "r"(addr));
}
__device__ __forceinline__ void mma16816(float* c, const uint32_t* a,
                                         uint32_t b0, uint32_t b1) {
    asm volatile(
        "mma.sync.aligned.m16n8k16.row.col.f32.bf16.bf16.f32 "
        "{%0,%1,%2,%3}, {%4,%5,%6,%7}, {%8,%9}, {%0,%1,%2,%3};"
        : "+f"(c[0]), "+f"(c[1]), "+f"(c[2]), "+f"(c[3])
        : "r"(a[0]), "r"(a[1]), "r"(a[2]), "r"(a[3]), "r"(b0), "r"(b1));
}

enum { TEPI_MFUSE = 0, TEPI_RELU = 1, TEPI_DOT = 2 };

// ---------------------------------------------------------------------------
// HMMA GEMM: out[r,n] = epi( sum_{k<512} A[r,k]*W[n,k] ), split bf16 planes.
// CTA 128x128, 512 thr (4x4 warps, warp tile 32x32), K-chunk 64, 2-stage
// cp.async pipeline, 64KB dynamic smem.
// ---------------------------------------------------------------------------
template<int EPI, bool PERM>
__global__ void __launch_bounds__(512, 1)
hmma_gemm(const __nv_bfloat16* __restrict__ Ah, const __nv_bfloat16* __restrict__ Al,
          const __nv_bfloat16* __restrict__ Bh, const __nv_bfloat16* __restrict__ Bl,
          const float* __restrict__ bias,   // bl1/bl2
          const float* __restrict__ extra,  // Hn (MFUSE) | Wlo (DOT)
          const float* __restrict__ pa,     // pa1 logits (PERM)
          __nv_bfloat16* __restrict__ Ch, __nv_bfloat16* __restrict__ Cl,
          float* __restrict__ dotOut)
{
    extern __shared__ __align__(128) uint8_t smem[];
    // layout: sA[2][16384 bytes], sB[2][16384 bytes]
    const uint32_t sA0 = smem_u32(smem);
    const uint32_t sB0 = sA0 + 32768;

    const int tid = threadIdx.x;
    const int wid = tid >> 5, lane = tid & 31;
    const int warp_m = wid & 3, warp_n = wid >> 2;
    const int rowBase = blockIdx.y << 7, colBase = blockIdx.x << 7;

    // ---- loader: each thread owns 2 A rows + 2 B rows (16B per stage each)
    const int lrow = tid >> 3, lseg = tid & 7;     // lrow 0..63
    size_t aOff[2], bOff[2];
    uint32_t sOff[2];
#pragma unroll
    for (int i = 0; i < 2; i++) {
        const int row = lrow + i * 64;
        int sr = rowBase + row;
        if (PERM) sr = permrow(sr);
        aOff[i] = (size_t)sr * 512 + lseg * 8;
        bOff[i] = (size_t)(colBase + row) * 512 + lseg * 8;
        sOff[i] = swz((uint32_t)row * 128 + lseg * 16);
    }

    // ---- ldmatrix lane addressing (byte offsets within a 16KB tile)
    // A x4 groups: (m0-7,k0) (m8-15,k0) (m0-7,k8) (m8-15,k8)
    const int mrow = warp_m * 32 + ((lane >> 3) & 1) * 8 + (lane & 7);
    const uint32_t aK = (uint32_t)(lane >> 4) * 16;
    // B x4 groups: (n0-7,k0) (n0-7,k8) (n8-15,k0) (n8-15,k8)
    const int brow = warp_n * 32 + (lane >> 4) * 8 + (lane & 7);
    const uint32_t bK = (uint32_t)((lane >> 3) & 1) * 16;

    float acc[2][4][4];
#pragma unroll
    for (int mt = 0; mt < 2; mt++)
#pragma unroll
        for (int nf = 0; nf < 4; nf++)
#pragma unroll
            for (int j = 0; j < 4; j++) acc[mt][nf][j] = 0.0f;

    auto load_stage = [&](int st, int ch) {
        const int pass = ch >> 3;
        const int kb = (ch & 7) * 64;
        const __nv_bfloat16* Ap = (pass == 1) ? Al : Ah;
        const __nv_bfloat16* Bp = (pass == 2) ? Bl : Bh;
        const uint32_t sa = sA0 + st * 16384;
        const uint32_t sb = sB0 + st * 16384;
#pragma unroll
        for (int i = 0; i < 2; i++) {
            cp16(sa + sOff[i], Ap + aOff[i] + kb);
            cp16(sb + sOff[i], Bp + bOff[i] + kb);
        }
        cp_commit();
    };

    load_stage(0, 0);

#pragma unroll 1
    for (int ch = 0; ch < 24; ch++) {
        if (ch < 23) load_stage((ch + 1) & 1, ch + 1);
        if (ch < 23) cp_wait<1>(); else cp_wait<0>();
        __syncthreads();

        const uint32_t sa = sA0 + (ch & 1) * 16384;
        const uint32_t sb = sB0 + (ch & 1) * 16384;
#pragma unroll
        for (int ks = 0; ks < 4; ks++) {
            uint32_t a[2][4], b[2][4];
#pragma unroll
            for (int mt = 0; mt < 2; mt++)
                ldm_x4(a[mt], sa + swz((uint32_t)(mrow + mt * 16) * 128 + ks * 32 + aK));
#pragma unroll
            for (int pr = 0; pr < 2; pr++)
                ldm_x4(b[pr], sb + swz((uint32_t)(brow + pr * 16) * 128 + ks * 32 + bK));
#pragma unroll
            for (int mt = 0; mt < 2; mt++)
#pragma unroll
                for (int nf = 0; nf < 4; nf++)
                    mma16816(acc[mt][nf], a[mt],
                             b[nf >> 1][(nf & 1) * 2], b[nf >> 1][(nf & 1) * 2 + 1]);
        }
        if (ch < 23) __syncthreads();
    }

    // ---------------- epilogue ----------------
    // c-frag: c0:(m=l/4, n=2(l%4))  c1:n+1  c2:(m+8)  c3:(m+8,n+1)
    const int r0 = rowBase + warp_m * 32 + (lane >> 2);
    const int c0 = colBase + warp_n * 32 + (lane & 3) * 2;

    if (EPI == TEPI_DOT) {
        float dsum[2][2] = {{0.f, 0.f}, {0.f, 0.f}};
#pragma unroll
        for (int mt = 0; mt < 2; mt++)
#pragma unroll
            for (int nf = 0; nf < 4; nf++) {
                const int gc = c0 + nf * 8;
                const float b0v = bias[gc], b1v = bias[gc + 1];
                const float w0v = extra[gc], w1v = extra[gc + 1];
                dsum[mt][0] += fmaxf(acc[mt][nf][0] + b0v, 0.f) * w0v
                             + fmaxf(acc[mt][nf][1] + b1v, 0.f) * w1v;
                dsum[mt][1] += fmaxf(acc[mt][nf][2] + b0v, 0.f) * w0v
                             + fmaxf(acc[mt][nf][3] + b1v, 0.f) * w1v;
            }
#pragma unroll
        for (int mt = 0; mt < 2; mt++)
#pragma unroll
            for (int h = 0; h < 2; h++) {
                float v = dsum[mt][h];
                v += __shfl_xor_sync(0xffffffffu, v, 1);
                v += __shfl_xor_sync(0xffffffffu, v, 2);
                if ((lane & 3) == 0)
                    atomicAdd(dotOut + r0 + mt * 16 + h * 8, v);
            }
    } else {
#pragma unroll
        for (int mt = 0; mt < 2; mt++)
#pragma unroll
            for (int h = 0; h < 2; h++) {
                const int row = r0 + mt * 16 + h * 8;
                float s = 1.0f;
                const float* hnrow = nullptr;
                if (EPI == TEPI_MFUSE)
                    hnrow = extra + (size_t)(((row >> 12) << 6) | (row & 63)) * 512;
                if (PERM) s = sigmoidf_(pa[permrow(row)]);
                uint32_t* oh = reinterpret_cast<uint32_t*>(Ch) + ((size_t)row * 512 >> 1);
                uint32_t* ol = reinterpret_cast<uint32_t*>(Cl) + ((size_t)row * 512 >> 1);
#pragma unroll
                for (int nf = 0; nf < 4; nf++) {
                    const int gc = c0 + nf * 8;
                    const float x0 = acc[mt][nf][h * 2 + 0];
                    const float x1 = acc[mt][nf][h * 2 + 1];
                    float y0, y1;
                    if (EPI == TEPI_MFUSE) {
                        y0 = fmaxf(x0 + hnrow[gc],     0.0f);
                        y1 = fmaxf(x1 + hnrow[gc + 1], 0.0f);
                    } else {
                        y0 = fmaxf(fmaf(s, x0, bias[gc]),     0.0f);
                        y1 = fmaxf(fmaf(s, x1, bias[gc + 1]), 0.0f);
                    }
                    __nv_bfloat162 h2, l2;
                    h2.x = __float2bfloat16(y0);
                    h2.y = __float2bfloat16(y1);
                    l2.x = __float2bfloat16(y0 - __bfloat162float(h2.x));
                    l2.y = __float2bfloat16(y1 - __bfloat162float(h2.y));
                    oh[gc >> 1] = *reinterpret_cast<uint32_t*>(&h2);
                    ol[gc >> 1] = *reinterpret_cast<uint32_t*>(&l2);
                }
            }
    }
}

// ---------------------------------------------------------------------------
// conversions
// ---------------------------------------------------------------------------
__global__ void split_ef(const float4* __restrict__ in,
                         uint2* __restrict__ hi, uint2* __restrict__ lo, int n4)
{
    const int i = blockIdx.x * blockDim.x + threadIdx.x;
    if (i >= n4) return;
    const float4 v = in[i];
    __nv_bfloat162 hA, hB, lA, lB;
    hA.x = __float2bfloat16(v.x); hA.y = __float2bfloat16(v.y);
    hB.x = __float2bfloat16(v.z); hB.y = __float2bfloat16(v.w);
    lA.x = __float2bfloat16(v.x - __bfloat162float(hA.x));
    lA.y = __float2bfloat16(v.y - __bfloat162float(hA.y));
    lB.x = __float2bfloat16(v.z - __bfloat162float(hB.x));
    lB.y = __float2bfloat16(v.w - __bfloat162float(hB.y));
    hi[i] = make_uint2(*reinterpret_cast<uint32_t*>(&hA), *reinterpret_cast<uint32_t*>(&hB));
    lo[i] = make_uint2(*reinterpret_cast<uint32_t*>(&lA), *reinterpret_cast<uint32_t*>(&lB));
}

__global__ void conv_w(const float* __restrict__ W, int ldW, int koff,
                       __nv_bfloat16* __restrict__ hi, __nv_bfloat16* __restrict__ lo)
{
    const int idx = blockIdx.x * blockDim.x + threadIdx.x;  // 512*512
    const int row = idx >> 9, k = idx & 511;
    const float x = W[(size_t)row * ldW + koff + k];
    const __nv_bfloat16 h = __float2bfloat16(x);
    hi[idx] = h;
    lo[idx] = __float2bfloat16(x - __bfloat162float(h));
}

// ---------------------------------------------------------------------------
// SIMT gemm for the small GEMMs (Hn, GI, GH). 128x128x16 tiles.
// ---------------------------------------------------------------------------
__global__ void __launch_bounds__(256)
gemm512(const float* __restrict__ A,
        const float* __restrict__ W, int ldW, int koff,
        const float* __restrict__ bias,
        float* __restrict__ Cout, int Ncols)
{
    __shared__ float As[16][128];
    __shared__ float Bs[16][128];

    const int tid = threadIdx.x;
    const int tn = tid & 15, tm = tid >> 4;
    const int rowBase = blockIdx.y << 7, colBase = blockIdx.x << 7;
    const int lm = tid >> 2, lkq = tid & 3;

    const float4* A4 = reinterpret_cast<const float4*>(A);
    const int ar0 = (rowBase + lm) << 7;
    const int ar1 = ar0 + (64 << 7);
    const float* Wp0 = W + (size_t)(colBase + lm) * ldW + koff + (lkq << 2);
    const float* Wp1 = Wp0 + (size_t)64 * ldW;

    float acc[8][8];
#pragma unroll
    for (int i = 0; i < 8; i++)
#pragma unroll
        for (int j = 0; j < 8; j++) acc[i][j] = 0.0f;

#pragma unroll 1
    for (int kt = 0; kt < 32; kt++) {
        float4 a0 = A4[ar0 + (kt << 2) + lkq];
        float4 a1 = A4[ar1 + (kt << 2) + lkq];
        float4 b0 = *reinterpret_cast<const float4*>(Wp0 + (kt << 4));
        float4 b1 = *reinterpret_cast<const float4*>(Wp1 + (kt << 4));
        __syncthreads();
        const int kq = lkq << 2;
        As[kq + 0][lm]      = a0.x; As[kq + 1][lm]      = a0.y;
        As[kq + 2][lm]      = a0.z; As[kq + 3][lm]      = a0.w;
        As[kq + 0][lm + 64] = a1.x; As[kq + 1][lm + 64] = a1.y;
        As[kq + 2][lm + 64] = a1.z; As[kq + 3][lm + 64] = a1.w;
        Bs[kq + 0][lm]      = b0.x; Bs[kq + 1][lm]      = b0.y;
        Bs[kq + 2][lm]      = b0.z; Bs[kq + 3][lm]      = b0.w;
        Bs[kq + 0][lm + 64] = b1.x; Bs[kq + 1][lm + 64] = b1.y;
        Bs[kq + 2][lm + 64] = b1.z; Bs[kq + 3][lm + 64] = b1.w;
        __syncthreads();
#pragma unroll
        for (int k = 0; k < 16; k++) {
            float av[8], bv[8];
            *reinterpret_cast<float4*>(&av[0]) =
                *reinterpret_cast<const float4*>(&As[k][tm << 3]);
            *reinterpret_cast<float4*>(&av[4]) =
                *reinterpret_cast<const float4*>(&As[k][(tm << 3) + 4]);
            *reinterpret_cast<float4*>(&bv[0]) =
                *reinterpret_cast<const float4*>(&Bs[k][tn << 3]);
            *reinterpret_cast<float4*>(&bv[4]) =
                *reinterpret_cast<const float4*>(&Bs[k][(tn << 3) + 4]);
#pragma unroll
            for (int i = 0; i < 8; i++)
#pragma unroll
                for (int j = 0; j < 8; j++)
                    acc[i][j] = fmaf(av[i], bv[j], acc[i][j]);
        }
    }
#pragma unroll
    for (int i = 0; i < 8; i++) {
        const int gr = rowBase + (tm << 3) + i;
        float v[8];
#pragma unroll
        for (int j = 0; j < 8; j++)
            v[j] = acc[i][j] + bias[colBase + (tn << 3) + j];
        float4* crow = reinterpret_cast<float4*>(
            Cout + (size_t)gr * Ncols + colBase + (tn << 3));
        crow[0] = make_float4(v[0], v[1], v[2], v[3]);
        crow[1] = make_float4(v[4], v[5], v[6], v[7]);
    }
}

__global__ void init_pa(float* __restrict__ pa1, float* __restrict__ pa2,
                        const float* __restrict__ blo)
{
    const int i = blockIdx.x * blockDim.x + threadIdx.x;
    if (i < Rr) {
        const float v = blo[0];
        pa1[i] = v;
        pa2[i] = v;
    }
}

// msum[b,v,m] = sum_w sig(pa2[b,v,w]) * (Mh+Ml)[(b,v,w), m]
__global__ void msum2(const __nv_bfloat16* __restrict__ Mh,
                      const __nv_bfloat16* __restrict__ Ml,
                      const float* __restrict__ pa2,
                      float* __restrict__ msum)
{
    const int bv = blockIdx.x;          // 0..1023
    const int t  = threadIdx.x;         // 128
    __shared__ float sg[64];
    if (t < 64) sg[t] = sigmoidf_(pa2[bv * 64 + t]);
    __syncthreads();
    const __nv_bfloat16* mh = Mh + (size_t)bv * 64 * 512;
    const __nv_bfloat16* ml = Ml + (size_t)bv * 64 * 512;
    float a0 = 0.f, a1 = 0.f, a2 = 0.f, a3 = 0.f;
    for (int w = 0; w < 64; w++) {
        const float s = sg[w];
        const __nv_bfloat16* rh = mh + w * 512;
        const __nv_bfloat16* rl = ml + w * 512;
        a0 = fmaf(s, __bfloat162float(rh[t])       + __bfloat162float(rl[t]),       a0);
        a1 = fmaf(s, __bfloat162float(rh[t + 128]) + __bfloat162float(rl[t + 128]), a1);
        a2 = fmaf(s, __bfloat162float(rh[t + 256]) + __bfloat162float(rl[t + 256]), a2);
        a3 = fmaf(s, __bfloat162float(rh[t + 384]) + __bfloat162float(rl[t + 384]), a3);
    }
    float* o = msum + (size_t)bv * 512;
    o[t] = a0; o[t + 128] = a1; o[t + 256] = a2; o[t + 384] = a3;
}

__global__ void gru_readout(const float* __restrict__ GI,
                            const float* __restrict__ GH,
                            const float* __restrict__ NF,
                            const float* __restrict__ Wr1, const float* __restrict__ br1,
                            const float* __restrict__ Wr2, const float* __restrict__ br2,
                            float* __restrict__ out)
{
    const int row = blockIdx.x;         // 0..1023
    __shared__ float hn[512];
    const int t = threadIdx.x;          // 256
    const float* gi = GI + (size_t)row * 1536;
    const float* gh = GH + (size_t)row * 1536;
    const float* h  = NF + (size_t)row * 512;
    for (int d = t; d < 512; d += 256) {
        const float r = sigmoidf_(gi[d] + gh[d]);
        const float z = sigmoidf_(gi[512 + d] + gh[512 + d]);
        const float n = tanhf(gi[1024 + d] + r * gh[1024 + d]);
        hn[d] = (1.0f - z) * n + z * h[d];
    }
    __syncthreads();
    const int warp = t >> 5, lane = t & 31;
    for (int o = warp; o < 28; o += 8) {
        const float* Wr = (o < 26) ? (Wr1 + o * 512) : (Wr2 + (o - 26) * 512);
        float acc = 0.0f;
        for (int k = lane; k < 512; k += 32) acc = fmaf(hn[k], Wr[k], acc);
#pragma unroll
        for (int off = 16; off; off >>= 1)
            acc += __shfl_down_sync(0xffffffffu, acc, off);
        if (lane == 0) {
            if (o < 26) out[65536 + row * 26 + o]               = acc + br1[o];
            else        out[65536 + 26624 + row * 2 + (o - 26)] = acc + br2[o - 26];
        }
    }
}

} // namespace

extern "C" void kernel_launch(void* const* d_in, const int* /*in_sizes*/, int /*n_in*/,
                              void* d_out, int /*out_size*/)
{
    const float* EF  = (const float*)d_in[0];
    const float* NF  = (const float*)d_in[1];
    const float* Wm  = (const float*)d_in[4];
    const float* bm  = (const float*)d_in[5];
    const float* Wl1 = (const float*)d_in[6];
    const float* bl1 = (const float*)d_in[7];
    const float* Wl2 = (const float*)d_in[8];
    const float* bl2 = (const float*)d_in[9];
    const float* Wlo = (const float*)d_in[10];
    const float* blo = (const float*)d_in[11];
    const float* Wih = (const float*)d_in[12];
    const float* bih = (const float*)d_in[13];
    const float* Whh = (const float*)d_in[14];
    const float* bhh = (const float*)d_in[15];
    const float* Wr1 = (const float*)d_in[16];
    const float* br1 = (const float*)d_in[17];
    const float* Wr2 = (const float*)d_in[18];
    const float* br2 = (const float*)d_in[19];
    float* out = (float*)d_out;

    __nv_bfloat16 *pEFh, *pEFl, *pMh, *pMl, *pTh, *pTl;
    __nv_bfloat16 *pWmh, *pWml, *pW1h, *pW1l, *pW2h, *pW2l;
    float *pHn, *pPa1, *pMs, *pGI, *pGH;
    cudaGetSymbolAddress((void**)&pEFh, g_EFh);
    cudaGetSymbolAddress((void**)&pEFl, g_EFl);
    cudaGetSymbolAddress((void**)&pMh,  g_Mh);
    cudaGetSymbolAddress((void**)&pMl,  g_Ml);
    cudaGetSymbolAddress((void**)&pTh,  g_Th);
    cudaGetSymbolAddress((void**)&pTl,  g_Tl);
    cudaGetSymbolAddress((void**)&pWmh, g_Wmh);
    cudaGetSymbolAddress((void**)&pWml, g_Wml);
    cudaGetSymbolAddress((void**)&pW1h, g_W1h);
    cudaGetSymbolAddress((void**)&pW1l, g_W1l);
    cudaGetSymbolAddress((void**)&pW2h, g_W2h);
    cudaGetSymbolAddress((void**)&pW2l, g_W2l);
    cudaGetSymbolAddress((void**)&pHn,  g_Hn);
    cudaGetSymbolAddress((void**)&pPa1, g_pa1);
    cudaGetSymbolAddress((void**)&pMs,  g_ms);
    cudaGetSymbolAddress((void**)&pGI,  g_GI);
    cudaGetSymbolAddress((void**)&pGH,  g_GH);

    const int SMEM = 65536;
    cudaFuncSetAttribute(hmma_gemm<TEPI_MFUSE, false>,
                         cudaFuncAttributeMaxDynamicSharedMemorySize, SMEM);
    cudaFuncSetAttribute(hmma_gemm<TEPI_RELU, false>,
                         cudaFuncAttributeMaxDynamicSharedMemorySize, SMEM);
    cudaFuncSetAttribute(hmma_gemm<TEPI_RELU, true>,
                         cudaFuncAttributeMaxDynamicSharedMemorySize, SMEM);
    cudaFuncSetAttribute(hmma_gemm<TEPI_DOT, false>,
                         cudaFuncAttributeMaxDynamicSharedMemorySize, SMEM);

    const int n4 = Rr * Cc / 4;
    split_ef<<<(n4 + 255) / 256, 256>>>((const float4*)EF, (uint2*)pEFh, (uint2*)pEFl, n4);
    conv_w<<<1024, 256>>>(Wm,  1024, 512, pWmh, pWml);
    conv_w<<<1024, 256>>>(Wl1, 512,  0,   pW1h, pW1l);
    conv_w<<<1024, 256>>>(Wl2, 512,  0,   pW2h, pW2l);
    init_pa<<<(Rr + 255) / 256, 256>>>(pPa1, out, blo);

    // Hn = NF @ Wm[:, :512]^T + bm   (small SIMT GEMM)
    gemm512<<<dim3(4, 8), 256>>>(NF, Wm, 1024, 0, bm, pHn, Cc);

    const dim3 gTC(4, 512);
    // M = relu(EF @ WmE^T + Hn)  -> Mh/Ml
    hmma_gemm<TEPI_MFUSE, false><<<gTC, 512, SMEM>>>(pEFh, pEFl, pWmh, pWml,
                                                     nullptr, pHn, nullptr, pMh, pMl, nullptr);
    // T1 = relu(EF @ Wl1^T + bl1) -> Th/Tl
    hmma_gemm<TEPI_RELU, false><<<gTC, 512, SMEM>>>(pEFh, pEFl, pW1h, pW1l,
                                                    bl1, nullptr, nullptr, pTh, pTl, nullptr);
    // pa1 += dot(relu(T1 @ Wl2^T + bl2), Wlo)
    hmma_gemm<TEPI_DOT, false><<<gTC, 512, SMEM>>>(pTh, pTl, pW2h, pW2l,
                                                   bl2, Wlo, nullptr, nullptr, nullptr, pPa1);
    // T1' = relu(sig(pa1[perm]) * M[perm] @ Wl1^T + bl1)
    hmma_gemm<TEPI_RELU, true><<<gTC, 512, SMEM>>>(pMh, pMl, pW1h, pW1l,
                                                   bl1, nullptr, pPa1, pTh, pTl, nullptr);
    // pred_adj += dot(relu(T1' @ Wl2^T + bl2), Wlo)
    hmma_gemm<TEPI_DOT, false><<<gTC, 512, SMEM>>>(pTh, pTl, pW2h, pW2l,
                                                   bl2, Wlo, nullptr, nullptr, nullptr, out);

    msum2<<<Bb * Nn, 128>>>(pMh, pMl, out, pMs);
    gemm512<<<dim3(12, 8), 256>>>(pMs, Wih, 512, 0, bih, pGI, 3 * Cc);
    gemm512<<<dim3(12, 8), 256>>>(NF,  Whh, 512, 0, bhh, pGH, 3 * Cc);
    gru_readout<<<Bb * Nn, 256>>>(pGI, pGH, NF, Wr1, br1, Wr2, br2, out);
}

// round 4
// speedup vs baseline: 2.5776x; 1.2601x over previous
#include <cuda_runtime.h>
#include <cuda_bf16.h>
#include <math.h>
#include <stdint.h>

// ---------------------------------------------------------------------------
// GPNN_VCOCO forward — bf16 split-precision GEMMs on warp-level mma.sync.
// Five 65536x512x512 GEMMs, effective K = 3*512 planes (hi*hi+lo*hi+hi*lo).
// R4: CTA tile 256x128, warp tile 64x32 (16 warps), 3-stage cp.async
// pipeline with a single __syncthreads per K-chunk.
// ---------------------------------------------------------------------------

namespace {

constexpr int Bb = 16;
constexpr int Nn = 64;
constexpr int Cc = 512;
constexpr int Rr = Bb * Nn * Nn;   // 65536

// ---------------- scratch (static device globals) ----------------
__device__ __nv_bfloat16 g_EFh[Rr * Cc], g_EFl[Rr * Cc];
__device__ __nv_bfloat16 g_Mh [Rr * Cc], g_Ml [Rr * Cc];
__device__ __nv_bfloat16 g_Th [Rr * Cc], g_Tl [Rr * Cc];
__device__ __nv_bfloat16 g_Wmh[Cc * Cc], g_Wml[Cc * Cc];
__device__ __nv_bfloat16 g_W1h[Cc * Cc], g_W1l[Cc * Cc];
__device__ __nv_bfloat16 g_W2h[Cc * Cc], g_W2l[Cc * Cc];
__device__ float g_Hn [Bb * Nn * Cc];
__device__ float g_pa1[Rr];
__device__ float g_ms [Bb * Nn * Cc];
__device__ float g_GI [Bb * Nn * 3 * Cc];
__device__ float g_GH [Bb * Nn * 3 * Cc];

__device__ __forceinline__ float sigmoidf_(float x) {
    return 1.0f / (1.0f + __expf(-x));
}
__device__ __forceinline__ int permrow(int gr) {
    return (gr & ~4095) | ((gr & 63) << 6) | ((gr >> 6) & 63);
}
__device__ __forceinline__ uint32_t smem_u32(const void* p) {
    uint32_t a;
    asm("{ .reg .u64 t; cvta.to.shared.u64 t, %1; cvt.u32.u64 %0, t; }"
        : "=r"(a) : "l"(p));
    return a;
}
__device__ __forceinline__ uint32_t swz(uint32_t o) {   // 128B-row xor swizzle
    return o ^ ((o >> 3) & 0x70);
}
__device__ __forceinline__ void cp16(uint32_t saddr, const void* g) {
    asm volatile("cp.async.cg.shared.global [%0], [%1], 16;"
                 :: "r"(saddr), "l"(g) : "memory");
}
__device__ __forceinline__ void cp_commit() {
    asm volatile("cp.async.commit_group;" ::: "memory");
}
template<int N>
__device__ __forceinline__ void cp_wait() {
    asm volatile("cp.async.wait_group %0;" :: "n"(N) : "memory");
}
__device__ __forceinline__ void ldm_x4(uint32_t* r, uint32_t addr) {
    asm volatile("ldmatrix.sync.aligned.m8n8.x4.shared.b16 {%0,%1,%2,%3}, [%4];"
                 : "=r"(r[0]), "=r"(r[1]), "=r"(r[2]), "=r"(r[3]) : "r"(addr));
}
__device__ __forceinline__ void mma16816(float* c, const uint32_t* a,
                                         uint32_t b0, uint32_t b1) {
    asm volatile(
        "mma.sync.aligned.m16n8k16.row.col.f32.bf16.bf16.f32 "
        "{%0,%1,%2,%3}, {%4,%5,%6,%7}, {%8,%9}, {%0,%1,%2,%3};"
        : "+f"(c[0]), "+f"(c[1]), "+f"(c[2]), "+f"(c[3])
        : "r"(a[0]), "r"(a[1]), "r"(a[2]), "r"(a[3]), "r"(b0), "r"(b1));
}

enum { TEPI_MFUSE = 0, TEPI_RELU = 1, TEPI_DOT = 2 };

constexpr int STAGE_BYTES = 49152;           // 32KB A (256x64 bf16) + 16KB B
constexpr int SMEM_BYTES  = 3 * STAGE_BYTES; // 144KB

// ---------------------------------------------------------------------------
// HMMA GEMM: out[r,n] = epi( sum_{k<512} A[r,k]*W[n,k] ), split bf16 planes.
// CTA 256x128, 512 thr = 16 warps (4m x 4n), warp tile 64x32, K-chunk 64,
// 3-stage cp.async pipeline (one __syncthreads per chunk).
// ---------------------------------------------------------------------------
template<int EPI, bool PERM>
__global__ void __launch_bounds__(512, 1)
hmma_gemm(const __nv_bfloat16* __restrict__ Ah, const __nv_bfloat16* __restrict__ Al,
          const __nv_bfloat16* __restrict__ Bh, const __nv_bfloat16* __restrict__ Bl,
          const float* __restrict__ bias,   // bl1/bl2
          const float* __restrict__ extra,  // Hn (MFUSE) | Wlo (DOT)
          const float* __restrict__ pa,     // pa1 logits (PERM)
          __nv_bfloat16* __restrict__ Ch, __nv_bfloat16* __restrict__ Cl,
          float* __restrict__ dotOut)
{
    extern __shared__ __align__(128) uint8_t smem[];
    const uint32_t sBase = smem_u32(smem);

    const int tid = threadIdx.x;
    const int wid = tid >> 5, lane = tid & 31;
    const int warp_m = wid & 3, warp_n = wid >> 2;
    const int rowBase = blockIdx.y << 8;    // 256-row blocks
    const int colBase = blockIdx.x << 7;    // 128-col blocks

    // ---- loader: A = 4 sweeps of 64 rows, B = 2 sweeps (16B per cp)
    const int lrow = tid >> 3, lseg = tid & 7;
    uint32_t aOff[4], sAOff[4], bOff[2], sBOff[2];
#pragma unroll
    for (int i = 0; i < 4; i++) {
        const int row = lrow + i * 64;
        int sr = rowBase + row;
        if (PERM) sr = permrow(sr);
        aOff[i]  = (uint32_t)sr * 512u + lseg * 8;
        sAOff[i] = swz((uint32_t)row * 128 + lseg * 16);
    }
#pragma unroll
    for (int i = 0; i < 2; i++) {
        const int row = lrow + i * 64;
        bOff[i]  = (uint32_t)(colBase + row) * 512u + lseg * 8;
        sBOff[i] = swz((uint32_t)row * 128 + lseg * 16);
    }

    auto load_stage = [&](int st, int ch) {
        const int pass = ch >> 3;
        const int kb = (ch & 7) * 64;
        const __nv_bfloat16* Ap = (pass == 1) ? Al : Ah;
        const __nv_bfloat16* Bp = (pass == 2) ? Bl : Bh;
        const uint32_t sa = sBase + st * STAGE_BYTES;
        const uint32_t sb = sa + 32768;
#pragma unroll
        for (int i = 0; i < 4; i++) cp16(sa + sAOff[i], Ap + aOff[i] + kb);
#pragma unroll
        for (int i = 0; i < 2; i++) cp16(sb + sBOff[i], Bp + bOff[i] + kb);
        cp_commit();
    };

    load_stage(0, 0);
    load_stage(1, 1);

    float acc[4][4][4];
#pragma unroll
    for (int mt = 0; mt < 4; mt++)
#pragma unroll
        for (int nf = 0; nf < 4; nf++)
#pragma unroll
            for (int j = 0; j < 4; j++) acc[mt][nf][j] = 0.0f;

    // ldmatrix lane addressing
    const int aRow = warp_m * 64 + ((lane >> 3) & 1) * 8 + (lane & 7);
    const uint32_t aK = (uint32_t)(lane >> 4) * 16;
    const int bRow = warp_n * 32 + (lane >> 4) * 8 + (lane & 7);
    const uint32_t bK = (uint32_t)((lane >> 3) & 1) * 16;

#pragma unroll 1
    for (int ch = 0; ch < 24; ch++) {
        if (ch < 23) cp_wait<1>(); else cp_wait<0>();
        __syncthreads();
        if (ch + 2 < 24) load_stage((ch + 2) % 3, ch + 2);

        const uint32_t sa = sBase + (ch % 3) * STAGE_BYTES;
        const uint32_t sb = sa + 32768;
#pragma unroll
        for (int ks = 0; ks < 4; ks++) {
            uint32_t a[4][4], b[2][4];
#pragma unroll
            for (int mt = 0; mt < 4; mt++)
                ldm_x4(a[mt], sa + swz((uint32_t)(aRow + mt * 16) * 128 + ks * 32 + aK));
#pragma unroll
            for (int pr = 0; pr < 2; pr++)
                ldm_x4(b[pr], sb + swz((uint32_t)(bRow + pr * 16) * 128 + ks * 32 + bK));
#pragma unroll
            for (int mt = 0; mt < 4; mt++)
#pragma unroll
                for (int nf = 0; nf < 4; nf++)
                    mma16816(acc[mt][nf], a[mt],
                             b[nf >> 1][(nf & 1) * 2], b[nf >> 1][(nf & 1) * 2 + 1]);
        }
    }

    // ---------------- epilogue ----------------
    // c-frag: c0:(m=l/4, n=2(l%4))  c1:n+1  c2:(m+8)  c3:(m+8,n+1)
    const int r0 = rowBase + warp_m * 64 + (lane >> 2);
    const int c0 = colBase + warp_n * 32 + (lane & 3) * 2;

    if (EPI == TEPI_DOT) {
        float dsum[4][2];
#pragma unroll
        for (int mt = 0; mt < 4; mt++) { dsum[mt][0] = 0.f; dsum[mt][1] = 0.f; }
#pragma unroll
        for (int mt = 0; mt < 4; mt++)
#pragma unroll
            for (int nf = 0; nf < 4; nf++) {
                const int gc = c0 + nf * 8;
                const float b0v = bias[gc], b1v = bias[gc + 1];
                const float w0v = extra[gc], w1v = extra[gc + 1];
                dsum[mt][0] += fmaxf(acc[mt][nf][0] + b0v, 0.f) * w0v
                             + fmaxf(acc[mt][nf][1] + b1v, 0.f) * w1v;
                dsum[mt][1] += fmaxf(acc[mt][nf][2] + b0v, 0.f) * w0v
                             + fmaxf(acc[mt][nf][3] + b1v, 0.f) * w1v;
            }
#pragma unroll
        for (int mt = 0; mt < 4; mt++)
#pragma unroll
            for (int h = 0; h < 2; h++) {
                float v = dsum[mt][h];
                v += __shfl_xor_sync(0xffffffffu, v, 1);
                v += __shfl_xor_sync(0xffffffffu, v, 2);
                if ((lane & 3) == 0)
                    atomicAdd(dotOut + r0 + mt * 16 + h * 8, v);
            }
    } else {
#pragma unroll
        for (int mt = 0; mt < 4; mt++)
#pragma unroll
            for (int h = 0; h < 2; h++) {
                const int row = r0 + mt * 16 + h * 8;
                float s = 1.0f;
                const float* hnrow = nullptr;
                if (EPI == TEPI_MFUSE)
                    hnrow = extra + (size_t)(((row >> 12) << 6) | (row & 63)) * 512;
                if (PERM) s = sigmoidf_(pa[permrow(row)]);
                uint32_t* oh = reinterpret_cast<uint32_t*>(Ch) + ((size_t)row * 512 >> 1);
                uint32_t* ol = reinterpret_cast<uint32_t*>(Cl) + ((size_t)row * 512 >> 1);
#pragma unroll
                for (int nf = 0; nf < 4; nf++) {
                    const int gc = c0 + nf * 8;
                    const float x0 = acc[mt][nf][h * 2 + 0];
                    const float x1 = acc[mt][nf][h * 2 + 1];
                    float y0, y1;
                    if (EPI == TEPI_MFUSE) {
                        y0 = fmaxf(x0 + hnrow[gc],     0.0f);
                        y1 = fmaxf(x1 + hnrow[gc + 1], 0.0f);
                    } else {
                        y0 = fmaxf(fmaf(s, x0, bias[gc]),     0.0f);
                        y1 = fmaxf(fmaf(s, x1, bias[gc + 1]), 0.0f);
                    }
                    __nv_bfloat162 h2, l2;
                    h2.x = __float2bfloat16(y0);
                    h2.y = __float2bfloat16(y1);
                    l2.x = __float2bfloat16(y0 - __bfloat162float(h2.x));
                    l2.y = __float2bfloat16(y1 - __bfloat162float(h2.y));
                    oh[gc >> 1] = *reinterpret_cast<uint32_t*>(&h2);
                    ol[gc >> 1] = *reinterpret_cast<uint32_t*>(&l2);
                }
            }
    }
}

// ---------------------------------------------------------------------------
// conversions
// ---------------------------------------------------------------------------
__global__ void split_ef(const float4* __restrict__ in,
                         uint2* __restrict__ hi, uint2* __restrict__ lo, int n4)
{
    const int i = blockIdx.x * blockDim.x + threadIdx.x;
    if (i >= n4) return;
    const float4 v = in[i];
    __nv_bfloat162 hA, hB, lA, lB;
    hA.x = __float2bfloat16(v.x); hA.y = __float2bfloat16(v.y);
    hB.x = __float2bfloat16(v.z); hB.y = __float2bfloat16(v.w);
    lA.x = __float2bfloat16(v.x - __bfloat162float(hA.x));
    lA.y = __float2bfloat16(v.y - __bfloat162float(hA.y));
    lB.x = __float2bfloat16(v.z - __bfloat162float(hB.x));
    lB.y = __float2bfloat16(v.w - __bfloat162float(hB.y));
    hi[i] = make_uint2(*reinterpret_cast<uint32_t*>(&hA), *reinterpret_cast<uint32_t*>(&hB));
    lo[i] = make_uint2(*reinterpret_cast<uint32_t*>(&lA), *reinterpret_cast<uint32_t*>(&lB));
}

__global__ void conv_w(const float* __restrict__ W, int ldW, int koff,
                       __nv_bfloat16* __restrict__ hi, __nv_bfloat16* __restrict__ lo)
{
    const int idx = blockIdx.x * blockDim.x + threadIdx.x;  // 512*512
    const int row = idx >> 9, k = idx & 511;
    const float x = W[(size_t)row * ldW + koff + k];
    const __nv_bfloat16 h = __float2bfloat16(x);
    hi[idx] = h;
    lo[idx] = __float2bfloat16(x - __bfloat162float(h));
}

// ---------------------------------------------------------------------------
// SIMT gemm for the small GEMMs (Hn, GI, GH). 128x128x16 tiles.
// ---------------------------------------------------------------------------
__global__ void __launch_bounds__(256)
gemm512(const float* __restrict__ A,
        const float* __restrict__ W, int ldW, int koff,
        const float* __restrict__ bias,
        float* __restrict__ Cout, int Ncols)
{
    __shared__ float As[16][128];
    __shared__ float Bs[16][128];

    const int tid = threadIdx.x;
    const int tn = tid & 15, tm = tid >> 4;
    const int rowBase = blockIdx.y << 7, colBase = blockIdx.x << 7;
    const int lm = tid >> 2, lkq = tid & 3;

    const float4* A4 = reinterpret_cast<const float4*>(A);
    const int ar0 = (rowBase + lm) << 7;
    const int ar1 = ar0 + (64 << 7);
    const float* Wp0 = W + (size_t)(colBase + lm) * ldW + koff + (lkq << 2);
    const float* Wp1 = Wp0 + (size_t)64 * ldW;

    float acc[8][8];
#pragma unroll
    for (int i = 0; i < 8; i++)
#pragma unroll
        for (int j = 0; j < 8; j++) acc[i][j] = 0.0f;

#pragma unroll 1
    for (int kt = 0; kt < 32; kt++) {
        float4 a0 = A4[ar0 + (kt << 2) + lkq];
        float4 a1 = A4[ar1 + (kt << 2) + lkq];
        float4 b0 = *reinterpret_cast<const float4*>(Wp0 + (kt << 4));
        float4 b1 = *reinterpret_cast<const float4*>(Wp1 + (kt << 4));
        __syncthreads();
        const int kq = lkq << 2;
        As[kq + 0][lm]      = a0.x; As[kq + 1][lm]      = a0.y;
        As[kq + 2][lm]      = a0.z; As[kq + 3][lm]      = a0.w;
        As[kq + 0][lm + 64] = a1.x; As[kq + 1][lm + 64] = a1.y;
        As[kq + 2][lm + 64] = a1.z; As[kq + 3][lm + 64] = a1.w;
        Bs[kq + 0][lm]      = b0.x; Bs[kq + 1][lm]      = b0.y;
        Bs[kq + 2][lm]      = b0.z; Bs[kq + 3][lm]      = b0.w;
        Bs[kq + 0][lm + 64] = b1.x; Bs[kq + 1][lm + 64] = b1.y;
        Bs[kq + 2][lm + 64] = b1.z; Bs[kq + 3][lm + 64] = b1.w;
        __syncthreads();
#pragma unroll
        for (int k = 0; k < 16; k++) {
            float av[8], bv[8];
            *reinterpret_cast<float4*>(&av[0]) =
                *reinterpret_cast<const float4*>(&As[k][tm << 3]);
            *reinterpret_cast<float4*>(&av[4]) =
                *reinterpret_cast<const float4*>(&As[k][(tm << 3) + 4]);
            *reinterpret_cast<float4*>(&bv[0]) =
                *reinterpret_cast<const float4*>(&Bs[k][tn << 3]);
            *reinterpret_cast<float4*>(&bv[4]) =
                *reinterpret_cast<const float4*>(&Bs[k][(tn << 3) + 4]);
#pragma unroll
            for (int i = 0; i < 8; i++)
#pragma unroll
                for (int j = 0; j < 8; j++)
                    acc[i][j] = fmaf(av[i], bv[j], acc[i][j]);
        }
    }
#pragma unroll
    for (int i = 0; i < 8; i++) {
        const int gr = rowBase + (tm << 3) + i;
        float v[8];
#pragma unroll
        for (int j = 0; j < 8; j++)
            v[j] = acc[i][j] + bias[colBase + (tn << 3) + j];
        float4* crow = reinterpret_cast<float4*>(
            Cout + (size_t)gr * Ncols + colBase + (tn << 3));
        crow[0] = make_float4(v[0], v[1], v[2], v[3]);
        crow[1] = make_float4(v[4], v[5], v[6], v[7]);
    }
}

__global__ void init_pa(float* __restrict__ pa1, float* __restrict__ pa2,
                        const float* __restrict__ blo)
{
    const int i = blockIdx.x * blockDim.x + threadIdx.x;
    if (i < Rr) {
        const float v = blo[0];
        pa1[i] = v;
        pa2[i] = v;
    }
}

// msum[b,v,m] = sum_w sig(pa2[b,v,w]) * (Mh+Ml)[(b,v,w), m]
// 128 threads, 4 cols each (bf16x2 vectorized).
__global__ void msum2(const __nv_bfloat16* __restrict__ Mh,
                      const __nv_bfloat16* __restrict__ Ml,
                      const float* __restrict__ pa2,
                      float* __restrict__ msum)
{
    const int bv = blockIdx.x;          // 0..1023
    const int t  = threadIdx.x;         // 128
    __shared__ float sg[64];
    if (t < 64) sg[t] = sigmoidf_(pa2[bv * 64 + t]);
    __syncthreads();
    const uint32_t* mh = reinterpret_cast<const uint32_t*>(Mh + (size_t)bv * 64 * 512);
    const uint32_t* ml = reinterpret_cast<const uint32_t*>(Ml + (size_t)bv * 64 * 512);
    const int c = t * 2;                // bf162 index (cols 4t..4t+3)
    float a0 = 0.f, a1 = 0.f, a2 = 0.f, a3 = 0.f;
#pragma unroll 4
    for (int w = 0; w < 64; w++) {
        const float s = sg[w];
        const uint32_t h0 = mh[w * 256 + c],     l0 = ml[w * 256 + c];
        const uint32_t h1 = mh[w * 256 + c + 1], l1 = ml[w * 256 + c + 1];
        const __nv_bfloat162 H0 = *reinterpret_cast<const __nv_bfloat162*>(&h0);
        const __nv_bfloat162 L0 = *reinterpret_cast<const __nv_bfloat162*>(&l0);
        const __nv_bfloat162 H1 = *reinterpret_cast<const __nv_bfloat162*>(&h1);
        const __nv_bfloat162 L1 = *reinterpret_cast<const __nv_bfloat162*>(&l1);
        a0 = fmaf(s, __bfloat162float(H0.x) + __bfloat162float(L0.x), a0);
        a1 = fmaf(s, __bfloat162float(H0.y) + __bfloat162float(L0.y), a1);
        a2 = fmaf(s, __bfloat162float(H1.x) + __bfloat162float(L1.x), a2);
        a3 = fmaf(s, __bfloat162float(H1.y) + __bfloat162float(L1.y), a3);
    }
    float4* o = reinterpret_cast<float4*>(msum + (size_t)bv * 512) + t;
    *o = make_float4(a0, a1, a2, a3);
}

__global__ void gru_readout(const float* __restrict__ GI,
                            const float* __restrict__ GH,
                            const float* __restrict__ NF,
                            const float* __restrict__ Wr1, const float* __restrict__ br1,
                            const float* __restrict__ Wr2, const float* __restrict__ br2,
                            float* __restrict__ out)
{
    const int row = blockIdx.x;         // 0..1023
    __shared__ float hn[512];
    const int t = threadIdx.x;          // 256
    const float* gi = GI + (size_t)row * 1536;
    const float* gh = GH + (size_t)row * 1536;
    const float* h  = NF + (size_t)row * 512;
    for (int d = t; d < 512; d += 256) {
        const float r = sigmoidf_(gi[d] + gh[d]);
        const float z = sigmoidf_(gi[512 + d] + gh[512 + d]);
        const float n = tanhf(gi[1024 + d] + r * gh[1024 + d]);
        hn[d] = (1.0f - z) * n + z * h[d];
    }
    __syncthreads();
    const int warp = t >> 5, lane = t & 31;
    for (int o = warp; o < 28; o += 8) {
        const float* Wr = (o < 26) ? (Wr1 + o * 512) : (Wr2 + (o - 26) * 512);
        float acc = 0.0f;
        for (int k = lane; k < 512; k += 32) acc = fmaf(hn[k], Wr[k], acc);
#pragma unroll
        for (int off = 16; off; off >>= 1)
            acc += __shfl_down_sync(0xffffffffu, acc, off);
        if (lane == 0) {
            if (o < 26) out[65536 + row * 26 + o]               = acc + br1[o];
            else        out[65536 + 26624 + row * 2 + (o - 26)] = acc + br2[o - 26];
        }
    }
}

} // namespace

extern "C" void kernel_launch(void* const* d_in, const int* /*in_sizes*/, int /*n_in*/,
                              void* d_out, int /*out_size*/)
{
    const float* EF  = (const float*)d_in[0];
    const float* NF  = (const float*)d_in[1];
    const float* Wm  = (const float*)d_in[4];
    const float* bm  = (const float*)d_in[5];
    const float* Wl1 = (const float*)d_in[6];
    const float* bl1 = (const float*)d_in[7];
    const float* Wl2 = (const float*)d_in[8];
    const float* bl2 = (const float*)d_in[9];
    const float* Wlo = (const float*)d_in[10];
    const float* blo = (const float*)d_in[11];
    const float* Wih = (const float*)d_in[12];
    const float* bih = (const float*)d_in[13];
    const float* Whh = (const float*)d_in[14];
    const float* bhh = (const float*)d_in[15];
    const float* Wr1 = (const float*)d_in[16];
    const float* br1 = (const float*)d_in[17];
    const float* Wr2 = (const float*)d_in[18];
    const float* br2 = (const float*)d_in[19];
    float* out = (float*)d_out;

    __nv_bfloat16 *pEFh, *pEFl, *pMh, *pMl, *pTh, *pTl;
    __nv_bfloat16 *pWmh, *pWml, *pW1h, *pW1l, *pW2h, *pW2l;
    float *pHn, *pPa1, *pMs, *pGI, *pGH;
    cudaGetSymbolAddress((void**)&pEFh, g_EFh);
    cudaGetSymbolAddress((void**)&pEFl, g_EFl);
    cudaGetSymbolAddress((void**)&pMh,  g_Mh);
    cudaGetSymbolAddress((void**)&pMl,  g_Ml);
    cudaGetSymbolAddress((void**)&pTh,  g_Th);
    cudaGetSymbolAddress((void**)&pTl,  g_Tl);
    cudaGetSymbolAddress((void**)&pWmh, g_Wmh);
    cudaGetSymbolAddress((void**)&pWml, g_Wml);
    cudaGetSymbolAddress((void**)&pW1h, g_W1h);
    cudaGetSymbolAddress((void**)&pW1l, g_W1l);
    cudaGetSymbolAddress((void**)&pW2h, g_W2h);
    cudaGetSymbolAddress((void**)&pW2l, g_W2l);
    cudaGetSymbolAddress((void**)&pHn,  g_Hn);
    cudaGetSymbolAddress((void**)&pPa1, g_pa1);
    cudaGetSymbolAddress((void**)&pMs,  g_ms);
    cudaGetSymbolAddress((void**)&pGI,  g_GI);
    cudaGetSymbolAddress((void**)&pGH,  g_GH);

    cudaFuncSetAttribute(hmma_gemm<TEPI_MFUSE, false>,
                         cudaFuncAttributeMaxDynamicSharedMemorySize, SMEM_BYTES);
    cudaFuncSetAttribute(hmma_gemm<TEPI_RELU, false>,
                         cudaFuncAttributeMaxDynamicSharedMemorySize, SMEM_BYTES);
    cudaFuncSetAttribute(hmma_gemm<TEPI_RELU, true>,
                         cudaFuncAttributeMaxDynamicSharedMemorySize, SMEM_BYTES);
    cudaFuncSetAttribute(hmma_gemm<TEPI_DOT, false>,
                         cudaFuncAttributeMaxDynamicSharedMemorySize, SMEM_BYTES);

    const int n4 = Rr * Cc / 4;
    split_ef<<<(n4 + 255) / 256, 256>>>((const float4*)EF, (uint2*)pEFh, (uint2*)pEFl, n4);
    conv_w<<<1024, 256>>>(Wm,  1024, 512, pWmh, pWml);
    conv_w<<<1024, 256>>>(Wl1, 512,  0,   pW1h, pW1l);
    conv_w<<<1024, 256>>>(Wl2, 512,  0,   pW2h, pW2l);
    init_pa<<<(Rr + 255) / 256, 256>>>(pPa1, out, blo);

    // Hn = NF @ Wm[:, :512]^T + bm   (small SIMT GEMM)
    gemm512<<<dim3(4, 8), 256>>>(NF, Wm, 1024, 0, bm, pHn, Cc);

    const dim3 gTC(4, 256);   // 256-row x 128-col tiles
    // M = relu(EF @ WmE^T + Hn)  -> Mh/Ml
    hmma_gemm<TEPI_MFUSE, false><<<gTC, 512, SMEM_BYTES>>>(pEFh, pEFl, pWmh, pWml,
                                                           nullptr, pHn, nullptr, pMh, pMl, nullptr);
    // T1 = relu(EF @ Wl1^T + bl1) -> Th/Tl
    hmma_gemm<TEPI_RELU, false><<<gTC, 512, SMEM_BYTES>>>(pEFh, pEFl, pW1h, pW1l,
                                                          bl1, nullptr, nullptr, pTh, pTl, nullptr);
    // pa1 += dot(relu(T1 @ Wl2^T + bl2), Wlo)
    hmma_gemm<TEPI_DOT, false><<<gTC, 512, SMEM_BYTES>>>(pTh, pTl, pW2h, pW2l,
                                                         bl2, Wlo, nullptr, nullptr, nullptr, pPa1);
    // T1' = relu(sig(pa1[perm]) * M[perm] @ Wl1^T + bl1)
    hmma_gemm<TEPI_RELU, true><<<gTC, 512, SMEM_BYTES>>>(pMh, pMl, pW1h, pW1l,
                                                         bl1, nullptr, pPa1, pTh, pTl, nullptr);
    // pred_adj += dot(relu(T1' @ Wl2^T + bl2), Wlo)
    hmma_gemm<TEPI_DOT, false><<<gTC, 512, SMEM_BYTES>>>(pTh, pTl, pW2h, pW2l,
                                                         bl2, Wlo, nullptr, nullptr, nullptr, out);

    msum2<<<Bb * Nn, 128>>>(pMh, pMl, out, pMs);
    gemm512<<<dim3(12, 8), 256>>>(pMs, Wih, 512, 0, bih, pGI, 3 * Cc);
    gemm512<<<dim3(12, 8), 256>>>(NF,  Whh, 512, 0, bhh, pGH, 3 * Cc);
    gru_readout<<<Bb * Nn, 256>>>(pGI, pGH, NF, Wr1, br1, Wr2, br2, out);
}

// round 5
// speedup vs baseline: 3.3701x; 1.3074x over previous
#include <cuda_runtime.h>
#include <cuda_fp16.h>
#include <math.h>
#include <stdint.h>

// ---------------------------------------------------------------------------
// GPNN_VCOCO forward — fp16 2-plane split GEMMs on warp-level mma.sync.
// Five 65536x512x512 GEMMs, effective K = 2*512 planes (Ah*Bh + Al*Bh).
// fp16 split residual ~2^-22; dropped Ah*Bl cross term ~2^-12 rel RMS.
// CTA tile 256x128, warp tile 64x32 (16 warps), 3-stage cp.async pipeline.
// ---------------------------------------------------------------------------

namespace {

constexpr int Bb = 16;
constexpr int Nn = 64;
constexpr int Cc = 512;
constexpr int Rr = Bb * Nn * Nn;   // 65536

// ---------------- scratch (static device globals) ----------------
__device__ __half g_EFh[Rr * Cc], g_EFl[Rr * Cc];
__device__ __half g_Mh [Rr * Cc], g_Ml [Rr * Cc];
__device__ __half g_Th [Rr * Cc], g_Tl [Rr * Cc];
__device__ __half g_Wmh[Cc * Cc];
__device__ __half g_W1h[Cc * Cc];
__device__ __half g_W2h[Cc * Cc];
__device__ float g_Hn [Bb * Nn * Cc];
__device__ float g_pa1[Rr];
__device__ float g_ms [Bb * Nn * Cc];
__device__ float g_GI [Bb * Nn * 3 * Cc];
__device__ float g_GH [Bb * Nn * 3 * Cc];

__device__ __forceinline__ float sigmoidf_(float x) {
    return 1.0f / (1.0f + __expf(-x));
}
__device__ __forceinline__ int permrow(int gr) {
    return (gr & ~4095) | ((gr & 63) << 6) | ((gr >> 6) & 63);
}
__device__ __forceinline__ uint32_t smem_u32(const void* p) {
    uint32_t a;
    asm("{ .reg .u64 t; cvta.to.shared.u64 t, %1; cvt.u32.u64 %0, t; }"
        : "=r"(a) : "l"(p));
    return a;
}
__device__ __forceinline__ uint32_t swz(uint32_t o) {   // 128B-row xor swizzle
    return o ^ ((o >> 3) & 0x70);
}
__device__ __forceinline__ void cp16(uint32_t saddr, const void* g) {
    asm volatile("cp.async.cg.shared.global [%0], [%1], 16;"
                 :: "r"(saddr), "l"(g) : "memory");
}
__device__ __forceinline__ void cp_commit() {
    asm volatile("cp.async.commit_group;" ::: "memory");
}
template<int N>
__device__ __forceinline__ void cp_wait() {
    asm volatile("cp.async.wait_group %0;" :: "n"(N) : "memory");
}
__device__ __forceinline__ void ldm_x4(uint32_t* r, uint32_t addr) {
    asm volatile("ldmatrix.sync.aligned.m8n8.x4.shared.b16 {%0,%1,%2,%3}, [%4];"
                 : "=r"(r[0]), "=r"(r[1]), "=r"(r[2]), "=r"(r[3]) : "r"(addr));
}
__device__ __forceinline__ void mma16816(float* c, const uint32_t* a,
                                         uint32_t b0, uint32_t b1) {
    asm volatile(
        "mma.sync.aligned.m16n8k16.row.col.f32.f16.f16.f32 "
        "{%0,%1,%2,%3}, {%4,%5,%6,%7}, {%8,%9}, {%0,%1,%2,%3};"
        : "+f"(c[0]), "+f"(c[1]), "+f"(c[2]), "+f"(c[3])
        : "r"(a[0]), "r"(a[1]), "r"(a[2]), "r"(a[3]), "r"(b0), "r"(b1));
}

enum { TEPI_MFUSE = 0, TEPI_RELU = 1, TEPI_DOT = 2 };

constexpr int STAGE_BYTES = 49152;           // 32KB A (256x64 fp16) + 16KB B
constexpr int SMEM_BYTES  = 3 * STAGE_BYTES; // 144KB
constexpr int NCHUNK      = 16;              // 2 planes x 8 chunks of K=64

// ---------------------------------------------------------------------------
// HMMA GEMM: out[r,n] = epi( sum_{k<512} A[r,k]*W[n,k] ), fp16 2-plane split.
// CTA 256x128, 512 thr = 16 warps (4m x 4n), warp tile 64x32, K-chunk 64,
// 3-stage cp.async pipeline (one __syncthreads per chunk).
// ---------------------------------------------------------------------------
template<int EPI, bool PERM>
__global__ void __launch_bounds__(512, 1)
hmma_gemm(const __half* __restrict__ Ah, const __half* __restrict__ Al,
          const __half* __restrict__ Bh,
          const float* __restrict__ bias,   // bl1/bl2
          const float* __restrict__ extra,  // Hn (MFUSE) | Wlo (DOT)
          const float* __restrict__ pa,     // pa1 logits (PERM)
          __half* __restrict__ Ch, __half* __restrict__ Cl,
          float* __restrict__ dotOut)
{
    extern __shared__ __align__(128) uint8_t smem[];
    const uint32_t sBase = smem_u32(smem);

    const int tid = threadIdx.x;
    const int wid = tid >> 5, lane = tid & 31;
    const int warp_m = wid & 3, warp_n = wid >> 2;
    const int rowBase = blockIdx.y << 8;    // 256-row blocks
    const int colBase = blockIdx.x << 7;    // 128-col blocks

    // ---- loader: A = 4 sweeps of 64 rows, B = 2 sweeps (16B per cp)
    const int lrow = tid >> 3, lseg = tid & 7;
    uint32_t aOff[4], sAOff[4], bOff[2], sBOff[2];
#pragma unroll
    for (int i = 0; i < 4; i++) {
        const int row = lrow + i * 64;
        int sr = rowBase + row;
        if (PERM) sr = permrow(sr);
        aOff[i]  = (uint32_t)sr * 512u + lseg * 8;
        sAOff[i] = swz((uint32_t)row * 128 + lseg * 16);
    }
#pragma unroll
    for (int i = 0; i < 2; i++) {
        const int row = lrow + i * 64;
        bOff[i]  = (uint32_t)(colBase + row) * 512u + lseg * 8;
        sBOff[i] = swz((uint32_t)row * 128 + lseg * 16);
    }

    auto load_stage = [&](int st, int ch) {
        const int kb = (ch & 7) * 64;
        const __half* Ap = (ch >> 3) ? Al : Ah;
        const uint32_t sa = sBase + st * STAGE_BYTES;
        const uint32_t sb = sa + 32768;
#pragma unroll
        for (int i = 0; i < 4; i++) cp16(sa + sAOff[i], Ap + aOff[i] + kb);
#pragma unroll
        for (int i = 0; i < 2; i++) cp16(sb + sBOff[i], Bh + bOff[i] + kb);
        cp_commit();
    };

    load_stage(0, 0);
    load_stage(1, 1);

    float acc[4][4][4];
#pragma unroll
    for (int mt = 0; mt < 4; mt++)
#pragma unroll
        for (int nf = 0; nf < 4; nf++)
#pragma unroll
            for (int j = 0; j < 4; j++) acc[mt][nf][j] = 0.0f;

    // ldmatrix lane addressing
    const int aRow = warp_m * 64 + ((lane >> 3) & 1) * 8 + (lane & 7);
    const uint32_t aK = (uint32_t)(lane >> 4) * 16;
    const int bRow = warp_n * 32 + (lane >> 4) * 8 + (lane & 7);
    const uint32_t bK = (uint32_t)((lane >> 3) & 1) * 16;

#pragma unroll 1
    for (int ch = 0; ch < NCHUNK; ch++) {
        if (ch < NCHUNK - 1) cp_wait<1>(); else cp_wait<0>();
        __syncthreads();
        if (ch + 2 < NCHUNK) load_stage((ch + 2) % 3, ch + 2);

        const uint32_t sa = sBase + (ch % 3) * STAGE_BYTES;
        const uint32_t sb = sa + 32768;
#pragma unroll
        for (int ks = 0; ks < 4; ks++) {
            uint32_t a[4][4], b[2][4];
#pragma unroll
            for (int mt = 0; mt < 4; mt++)
                ldm_x4(a[mt], sa + swz((uint32_t)(aRow + mt * 16) * 128 + ks * 32 + aK));
#pragma unroll
            for (int pr = 0; pr < 2; pr++)
                ldm_x4(b[pr], sb + swz((uint32_t)(bRow + pr * 16) * 128 + ks * 32 + bK));
#pragma unroll
            for (int mt = 0; mt < 4; mt++)
#pragma unroll
                for (int nf = 0; nf < 4; nf++)
                    mma16816(acc[mt][nf], a[mt],
                             b[nf >> 1][(nf & 1) * 2], b[nf >> 1][(nf & 1) * 2 + 1]);
        }
    }

    // ---------------- epilogue ----------------
    // c-frag: c0:(m=l/4, n=2(l%4))  c1:n+1  c2:(m+8)  c3:(m+8,n+1)
    const int r0 = rowBase + warp_m * 64 + (lane >> 2);
    const int c0 = colBase + warp_n * 32 + (lane & 3) * 2;

    if (EPI == TEPI_DOT) {
        float dsum[4][2];
#pragma unroll
        for (int mt = 0; mt < 4; mt++) { dsum[mt][0] = 0.f; dsum[mt][1] = 0.f; }
#pragma unroll
        for (int mt = 0; mt < 4; mt++)
#pragma unroll
            for (int nf = 0; nf < 4; nf++) {
                const int gc = c0 + nf * 8;
                const float b0v = bias[gc], b1v = bias[gc + 1];
                const float w0v = extra[gc], w1v = extra[gc + 1];
                dsum[mt][0] += fmaxf(acc[mt][nf][0] + b0v, 0.f) * w0v
                             + fmaxf(acc[mt][nf][1] + b1v, 0.f) * w1v;
                dsum[mt][1] += fmaxf(acc[mt][nf][2] + b0v, 0.f) * w0v
                             + fmaxf(acc[mt][nf][3] + b1v, 0.f) * w1v;
            }
#pragma unroll
        for (int mt = 0; mt < 4; mt++)
#pragma unroll
            for (int h = 0; h < 2; h++) {
                float v = dsum[mt][h];
                v += __shfl_xor_sync(0xffffffffu, v, 1);
                v += __shfl_xor_sync(0xffffffffu, v, 2);
                if ((lane & 3) == 0)
                    atomicAdd(dotOut + r0 + mt * 16 + h * 8, v);
            }
    } else {
#pragma unroll
        for (int mt = 0; mt < 4; mt++)
#pragma unroll
            for (int h = 0; h < 2; h++) {
                const int row = r0 + mt * 16 + h * 8;
                float s = 1.0f;
                const float* hnrow = nullptr;
                if (EPI == TEPI_MFUSE)
                    hnrow = extra + (size_t)(((row >> 12) << 6) | (row & 63)) * 512;
                if (PERM) s = sigmoidf_(pa[permrow(row)]);
                uint32_t* oh = reinterpret_cast<uint32_t*>(Ch) + ((size_t)row * 512 >> 1);
                uint32_t* ol = reinterpret_cast<uint32_t*>(Cl) + ((size_t)row * 512 >> 1);
#pragma unroll
                for (int nf = 0; nf < 4; nf++) {
                    const int gc = c0 + nf * 8;
                    const float x0 = acc[mt][nf][h * 2 + 0];
                    const float x1 = acc[mt][nf][h * 2 + 1];
                    float y0, y1;
                    if (EPI == TEPI_MFUSE) {
                        y0 = fmaxf(x0 + hnrow[gc],     0.0f);
                        y1 = fmaxf(x1 + hnrow[gc + 1], 0.0f);
                    } else {
                        y0 = fmaxf(fmaf(s, x0, bias[gc]),     0.0f);
                        y1 = fmaxf(fmaf(s, x1, bias[gc + 1]), 0.0f);
                    }
                    __half2 h2, l2;
                    h2.x = __float2half_rn(y0);
                    h2.y = __float2half_rn(y1);
                    l2.x = __float2half_rn(y0 - __half2float(h2.x));
                    l2.y = __float2half_rn(y1 - __half2float(h2.y));
                    oh[gc >> 1] = *reinterpret_cast<uint32_t*>(&h2);
                    ol[gc >> 1] = *reinterpret_cast<uint32_t*>(&l2);
                }
            }
    }
}

// ---------------------------------------------------------------------------
// conversions
// ---------------------------------------------------------------------------
__global__ void split_ef(const float4* __restrict__ in,
                         uint2* __restrict__ hi, uint2* __restrict__ lo, int n4)
{
    const int i = blockIdx.x * blockDim.x + threadIdx.x;
    if (i >= n4) return;
    const float4 v = in[i];
    __half2 hA, hB, lA, lB;
    hA.x = __float2half_rn(v.x); hA.y = __float2half_rn(v.y);
    hB.x = __float2half_rn(v.z); hB.y = __float2half_rn(v.w);
    lA.x = __float2half_rn(v.x - __half2float(hA.x));
    lA.y = __float2half_rn(v.y - __half2float(hA.y));
    lB.x = __float2half_rn(v.z - __half2float(hB.x));
    lB.y = __float2half_rn(v.w - __half2float(hB.y));
    hi[i] = make_uint2(*reinterpret_cast<uint32_t*>(&hA), *reinterpret_cast<uint32_t*>(&hB));
    lo[i] = make_uint2(*reinterpret_cast<uint32_t*>(&lA), *reinterpret_cast<uint32_t*>(&lB));
}

// weights: hi plane only (fp16); cross term dropped by design
__global__ void conv_w(const float* __restrict__ W, int ldW, int koff,
                       __half* __restrict__ hi)
{
    const int idx = blockIdx.x * blockDim.x + threadIdx.x;  // 512*512
    const int row = idx >> 9, k = idx & 511;
    hi[idx] = __float2half_rn(W[(size_t)row * ldW + koff + k]);
}

// ---------------------------------------------------------------------------
// SIMT gemm for the small GEMMs (Hn, GI, GH). 128x128x16 tiles.
// ---------------------------------------------------------------------------
__global__ void __launch_bounds__(256)
gemm512(const float* __restrict__ A,
        const float* __restrict__ W, int ldW, int koff,
        const float* __restrict__ bias,
        float* __restrict__ Cout, int Ncols)
{
    __shared__ float As[16][128];
    __shared__ float Bs[16][128];

    const int tid = threadIdx.x;
    const int tn = tid & 15, tm = tid >> 4;
    const int rowBase = blockIdx.y << 7, colBase = blockIdx.x << 7;
    const int lm = tid >> 2, lkq = tid & 3;

    const float4* A4 = reinterpret_cast<const float4*>(A);
    const int ar0 = (rowBase + lm) << 7;
    const int ar1 = ar0 + (64 << 7);
    const float* Wp0 = W + (size_t)(colBase + lm) * ldW + koff + (lkq << 2);
    const float* Wp1 = Wp0 + (size_t)64 * ldW;

    float acc[8][8];
#pragma unroll
    for (int i = 0; i < 8; i++)
#pragma unroll
        for (int j = 0; j < 8; j++) acc[i][j] = 0.0f;

#pragma unroll 1
    for (int kt = 0; kt < 32; kt++) {
        float4 a0 = A4[ar0 + (kt << 2) + lkq];
        float4 a1 = A4[ar1 + (kt << 2) + lkq];
        float4 b0 = *reinterpret_cast<const float4*>(Wp0 + (kt << 4));
        float4 b1 = *reinterpret_cast<const float4*>(Wp1 + (kt << 4));
        __syncthreads();
        const int kq = lkq << 2;
        As[kq + 0][lm]      = a0.x; As[kq + 1][lm]      = a0.y;
        As[kq + 2][lm]      = a0.z; As[kq + 3][lm]      = a0.w;
        As[kq + 0][lm + 64] = a1.x; As[kq + 1][lm + 64] = a1.y;
        As[kq + 2][lm + 64] = a1.z; As[kq + 3][lm + 64] = a1.w;
        Bs[kq + 0][lm]      = b0.x; Bs[kq + 1][lm]      = b0.y;
        Bs[kq + 2][lm]      = b0.z; Bs[kq + 3][lm]      = b0.w;
        Bs[kq + 0][lm + 64] = b1.x; Bs[kq + 1][lm + 64] = b1.y;
        Bs[kq + 2][lm + 64] = b1.z; Bs[kq + 3][lm + 64] = b1.w;
        __syncthreads();
#pragma unroll
        for (int k = 0; k < 16; k++) {
            float av[8], bv[8];
            *reinterpret_cast<float4*>(&av[0]) =
                *reinterpret_cast<const float4*>(&As[k][tm << 3]);
            *reinterpret_cast<float4*>(&av[4]) =
                *reinterpret_cast<const float4*>(&As[k][(tm << 3) + 4]);
            *reinterpret_cast<float4*>(&bv[0]) =
                *reinterpret_cast<const float4*>(&Bs[k][tn << 3]);
            *reinterpret_cast<float4*>(&bv[4]) =
                *reinterpret_cast<const float4*>(&Bs[k][(tn << 3) + 4]);
#pragma unroll
            for (int i = 0; i < 8; i++)
#pragma unroll
                for (int j = 0; j < 8; j++)
                    acc[i][j] = fmaf(av[i], bv[j], acc[i][j]);
        }
    }
#pragma unroll
    for (int i = 0; i < 8; i++) {
        const int gr = rowBase + (tm << 3) + i;
        float v[8];
#pragma unroll
        for (int j = 0; j < 8; j++)
            v[j] = acc[i][j] + bias[colBase + (tn << 3) + j];
        float4* crow = reinterpret_cast<float4*>(
            Cout + (size_t)gr * Ncols + colBase + (tn << 3));
        crow[0] = make_float4(v[0], v[1], v[2], v[3]);
        crow[1] = make_float4(v[4], v[5], v[6], v[7]);
    }
}

__global__ void init_pa(float* __restrict__ pa1, float* __restrict__ pa2,
                        const float* __restrict__ blo)
{
    const int i = blockIdx.x * blockDim.x + threadIdx.x;
    if (i < Rr) {
        const float v = blo[0];
        pa1[i] = v;
        pa2[i] = v;
    }
}

// msum[b,v,m] = sum_w sig(pa2[b,v,w]) * (Mh+Ml)[(b,v,w), m]
__global__ void msum2(const __half* __restrict__ Mh,
                      const __half* __restrict__ Ml,
                      const float* __restrict__ pa2,
                      float* __restrict__ msum)
{
    const int bv = blockIdx.x;          // 0..1023
    const int t  = threadIdx.x;         // 128
    __shared__ float sg[64];
    if (t < 64) sg[t] = sigmoidf_(pa2[bv * 64 + t]);
    __syncthreads();
    const uint32_t* mh = reinterpret_cast<const uint32_t*>(Mh + (size_t)bv * 64 * 512);
    const uint32_t* ml = reinterpret_cast<const uint32_t*>(Ml + (size_t)bv * 64 * 512);
    const int c = t * 2;                // half2 index (cols 4t..4t+3)
    float a0 = 0.f, a1 = 0.f, a2 = 0.f, a3 = 0.f;
#pragma unroll 4
    for (int w = 0; w < 64; w++) {
        const float s = sg[w];
        const uint32_t h0 = mh[w * 256 + c],     l0 = ml[w * 256 + c];
        const uint32_t h1 = mh[w * 256 + c + 1], l1 = ml[w * 256 + c + 1];
        const __half2 H0 = *reinterpret_cast<const __half2*>(&h0);
        const __half2 L0 = *reinterpret_cast<const __half2*>(&l0);
        const __half2 H1 = *reinterpret_cast<const __half2*>(&h1);
        const __half2 L1 = *reinterpret_cast<const __half2*>(&l1);
        a0 = fmaf(s, __half2float(H0.x) + __half2float(L0.x), a0);
        a1 = fmaf(s, __half2float(H0.y) + __half2float(L0.y), a1);
        a2 = fmaf(s, __half2float(H1.x) + __half2float(L1.x), a2);
        a3 = fmaf(s, __half2float(H1.y) + __half2float(L1.y), a3);
    }
    float4* o = reinterpret_cast<float4*>(msum + (size_t)bv * 512) + t;
    *o = make_float4(a0, a1, a2, a3);
}

__global__ void gru_readout(const float* __restrict__ GI,
                            const float* __restrict__ GH,
                            const float* __restrict__ NF,
                            const float* __restrict__ Wr1, const float* __restrict__ br1,
                            const float* __restrict__ Wr2, const float* __restrict__ br2,
                            float* __restrict__ out)
{
    const int row = blockIdx.x;         // 0..1023
    __shared__ float hn[512];
    const int t = threadIdx.x;          // 256
    const float* gi = GI + (size_t)row * 1536;
    const float* gh = GH + (size_t)row * 1536;
    const float* h  = NF + (size_t)row * 512;
    for (int d = t; d < 512; d += 256) {
        const float r = sigmoidf_(gi[d] + gh[d]);
        const float z = sigmoidf_(gi[512 + d] + gh[512 + d]);
        const float n = tanhf(gi[1024 + d] + r * gh[1024 + d]);
        hn[d] = (1.0f - z) * n + z * h[d];
    }
    __syncthreads();
    const int warp = t >> 5, lane = t & 31;
    for (int o = warp; o < 28; o += 8) {
        const float* Wr = (o < 26) ? (Wr1 + o * 512) : (Wr2 + (o - 26) * 512);
        float acc = 0.0f;
        for (int k = lane; k < 512; k += 32) acc = fmaf(hn[k], Wr[k], acc);
#pragma unroll
        for (int off = 16; off; off >>= 1)
            acc += __shfl_down_sync(0xffffffffu, acc, off);
        if (lane == 0) {
            if (o < 26) out[65536 + row * 26 + o]               = acc + br1[o];
            else        out[65536 + 26624 + row * 2 + (o - 26)] = acc + br2[o - 26];
        }
    }
}

} // namespace

extern "C" void kernel_launch(void* const* d_in, const int* /*in_sizes*/, int /*n_in*/,
                              void* d_out, int /*out_size*/)
{
    const float* EF  = (const float*)d_in[0];
    const float* NF  = (const float*)d_in[1];
    const float* Wm  = (const float*)d_in[4];
    const float* bm  = (const float*)d_in[5];
    const float* Wl1 = (const float*)d_in[6];
    const float* bl1 = (const float*)d_in[7];
    const float* Wl2 = (const float*)d_in[8];
    const float* bl2 = (const float*)d_in[9];
    const float* Wlo = (const float*)d_in[10];
    const float* blo = (const float*)d_in[11];
    const float* Wih = (const float*)d_in[12];
    const float* bih = (const float*)d_in[13];
    const float* Whh = (const float*)d_in[14];
    const float* bhh = (const float*)d_in[15];
    const float* Wr1 = (const float*)d_in[16];
    const float* br1 = (const float*)d_in[17];
    const float* Wr2 = (const float*)d_in[18];
    const float* br2 = (const float*)d_in[19];
    float* out = (float*)d_out;

    __half *pEFh, *pEFl, *pMh, *pMl, *pTh, *pTl;
    __half *pWmh, *pW1h, *pW2h;
    float *pHn, *pPa1, *pMs, *pGI, *pGH;
    cudaGetSymbolAddress((void**)&pEFh, g_EFh);
    cudaGetSymbolAddress((void**)&pEFl, g_EFl);
    cudaGetSymbolAddress((void**)&pMh,  g_Mh);
    cudaGetSymbolAddress((void**)&pMl,  g_Ml);
    cudaGetSymbolAddress((void**)&pTh,  g_Th);
    cudaGetSymbolAddress((void**)&pTl,  g_Tl);
    cudaGetSymbolAddress((void**)&pWmh, g_Wmh);
    cudaGetSymbolAddress((void**)&pW1h, g_W1h);
    cudaGetSymbolAddress((void**)&pW2h, g_W2h);
    cudaGetSymbolAddress((void**)&pHn,  g_Hn);
    cudaGetSymbolAddress((void**)&pPa1, g_pa1);
    cudaGetSymbolAddress((void**)&pMs,  g_ms);
    cudaGetSymbolAddress((void**)&pGI,  g_GI);
    cudaGetSymbolAddress((void**)&pGH,  g_GH);

    cudaFuncSetAttribute(hmma_gemm<TEPI_MFUSE, false>,
                         cudaFuncAttributeMaxDynamicSharedMemorySize, SMEM_BYTES);
    cudaFuncSetAttribute(hmma_gemm<TEPI_RELU, false>,
                         cudaFuncAttributeMaxDynamicSharedMemorySize, SMEM_BYTES);
    cudaFuncSetAttribute(hmma_gemm<TEPI_RELU, true>,
                         cudaFuncAttributeMaxDynamicSharedMemorySize, SMEM_BYTES);
    cudaFuncSetAttribute(hmma_gemm<TEPI_DOT, false>,
                         cudaFuncAttributeMaxDynamicSharedMemorySize, SMEM_BYTES);

    const int n4 = Rr * Cc / 4;
    split_ef<<<(n4 + 255) / 256, 256>>>((const float4*)EF, (uint2*)pEFh, (uint2*)pEFl, n4);
    conv_w<<<1024, 256>>>(Wm,  1024, 512, pWmh);
    conv_w<<<1024, 256>>>(Wl1, 512,  0,   pW1h);
    conv_w<<<1024, 256>>>(Wl2, 512,  0,   pW2h);
    init_pa<<<(Rr + 255) / 256, 256>>>(pPa1, out, blo);

    // Hn = NF @ Wm[:, :512]^T + bm   (small SIMT GEMM, fp32)
    gemm512<<<dim3(4, 8), 256>>>(NF, Wm, 1024, 0, bm, pHn, Cc);

    const dim3 gTC(4, 256);   // 256-row x 128-col tiles
    // M = relu(EF @ WmE^T + Hn)  -> Mh/Ml
    hmma_gemm<TEPI_MFUSE, false><<<gTC, 512, SMEM_BYTES>>>(pEFh, pEFl, pWmh,
                                                           nullptr, pHn, nullptr, pMh, pMl, nullptr);
    // T1 = relu(EF @ Wl1^T + bl1) -> Th/Tl
    hmma_gemm<TEPI_RELU, false><<<gTC, 512, SMEM_BYTES>>>(pEFh, pEFl, pW1h,
                                                          bl1, nullptr, nullptr, pTh, pTl, nullptr);
    // pa1 += dot(relu(T1 @ Wl2^T + bl2), Wlo)
    hmma_gemm<TEPI_DOT, false><<<gTC, 512, SMEM_BYTES>>>(pTh, pTl, pW2h,
                                                         bl2, Wlo, nullptr, nullptr, nullptr, pPa1);
    // T1' = relu(sig(pa1[perm]) * M[perm] @ Wl1^T + bl1)
    hmma_gemm<TEPI_RELU, true><<<gTC, 512, SMEM_BYTES>>>(pMh, pMl, pW1h,
                                                         bl1, nullptr, pPa1, pTh, pTl, nullptr);
    // pred_adj += dot(relu(T1' @ Wl2^T + bl2), Wlo)
    hmma_gemm<TEPI_DOT, false><<<gTC, 512, SMEM_BYTES>>>(pTh, pTl, pW2h,
                                                         bl2, Wlo, nullptr, nullptr, nullptr, out);

    msum2<<<Bb * Nn, 128>>>(pMh, pMl, out, pMs);
    gemm512<<<dim3(12, 8), 256>>>(pMs, Wih, 512, 0, bih, pGI, 3 * Cc);
    gemm512<<<dim3(12, 8), 256>>>(NF,  Whh, 512, 0, bhh, pGH, 3 * Cc);
    gru_readout<<<Bb * Nn, 256>>>(pGI, pGH, NF, Wr1, br1, Wr2, br2, out);
}

// round 6
// speedup vs baseline: 4.3059x; 1.2777x over previous
#include <cuda_runtime.h>
#include <cuda_fp16.h>
#include <math.h>
#include <stdint.h>

// ---------------------------------------------------------------------------
// GPNN_VCOCO forward — fp16 split GEMMs on warp-level mma.sync.
// R6: DOT GEMMs use single-plane T1 (K=512); RELU GEMMs write hi plane only;
// GI/GH/Hn moved to HMMA with 3-plane (near-fp32) schedule + fp32 BIAS
// epilogue; msum emits fp16 hi/lo planes directly.
// ---------------------------------------------------------------------------

namespace {

constexpr int Bb = 16;
constexpr int Nn = 64;
constexpr int Cc = 512;
constexpr int Rr = Bb * Nn * Nn;   // 65536

// ---------------- scratch (static device globals) ----------------
__device__ __half g_EFh[Rr * Cc], g_EFl[Rr * Cc];
__device__ __half g_Mh [Rr * Cc], g_Ml [Rr * Cc];
__device__ __half g_Th [Rr * Cc];
__device__ __half g_Wmh [Cc * Cc];                 // Wm edge half, hi
__device__ __half g_WmNh[Cc * Cc], g_WmNl[Cc * Cc];// Wm node half, hi/lo
__device__ __half g_W1h [Cc * Cc];
__device__ __half g_W2h [Cc * Cc];
__device__ __half g_Wihh[3 * Cc * Cc], g_Wihl[3 * Cc * Cc];
__device__ __half g_Whhh[3 * Cc * Cc], g_Whhl[3 * Cc * Cc];
__device__ __half g_NFh [Bb * Nn * Cc], g_NFl[Bb * Nn * Cc];
__device__ __half g_msh [Bb * Nn * Cc], g_msl[Bb * Nn * Cc];
__device__ float g_Hn [Bb * Nn * Cc];
__device__ float g_pa1[Rr];
__device__ float g_GI [Bb * Nn * 3 * Cc];
__device__ float g_GH [Bb * Nn * 3 * Cc];

__device__ __forceinline__ float sigmoidf_(float x) {
    return 1.0f / (1.0f + __expf(-x));
}
__device__ __forceinline__ int permrow(int gr) {
    return (gr & ~4095) | ((gr & 63) << 6) | ((gr >> 6) & 63);
}
__device__ __forceinline__ uint32_t smem_u32(const void* p) {
    uint32_t a;
    asm("{ .reg .u64 t; cvta.to.shared.u64 t, %1; cvt.u32.u64 %0, t; }"
        : "=r"(a) : "l"(p));
    return a;
}
__device__ __forceinline__ uint32_t swz(uint32_t o) {   // 128B-row xor swizzle
    return o ^ ((o >> 3) & 0x70);
}
__device__ __forceinline__ void cp16(uint32_t saddr, const void* g) {
    asm volatile("cp.async.cg.shared.global [%0], [%1], 16;"
                 :: "r"(saddr), "l"(g) : "memory");
}
__device__ __forceinline__ void cp_commit() {
    asm volatile("cp.async.commit_group;" ::: "memory");
}
template<int N>
__device__ __forceinline__ void cp_wait() {
    asm volatile("cp.async.wait_group %0;" :: "n"(N) : "memory");
}
__device__ __forceinline__ void ldm_x4(uint32_t* r, uint32_t addr) {
    asm volatile("ldmatrix.sync.aligned.m8n8.x4.shared.b16 {%0,%1,%2,%3}, [%4];"
                 : "=r"(r[0]), "=r"(r[1]), "=r"(r[2]), "=r"(r[3]) : "r"(addr));
}
__device__ __forceinline__ void mma16816(float* c, const uint32_t* a,
                                         uint32_t b0, uint32_t b1) {
    asm volatile(
        "mma.sync.aligned.m16n8k16.row.col.f32.f16.f16.f32 "
        "{%0,%1,%2,%3}, {%4,%5,%6,%7}, {%8,%9}, {%0,%1,%2,%3};"
        : "+f"(c[0]), "+f"(c[1]), "+f"(c[2]), "+f"(c[3])
        : "r"(a[0]), "r"(a[1]), "r"(a[2]), "r"(a[3]), "r"(b0), "r"(b1));
}

enum { TEPI_MFUSE = 0, TEPI_RELU = 1, TEPI_DOT = 2, TEPI_BIAS = 3 };

constexpr int STAGE_BYTES = 49152;           // 32KB A (256x64 fp16) + 16KB B
constexpr int SMEM_BYTES  = 3 * STAGE_BYTES; // 144KB

// ---------------------------------------------------------------------------
// HMMA GEMM: out[r,n] = epi( sum_{k<512} A[r,k]*W[n,k] ).
// PLANES: 1 = Ah*Bh; 2 = +Al*Bh; 3 = +Ah*Bl (near-fp32).
// CTA 256x128, 512 thr = 16 warps (4m x 4n), warp tile 64x32, K-chunk 64,
// 3-stage cp.async pipeline (one __syncthreads per chunk).
// ---------------------------------------------------------------------------
template<int EPI, bool PERM, int PLANES, bool WLO>
__global__ void __launch_bounds__(512, 1)
hmma_gemm(const __half* __restrict__ Ah, const __half* __restrict__ Al,
          const __half* __restrict__ Bh, const __half* __restrict__ Bl,
          const float* __restrict__ bias,   // bl1/bl2/bm/bih/bhh
          const float* __restrict__ extra,  // Hn (MFUSE) | Wlo (DOT)
          const float* __restrict__ pa,     // pa1 logits (PERM)
          __half* __restrict__ Ch, __half* __restrict__ Cl,
          float* __restrict__ Cf, int ldC,  // fp32 out (BIAS)
          float* __restrict__ dotOut)
{
    extern __shared__ __align__(128) uint8_t smem[];
    const uint32_t sBase = smem_u32(smem);
    constexpr int NCHUNK = PLANES * 8;

    const int tid = threadIdx.x;
    const int wid = tid >> 5, lane = tid & 31;
    const int warp_m = wid & 3, warp_n = wid >> 2;
    const int rowBase = blockIdx.y << 8;    // 256-row blocks
    const int colBase = blockIdx.x << 7;    // 128-col blocks

    // ---- loader: A = 4 sweeps of 64 rows, B = 2 sweeps (16B per cp)
    const int lrow = tid >> 3, lseg = tid & 7;
    uint32_t aOff[4], sAOff[4], bOff[2], sBOff[2];
#pragma unroll
    for (int i = 0; i < 4; i++) {
        const int row = lrow + i * 64;
        int sr = rowBase + row;
        if (PERM) sr = permrow(sr);
        aOff[i]  = (uint32_t)sr * 512u + lseg * 8;
        sAOff[i] = swz((uint32_t)row * 128 + lseg * 16);
    }
#pragma unroll
    for (int i = 0; i < 2; i++) {
        const int row = lrow + i * 64;
        bOff[i]  = (uint32_t)(colBase + row) * 512u + lseg * 8;
        sBOff[i] = swz((uint32_t)row * 128 + lseg * 16);
    }

    auto load_stage = [&](int st, int ch) {
        const int p  = ch >> 3;
        const int kb = (ch & 7) * 64;
        const __half* Ap = (p == 1) ? Al : Ah;
        const __half* Bp = (p == 2) ? Bl : Bh;
        const uint32_t sa = sBase + st * STAGE_BYTES;
        const uint32_t sb = sa + 32768;
#pragma unroll
        for (int i = 0; i < 4; i++) cp16(sa + sAOff[i], Ap + aOff[i] + kb);
#pragma unroll
        for (int i = 0; i < 2; i++) cp16(sb + sBOff[i], Bp + bOff[i] + kb);
        cp_commit();
    };

    load_stage(0, 0);
    load_stage(1, 1);

    float acc[4][4][4];
#pragma unroll
    for (int mt = 0; mt < 4; mt++)
#pragma unroll
        for (int nf = 0; nf < 4; nf++)
#pragma unroll
            for (int j = 0; j < 4; j++) acc[mt][nf][j] = 0.0f;

    // ldmatrix lane addressing
    const int aRow = warp_m * 64 + ((lane >> 3) & 1) * 8 + (lane & 7);
    const uint32_t aK = (uint32_t)(lane >> 4) * 16;
    const int bRow = warp_n * 32 + (lane >> 4) * 8 + (lane & 7);
    const uint32_t bK = (uint32_t)((lane >> 3) & 1) * 16;

#pragma unroll 1
    for (int ch = 0; ch < NCHUNK; ch++) {
        if (ch < NCHUNK - 1) cp_wait<1>(); else cp_wait<0>();
        __syncthreads();
        if (ch + 2 < NCHUNK) load_stage((ch + 2) % 3, ch + 2);

        const uint32_t sa = sBase + (ch % 3) * STAGE_BYTES;
        const uint32_t sb = sa + 32768;
#pragma unroll
        for (int ks = 0; ks < 4; ks++) {
            uint32_t a[4][4], b[2][4];
#pragma unroll
            for (int mt = 0; mt < 4; mt++)
                ldm_x4(a[mt], sa + swz((uint32_t)(aRow + mt * 16) * 128 + ks * 32 + aK));
#pragma unroll
            for (int pr = 0; pr < 2; pr++)
                ldm_x4(b[pr], sb + swz((uint32_t)(bRow + pr * 16) * 128 + ks * 32 + bK));
#pragma unroll
            for (int mt = 0; mt < 4; mt++)
#pragma unroll
                for (int nf = 0; nf < 4; nf++)
                    mma16816(acc[mt][nf], a[mt],
                             b[nf >> 1][(nf & 1) * 2], b[nf >> 1][(nf & 1) * 2 + 1]);
        }
    }

    // ---------------- epilogue ----------------
    // c-frag: c0:(m=l/4, n=2(l%4))  c1:n+1  c2:(m+8)  c3:(m+8,n+1)
    const int r0 = rowBase + warp_m * 64 + (lane >> 2);
    const int c0 = colBase + warp_n * 32 + (lane & 3) * 2;

    if (EPI == TEPI_DOT) {
        float dsum[4][2];
#pragma unroll
        for (int mt = 0; mt < 4; mt++) { dsum[mt][0] = 0.f; dsum[mt][1] = 0.f; }
#pragma unroll
        for (int mt = 0; mt < 4; mt++)
#pragma unroll
            for (int nf = 0; nf < 4; nf++) {
                const int gc = c0 + nf * 8;
                const float b0v = bias[gc], b1v = bias[gc + 1];
                const float w0v = extra[gc], w1v = extra[gc + 1];
                dsum[mt][0] += fmaxf(acc[mt][nf][0] + b0v, 0.f) * w0v
                             + fmaxf(acc[mt][nf][1] + b1v, 0.f) * w1v;
                dsum[mt][1] += fmaxf(acc[mt][nf][2] + b0v, 0.f) * w0v
                             + fmaxf(acc[mt][nf][3] + b1v, 0.f) * w1v;
            }
#pragma unroll
        for (int mt = 0; mt < 4; mt++)
#pragma unroll
            for (int h = 0; h < 2; h++) {
                float v = dsum[mt][h];
                v += __shfl_xor_sync(0xffffffffu, v, 1);
                v += __shfl_xor_sync(0xffffffffu, v, 2);
                if ((lane & 3) == 0)
                    atomicAdd(dotOut + r0 + mt * 16 + h * 8, v);
            }
    } else if (EPI == TEPI_BIAS) {
#pragma unroll
        for (int mt = 0; mt < 4; mt++)
#pragma unroll
            for (int h = 0; h < 2; h++) {
                const int row = r0 + mt * 16 + h * 8;
                float2* orow = reinterpret_cast<float2*>(Cf + (size_t)row * ldC);
#pragma unroll
                for (int nf = 0; nf < 4; nf++) {
                    const int gc = c0 + nf * 8;
                    orow[gc >> 1] = make_float2(acc[mt][nf][h * 2] + bias[gc],
                                                acc[mt][nf][h * 2 + 1] + bias[gc + 1]);
                }
            }
    } else {
#pragma unroll
        for (int mt = 0; mt < 4; mt++)
#pragma unroll
            for (int h = 0; h < 2; h++) {
                const int row = r0 + mt * 16 + h * 8;
                float s = 1.0f;
                const float* hnrow = nullptr;
                if (EPI == TEPI_MFUSE)
                    hnrow = extra + (size_t)(((row >> 12) << 6) | (row & 63)) * 512;
                if (PERM) s = sigmoidf_(pa[permrow(row)]);
                uint32_t* oh = reinterpret_cast<uint32_t*>(Ch) + ((size_t)row * 512 >> 1);
                uint32_t* ol = reinterpret_cast<uint32_t*>(Cl) + ((size_t)row * 512 >> 1);
#pragma unroll
                for (int nf = 0; nf < 4; nf++) {
                    const int gc = c0 + nf * 8;
                    const float x0 = acc[mt][nf][h * 2 + 0];
                    const float x1 = acc[mt][nf][h * 2 + 1];
                    float y0, y1;
                    if (EPI == TEPI_MFUSE) {
                        y0 = fmaxf(x0 + hnrow[gc],     0.0f);
                        y1 = fmaxf(x1 + hnrow[gc + 1], 0.0f);
                    } else {
                        y0 = fmaxf(fmaf(s, x0, bias[gc]),     0.0f);
                        y1 = fmaxf(fmaf(s, x1, bias[gc + 1]), 0.0f);
                    }
                    __half2 h2;
                    h2.x = __float2half_rn(y0);
                    h2.y = __float2half_rn(y1);
                    oh[gc >> 1] = *reinterpret_cast<uint32_t*>(&h2);
                    if (WLO) {
                        __half2 l2;
                        l2.x = __float2half_rn(y0 - __half2float(h2.x));
                        l2.y = __float2half_rn(y1 - __half2float(h2.y));
                        ol[gc >> 1] = *reinterpret_cast<uint32_t*>(&l2);
                    }
                }
            }
    }
}

// ---------------------------------------------------------------------------
// conversions
// ---------------------------------------------------------------------------
__global__ void split_f32(const float4* __restrict__ in,
                          uint2* __restrict__ hi, uint2* __restrict__ lo, int n4)
{
    const int i = blockIdx.x * blockDim.x + threadIdx.x;
    if (i >= n4) return;
    const float4 v = in[i];
    __half2 hA, hB, lA, lB;
    hA.x = __float2half_rn(v.x); hA.y = __float2half_rn(v.y);
    hB.x = __float2half_rn(v.z); hB.y = __float2half_rn(v.w);
    lA.x = __float2half_rn(v.x - __half2float(hA.x));
    lA.y = __float2half_rn(v.y - __half2float(hA.y));
    lB.x = __float2half_rn(v.z - __half2float(hB.x));
    lB.y = __float2half_rn(v.w - __half2float(hB.y));
    hi[i] = make_uint2(*reinterpret_cast<uint32_t*>(&hA), *reinterpret_cast<uint32_t*>(&hB));
    lo[i] = make_uint2(*reinterpret_cast<uint32_t*>(&lA), *reinterpret_cast<uint32_t*>(&lB));
}

__global__ void conv_w_h(const float* __restrict__ W, int ldW, int koff,
                         __half* __restrict__ hi)
{
    const int idx = blockIdx.x * blockDim.x + threadIdx.x;
    const int row = idx >> 9, k = idx & 511;
    hi[idx] = __float2half_rn(W[(size_t)row * ldW + koff + k]);
}

__global__ void conv_w_hl(const float* __restrict__ W, int ldW, int koff,
                          __half* __restrict__ hi, __half* __restrict__ lo)
{
    const int idx = blockIdx.x * blockDim.x + threadIdx.x;
    const int row = idx >> 9, k = idx & 511;
    const float x = W[(size_t)row * ldW + koff + k];
    const __half h = __float2half_rn(x);
    hi[idx] = h;
    lo[idx] = __float2half_rn(x - __half2float(h));
}

__global__ void init_pa(float* __restrict__ pa1, float* __restrict__ pa2,
                        const float* __restrict__ blo)
{
    const int i = blockIdx.x * blockDim.x + threadIdx.x;
    if (i < Rr) {
        const float v = blo[0];
        pa1[i] = v;
        pa2[i] = v;
    }
}

// msum[b,v,:] = sum_w sig(pa2[b,v,w]) * (Mh+Ml)[(b,v,w), :]  -> fp16 hi/lo
__global__ void msum2(const __half* __restrict__ Mh,
                      const __half* __restrict__ Ml,
                      const float* __restrict__ pa2,
                      __half* __restrict__ msh, __half* __restrict__ msl)
{
    const int bv = blockIdx.x;          // 0..1023
    const int t  = threadIdx.x;         // 128
    __shared__ float sg[64];
    if (t < 64) sg[t] = sigmoidf_(pa2[bv * 64 + t]);
    __syncthreads();
    const uint32_t* mh = reinterpret_cast<const uint32_t*>(Mh + (size_t)bv * 64 * 512);
    const uint32_t* ml = reinterpret_cast<const uint32_t*>(Ml + (size_t)bv * 64 * 512);
    const int c = t * 2;                // half2 index (cols 4t..4t+3)
    float a0 = 0.f, a1 = 0.f, a2 = 0.f, a3 = 0.f;
#pragma unroll 4
    for (int w = 0; w < 64; w++) {
        const float s = sg[w];
        const uint32_t h0 = mh[w * 256 + c],     l0 = ml[w * 256 + c];
        const uint32_t h1 = mh[w * 256 + c + 1], l1 = ml[w * 256 + c + 1];
        const __half2 H0 = *reinterpret_cast<const __half2*>(&h0);
        const __half2 L0 = *reinterpret_cast<const __half2*>(&l0);
        const __half2 H1 = *reinterpret_cast<const __half2*>(&h1);
        const __half2 L1 = *reinterpret_cast<const __half2*>(&l1);
        a0 = fmaf(s, __half2float(H0.x) + __half2float(L0.x), a0);
        a1 = fmaf(s, __half2float(H0.y) + __half2float(L0.y), a1);
        a2 = fmaf(s, __half2float(H1.x) + __half2float(L1.x), a2);
        a3 = fmaf(s, __half2float(H1.y) + __half2float(L1.y), a3);
    }
    __half2 h2a, h2b, l2a, l2b;
    h2a.x = __float2half_rn(a0); h2a.y = __float2half_rn(a1);
    h2b.x = __float2half_rn(a2); h2b.y = __float2half_rn(a3);
    l2a.x = __float2half_rn(a0 - __half2float(h2a.x));
    l2a.y = __float2half_rn(a1 - __half2float(h2a.y));
    l2b.x = __float2half_rn(a2 - __half2float(h2b.x));
    l2b.y = __float2half_rn(a3 - __half2float(h2b.y));
    uint2* oh = reinterpret_cast<uint2*>(msh + (size_t)bv * 512) + t;
    uint2* ol = reinterpret_cast<uint2*>(msl + (size_t)bv * 512) + t;
    *oh = make_uint2(*reinterpret_cast<uint32_t*>(&h2a), *reinterpret_cast<uint32_t*>(&h2b));
    *ol = make_uint2(*reinterpret_cast<uint32_t*>(&l2a), *reinterpret_cast<uint32_t*>(&l2b));
}

__global__ void gru_readout(const float* __restrict__ GI,
                            const float* __restrict__ GH,
                            const float* __restrict__ NF,
                            const float* __restrict__ Wr1, const float* __restrict__ br1,
                            const float* __restrict__ Wr2, const float* __restrict__ br2,
                            float* __restrict__ out)
{
    const int row = blockIdx.x;         // 0..1023
    __shared__ float hn[512];
    const int t = threadIdx.x;          // 256
    const float* gi = GI + (size_t)row * 1536;
    const float* gh = GH + (size_t)row * 1536;
    const float* h  = NF + (size_t)row * 512;
    for (int d = t; d < 512; d += 256) {
        const float r = sigmoidf_(gi[d] + gh[d]);
        const float z = sigmoidf_(gi[512 + d] + gh[512 + d]);
        const float n = tanhf(gi[1024 + d] + r * gh[1024 + d]);
        hn[d] = (1.0f - z) * n + z * h[d];
    }
    __syncthreads();
    const int warp = t >> 5, lane = t & 31;
    for (int o = warp; o < 28; o += 8) {
        const float* Wr = (o < 26) ? (Wr1 + o * 512) : (Wr2 + (o - 26) * 512);
        float acc = 0.0f;
        for (int k = lane; k < 512; k += 32) acc = fmaf(hn[k], Wr[k], acc);
#pragma unroll
        for (int off = 16; off; off >>= 1)
            acc += __shfl_down_sync(0xffffffffu, acc, off);
        if (lane == 0) {
            if (o < 26) out[65536 + row * 26 + o]               = acc + br1[o];
            else        out[65536 + 26624 + row * 2 + (o - 26)] = acc + br2[o - 26];
        }
    }
}

} // namespace

extern "C" void kernel_launch(void* const* d_in, const int* /*in_sizes*/, int /*n_in*/,
                              void* d_out, int /*out_size*/)
{
    const float* EF  = (const float*)d_in[0];
    const float* NF  = (const float*)d_in[1];
    const float* Wm  = (const float*)d_in[4];
    const float* bm  = (const float*)d_in[5];
    const float* Wl1 = (const float*)d_in[6];
    const float* bl1 = (const float*)d_in[7];
    const float* Wl2 = (const float*)d_in[8];
    const float* bl2 = (const float*)d_in[9];
    const float* Wlo = (const float*)d_in[10];
    const float* blo = (const float*)d_in[11];
    const float* Wih = (const float*)d_in[12];
    const float* bih = (const float*)d_in[13];
    const float* Whh = (const float*)d_in[14];
    const float* bhh = (const float*)d_in[15];
    const float* Wr1 = (const float*)d_in[16];
    const float* br1 = (const float*)d_in[17];
    const float* Wr2 = (const float*)d_in[18];
    const float* br2 = (const float*)d_in[19];
    float* out = (float*)d_out;

    __half *pEFh, *pEFl, *pMh, *pMl, *pTh;
    __half *pWmh, *pWmNh, *pWmNl, *pW1h, *pW2h;
    __half *pWihh, *pWihl, *pWhhh, *pWhhl, *pNFh, *pNFl, *pmsh, *pmsl;
    float *pHn, *pPa1, *pGI, *pGH;
    cudaGetSymbolAddress((void**)&pEFh,  g_EFh);
    cudaGetSymbolAddress((void**)&pEFl,  g_EFl);
    cudaGetSymbolAddress((void**)&pMh,   g_Mh);
    cudaGetSymbolAddress((void**)&pMl,   g_Ml);
    cudaGetSymbolAddress((void**)&pTh,   g_Th);
    cudaGetSymbolAddress((void**)&pWmh,  g_Wmh);
    cudaGetSymbolAddress((void**)&pWmNh, g_WmNh);
    cudaGetSymbolAddress((void**)&pWmNl, g_WmNl);
    cudaGetSymbolAddress((void**)&pW1h,  g_W1h);
    cudaGetSymbolAddress((void**)&pW2h,  g_W2h);
    cudaGetSymbolAddress((void**)&pWihh, g_Wihh);
    cudaGetSymbolAddress((void**)&pWihl, g_Wihl);
    cudaGetSymbolAddress((void**)&pWhhh, g_Whhh);
    cudaGetSymbolAddress((void**)&pWhhl, g_Whhl);
    cudaGetSymbolAddress((void**)&pNFh,  g_NFh);
    cudaGetSymbolAddress((void**)&pNFl,  g_NFl);
    cudaGetSymbolAddress((void**)&pmsh,  g_msh);
    cudaGetSymbolAddress((void**)&pmsl,  g_msl);
    cudaGetSymbolAddress((void**)&pHn,   g_Hn);
    cudaGetSymbolAddress((void**)&pPa1,  g_pa1);
    cudaGetSymbolAddress((void**)&pGI,   g_GI);
    cudaGetSymbolAddress((void**)&pGH,   g_GH);

    // kernel variants
    auto kBIAS = hmma_gemm<TEPI_BIAS,  false, 3, false>;
    auto kMF   = hmma_gemm<TEPI_MFUSE, false, 2, true>;
    auto kRE   = hmma_gemm<TEPI_RELU,  false, 2, false>;
    auto kRP   = hmma_gemm<TEPI_RELU,  true,  2, false>;
    auto kDOT  = hmma_gemm<TEPI_DOT,   false, 1, false>;
    cudaFuncSetAttribute(kBIAS, cudaFuncAttributeMaxDynamicSharedMemorySize, SMEM_BYTES);
    cudaFuncSetAttribute(kMF,   cudaFuncAttributeMaxDynamicSharedMemorySize, SMEM_BYTES);
    cudaFuncSetAttribute(kRE,   cudaFuncAttributeMaxDynamicSharedMemorySize, SMEM_BYTES);
    cudaFuncSetAttribute(kRP,   cudaFuncAttributeMaxDynamicSharedMemorySize, SMEM_BYTES);
    cudaFuncSetAttribute(kDOT,  cudaFuncAttributeMaxDynamicSharedMemorySize, SMEM_BYTES);

    const int n4ef = Rr * Cc / 4;
    const int n4nf = Bb * Nn * Cc / 4;
    split_f32<<<(n4ef + 255) / 256, 256>>>((const float4*)EF, (uint2*)pEFh, (uint2*)pEFl, n4ef);
    split_f32<<<(n4nf + 255) / 256, 256>>>((const float4*)NF, (uint2*)pNFh, (uint2*)pNFl, n4nf);
    conv_w_h <<<1024, 256>>>(Wm, 1024, 512, pWmh);            // edge half, hi
    conv_w_hl<<<1024, 256>>>(Wm, 1024, 0, pWmNh, pWmNl);      // node half, hi/lo
    conv_w_h <<<1024, 256>>>(Wl1, 512, 0, pW1h);
    conv_w_h <<<1024, 256>>>(Wl2, 512, 0, pW2h);
    conv_w_hl<<<3072, 256>>>(Wih, 512, 0, pWihh, pWihl);
    conv_w_hl<<<3072, 256>>>(Whh, 512, 0, pWhhh, pWhhl);
    init_pa<<<(Rr + 255) / 256, 256>>>(pPa1, out, blo);

    // Hn = NF @ Wm[:, :512]^T + bm   (3-plane, fp32 out)
    kBIAS<<<dim3(4, 4), 512, SMEM_BYTES>>>(pNFh, pNFl, pWmNh, pWmNl, bm,
                                           nullptr, nullptr, nullptr, nullptr,
                                           pHn, 512, nullptr);

    const dim3 gTC(4, 256);   // 256-row x 128-col tiles, 65536 rows
    // M = relu(EF @ WmE^T + Hn)  -> Mh/Ml
    kMF<<<gTC, 512, SMEM_BYTES>>>(pEFh, pEFl, pWmh, nullptr, nullptr, pHn,
                                  nullptr, pMh, pMl, nullptr, 0, nullptr);
    // T1 = relu(EF @ Wl1^T + bl1) -> Th (hi only)
    kRE<<<gTC, 512, SMEM_BYTES>>>(pEFh, pEFl, pW1h, nullptr, bl1, nullptr,
                                  nullptr, pTh, nullptr, nullptr, 0, nullptr);
    // pa1 += dot(relu(T1 @ Wl2^T + bl2), Wlo)   (single plane, K=512)
    kDOT<<<gTC, 512, SMEM_BYTES>>>(pTh, nullptr, pW2h, nullptr, bl2, Wlo,
                                   nullptr, nullptr, nullptr, nullptr, 0, pPa1);
    // T1' = relu(sig(pa1[perm]) * M[perm] @ Wl1^T + bl1) -> Th
    kRP<<<gTC, 512, SMEM_BYTES>>>(pMh, pMl, pW1h, nullptr, bl1, nullptr,
                                  pPa1, pTh, nullptr, nullptr, 0, nullptr);
    // pred_adj += dot(relu(T1' @ Wl2^T + bl2), Wlo)
    kDOT<<<gTC, 512, SMEM_BYTES>>>(pTh, nullptr, pW2h, nullptr, bl2, Wlo,
                                   nullptr, nullptr, nullptr, nullptr, 0, out);

    msum2<<<Bb * Nn, 128>>>(pMh, pMl, out, pmsh, pmsl);
    // GI = msum @ W_ih^T + b_ih   (3-plane)
    kBIAS<<<dim3(12, 4), 512, SMEM_BYTES>>>(pmsh, pmsl, pWihh, pWihl, bih,
                                            nullptr, nullptr, nullptr, nullptr,
                                            pGI, 1536, nullptr);
    // GH = NF @ W_hh^T + b_hh     (3-plane)
    kBIAS<<<dim3(12, 4), 512, SMEM_BYTES>>>(pNFh, pNFl, pWhhh, pWhhl, bhh,
                                            nullptr, nullptr, nullptr, nullptr,
                                            pGH, 1536, nullptr);
    gru_readout<<<Bb * Nn, 256>>>(pGI, pGH, NF, Wr1, br1, Wr2, br2, out);
}

// round 7
// speedup vs baseline: 5.1200x; 1.1891x over previous
#include <cuda_runtime.h>
#include <cuda_fp16.h>
#include <math.h>
#include <stdint.h>

// ---------------------------------------------------------------------------
// GPNN_VCOCO forward — fp16 split GEMMs on warp-level mma.sync.
// R7: kMF and kRE single-plane (EFh only; EF lo plane eliminated);
// M still stored hi/lo so kRP (2-plane) and msum keep full fp16-pair
// precision; DOT GEMMs single-plane; GRU/Hn GEMMs 3-plane near-fp32.
// ---------------------------------------------------------------------------

namespace {

constexpr int Bb = 16;
constexpr int Nn = 64;
constexpr int Cc = 512;
constexpr int Rr = Bb * Nn * Nn;   // 65536

// ---------------- scratch (static device globals) ----------------
__device__ __half g_EFh[Rr * Cc];
__device__ __half g_Mh [Rr * Cc], g_Ml [Rr * Cc];
__device__ __half g_Th [Rr * Cc];
__device__ __half g_Wmh [Cc * Cc];                 // Wm edge half, hi
__device__ __half g_WmNh[Cc * Cc], g_WmNl[Cc * Cc];// Wm node half, hi/lo
__device__ __half g_W1h [Cc * Cc];
__device__ __half g_W2h [Cc * Cc];
__device__ __half g_Wihh[3 * Cc * Cc], g_Wihl[3 * Cc * Cc];
__device__ __half g_Whhh[3 * Cc * Cc], g_Whhl[3 * Cc * Cc];
__device__ __half g_NFh [Bb * Nn * Cc], g_NFl[Bb * Nn * Cc];
__device__ __half g_msh [Bb * Nn * Cc], g_msl[Bb * Nn * Cc];
__device__ float g_Hn [Bb * Nn * Cc];
__device__ float g_pa1[Rr];
__device__ float g_GI [Bb * Nn * 3 * Cc];
__device__ float g_GH [Bb * Nn * 3 * Cc];

__device__ __forceinline__ float sigmoidf_(float x) {
    return 1.0f / (1.0f + __expf(-x));
}
__device__ __forceinline__ int permrow(int gr) {
    return (gr & ~4095) | ((gr & 63) << 6) | ((gr >> 6) & 63);
}
__device__ __forceinline__ uint32_t smem_u32(const void* p) {
    uint32_t a;
    asm("{ .reg .u64 t; cvta.to.shared.u64 t, %1; cvt.u32.u64 %0, t; }"
        : "=r"(a) : "l"(p));
    return a;
}
__device__ __forceinline__ uint32_t swz(uint32_t o) {   // 128B-row xor swizzle
    return o ^ ((o >> 3) & 0x70);
}
__device__ __forceinline__ void cp16(uint32_t saddr, const void* g) {
    asm volatile("cp.async.cg.shared.global [%0], [%1], 16;"
                 :: "r"(saddr), "l"(g) : "memory");
}
__device__ __forceinline__ void cp_commit() {
    asm volatile("cp.async.commit_group;" ::: "memory");
}
template<int N>
__device__ __forceinline__ void cp_wait() {
    asm volatile("cp.async.wait_group %0;" :: "n"(N) : "memory");
}
__device__ __forceinline__ void ldm_x4(uint32_t* r, uint32_t addr) {
    asm volatile("ldmatrix.sync.aligned.m8n8.x4.shared.b16 {%0,%1,%2,%3}, [%4];"
                 : "=r"(r[0]), "=r"(r[1]), "=r"(r[2]), "=r"(r[3]) : "r"(addr));
}
__device__ __forceinline__ void mma16816(float* c, const uint32_t* a,
                                         uint32_t b0, uint32_t b1) {
    asm volatile(
        "mma.sync.aligned.m16n8k16.row.col.f32.f16.f16.f32 "
        "{%0,%1,%2,%3}, {%4,%5,%6,%7}, {%8,%9}, {%0,%1,%2,%3};"
        : "+f"(c[0]), "+f"(c[1]), "+f"(c[2]), "+f"(c[3])
        : "r"(a[0]), "r"(a[1]), "r"(a[2]), "r"(a[3]), "r"(b0), "r"(b1));
}

enum { TEPI_MFUSE = 0, TEPI_RELU = 1, TEPI_DOT = 2, TEPI_BIAS = 3 };

constexpr int STAGE_BYTES = 49152;           // 32KB A (256x64 fp16) + 16KB B
constexpr int SMEM_BYTES  = 3 * STAGE_BYTES; // 144KB

// ---------------------------------------------------------------------------
// HMMA GEMM: out[r,n] = epi( sum_{k<512} A[r,k]*W[n,k] ).
// PLANES: 1 = Ah*Bh; 2 = +Al*Bh; 3 = +Ah*Bl (near-fp32).
// CTA 256x128, 512 thr = 16 warps (4m x 4n), warp tile 64x32, K-chunk 64,
// 3-stage cp.async pipeline (one __syncthreads per chunk).
// ---------------------------------------------------------------------------
template<int EPI, bool PERM, int PLANES, bool WLO>
__global__ void __launch_bounds__(512, 1)
hmma_gemm(const __half* __restrict__ Ah, const __half* __restrict__ Al,
          const __half* __restrict__ Bh, const __half* __restrict__ Bl,
          const float* __restrict__ bias,   // bl1/bl2/bm/bih/bhh
          const float* __restrict__ extra,  // Hn (MFUSE) | Wlo (DOT)
          const float* __restrict__ pa,     // pa1 logits (PERM)
          __half* __restrict__ Ch, __half* __restrict__ Cl,
          float* __restrict__ Cf, int ldC,  // fp32 out (BIAS)
          float* __restrict__ dotOut)
{
    extern __shared__ __align__(128) uint8_t smem[];
    const uint32_t sBase = smem_u32(smem);
    constexpr int NCHUNK = PLANES * 8;

    const int tid = threadIdx.x;
    const int wid = tid >> 5, lane = tid & 31;
    const int warp_m = wid & 3, warp_n = wid >> 2;
    const int rowBase = blockIdx.y << 8;    // 256-row blocks
    const int colBase = blockIdx.x << 7;    // 128-col blocks

    // ---- loader: A = 4 sweeps of 64 rows, B = 2 sweeps (16B per cp)
    const int lrow = tid >> 3, lseg = tid & 7;
    uint32_t aOff[4], sAOff[4], bOff[2], sBOff[2];
#pragma unroll
    for (int i = 0; i < 4; i++) {
        const int row = lrow + i * 64;
        int sr = rowBase + row;
        if (PERM) sr = permrow(sr);
        aOff[i]  = (uint32_t)sr * 512u + lseg * 8;
        sAOff[i] = swz((uint32_t)row * 128 + lseg * 16);
    }
#pragma unroll
    for (int i = 0; i < 2; i++) {
        const int row = lrow + i * 64;
        bOff[i]  = (uint32_t)(colBase + row) * 512u + lseg * 8;
        sBOff[i] = swz((uint32_t)row * 128 + lseg * 16);
    }

    auto load_stage = [&](int st, int ch) {
        const int p  = ch >> 3;
        const int kb = (ch & 7) * 64;
        const __half* Ap = (p == 1) ? Al : Ah;
        const __half* Bp = (p == 2) ? Bl : Bh;
        const uint32_t sa = sBase + st * STAGE_BYTES;
        const uint32_t sb = sa + 32768;
#pragma unroll
        for (int i = 0; i < 4; i++) cp16(sa + sAOff[i], Ap + aOff[i] + kb);
#pragma unroll
        for (int i = 0; i < 2; i++) cp16(sb + sBOff[i], Bp + bOff[i] + kb);
        cp_commit();
    };

    load_stage(0, 0);
    load_stage(1, 1);

    float acc[4][4][4];
#pragma unroll
    for (int mt = 0; mt < 4; mt++)
#pragma unroll
        for (int nf = 0; nf < 4; nf++)
#pragma unroll
            for (int j = 0; j < 4; j++) acc[mt][nf][j] = 0.0f;

    // ldmatrix lane addressing
    const int aRow = warp_m * 64 + ((lane >> 3) & 1) * 8 + (lane & 7);
    const uint32_t aK = (uint32_t)(lane >> 4) * 16;
    const int bRow = warp_n * 32 + (lane >> 4) * 8 + (lane & 7);
    const uint32_t bK = (uint32_t)((lane >> 3) & 1) * 16;

#pragma unroll 1
    for (int ch = 0; ch < NCHUNK; ch++) {
        if (ch < NCHUNK - 1) cp_wait<1>(); else cp_wait<0>();
        __syncthreads();
        if (ch + 2 < NCHUNK) load_stage((ch + 2) % 3, ch + 2);

        const uint32_t sa = sBase + (ch % 3) * STAGE_BYTES;
        const uint32_t sb = sa + 32768;
#pragma unroll
        for (int ks = 0; ks < 4; ks++) {
            uint32_t a[4][4], b[2][4];
#pragma unroll
            for (int mt = 0; mt < 4; mt++)
                ldm_x4(a[mt], sa + swz((uint32_t)(aRow + mt * 16) * 128 + ks * 32 + aK));
#pragma unroll
            for (int pr = 0; pr < 2; pr++)
                ldm_x4(b[pr], sb + swz((uint32_t)(bRow + pr * 16) * 128 + ks * 32 + bK));
#pragma unroll
            for (int mt = 0; mt < 4; mt++)
#pragma unroll
                for (int nf = 0; nf < 4; nf++)
                    mma16816(acc[mt][nf], a[mt],
                             b[nf >> 1][(nf & 1) * 2], b[nf >> 1][(nf & 1) * 2 + 1]);
        }
    }

    // ---------------- epilogue ----------------
    // c-frag: c0:(m=l/4, n=2(l%4))  c1:n+1  c2:(m+8)  c3:(m+8,n+1)
    const int r0 = rowBase + warp_m * 64 + (lane >> 2);
    const int c0 = colBase + warp_n * 32 + (lane & 3) * 2;

    if (EPI == TEPI_DOT) {
        float dsum[4][2];
#pragma unroll
        for (int mt = 0; mt < 4; mt++) { dsum[mt][0] = 0.f; dsum[mt][1] = 0.f; }
#pragma unroll
        for (int mt = 0; mt < 4; mt++)
#pragma unroll
            for (int nf = 0; nf < 4; nf++) {
                const int gc = c0 + nf * 8;
                const float b0v = bias[gc], b1v = bias[gc + 1];
                const float w0v = extra[gc], w1v = extra[gc + 1];
                dsum[mt][0] += fmaxf(acc[mt][nf][0] + b0v, 0.f) * w0v
                             + fmaxf(acc[mt][nf][1] + b1v, 0.f) * w1v;
                dsum[mt][1] += fmaxf(acc[mt][nf][2] + b0v, 0.f) * w0v
                             + fmaxf(acc[mt][nf][3] + b1v, 0.f) * w1v;
            }
#pragma unroll
        for (int mt = 0; mt < 4; mt++)
#pragma unroll
            for (int h = 0; h < 2; h++) {
                float v = dsum[mt][h];
                v += __shfl_xor_sync(0xffffffffu, v, 1);
                v += __shfl_xor_sync(0xffffffffu, v, 2);
                if ((lane & 3) == 0)
                    atomicAdd(dotOut + r0 + mt * 16 + h * 8, v);
            }
    } else if (EPI == TEPI_BIAS) {
#pragma unroll
        for (int mt = 0; mt < 4; mt++)
#pragma unroll
            for (int h = 0; h < 2; h++) {
                const int row = r0 + mt * 16 + h * 8;
                float2* orow = reinterpret_cast<float2*>(Cf + (size_t)row * ldC);
#pragma unroll
                for (int nf = 0; nf < 4; nf++) {
                    const int gc = c0 + nf * 8;
                    orow[gc >> 1] = make_float2(acc[mt][nf][h * 2] + bias[gc],
                                                acc[mt][nf][h * 2 + 1] + bias[gc + 1]);
                }
            }
    } else {
#pragma unroll
        for (int mt = 0; mt < 4; mt++)
#pragma unroll
            for (int h = 0; h < 2; h++) {
                const int row = r0 + mt * 16 + h * 8;
                float s = 1.0f;
                const float* hnrow = nullptr;
                if (EPI == TEPI_MFUSE)
                    hnrow = extra + (size_t)(((row >> 12) << 6) | (row & 63)) * 512;
                if (PERM) s = sigmoidf_(pa[permrow(row)]);
                uint32_t* oh = reinterpret_cast<uint32_t*>(Ch) + ((size_t)row * 512 >> 1);
                uint32_t* ol = reinterpret_cast<uint32_t*>(Cl) + ((size_t)row * 512 >> 1);
#pragma unroll
                for (int nf = 0; nf < 4; nf++) {
                    const int gc = c0 + nf * 8;
                    const float x0 = acc[mt][nf][h * 2 + 0];
                    const float x1 = acc[mt][nf][h * 2 + 1];
                    float y0, y1;
                    if (EPI == TEPI_MFUSE) {
                        y0 = fmaxf(x0 + hnrow[gc],     0.0f);
                        y1 = fmaxf(x1 + hnrow[gc + 1], 0.0f);
                    } else {
                        y0 = fmaxf(fmaf(s, x0, bias[gc]),     0.0f);
                        y1 = fmaxf(fmaf(s, x1, bias[gc + 1]), 0.0f);
                    }
                    __half2 h2;
                    h2.x = __float2half_rn(y0);
                    h2.y = __float2half_rn(y1);
                    oh[gc >> 1] = *reinterpret_cast<uint32_t*>(&h2);
                    if (WLO) {
                        __half2 l2;
                        l2.x = __float2half_rn(y0 - __half2float(h2.x));
                        l2.y = __float2half_rn(y1 - __half2float(h2.y));
                        ol[gc >> 1] = *reinterpret_cast<uint32_t*>(&l2);
                    }
                }
            }
    }
}

// ---------------------------------------------------------------------------
// conversions
// ---------------------------------------------------------------------------
__global__ void split_f32(const float4* __restrict__ in,
                          uint2* __restrict__ hi, uint2* __restrict__ lo, int n4)
{
    const int i = blockIdx.x * blockDim.x + threadIdx.x;
    if (i >= n4) return;
    const float4 v = in[i];
    __half2 hA, hB, lA, lB;
    hA.x = __float2half_rn(v.x); hA.y = __float2half_rn(v.y);
    hB.x = __float2half_rn(v.z); hB.y = __float2half_rn(v.w);
    lA.x = __float2half_rn(v.x - __half2float(hA.x));
    lA.y = __float2half_rn(v.y - __half2float(hA.y));
    lB.x = __float2half_rn(v.z - __half2float(hB.x));
    lB.y = __float2half_rn(v.w - __half2float(hB.y));
    hi[i] = make_uint2(*reinterpret_cast<uint32_t*>(&hA), *reinterpret_cast<uint32_t*>(&hB));
    lo[i] = make_uint2(*reinterpret_cast<uint32_t*>(&lA), *reinterpret_cast<uint32_t*>(&lB));
}

// plain fp32 -> fp16 cast (hi plane only), vectorized
__global__ void conv_act(const float4* __restrict__ in,
                         uint2* __restrict__ hi, int n4)
{
    const int i = blockIdx.x * blockDim.x + threadIdx.x;
    if (i >= n4) return;
    const float4 v = in[i];
    __half2 hA, hB;
    hA.x = __float2half_rn(v.x); hA.y = __float2half_rn(v.y);
    hB.x = __float2half_rn(v.z); hB.y = __float2half_rn(v.w);
    hi[i] = make_uint2(*reinterpret_cast<uint32_t*>(&hA), *reinterpret_cast<uint32_t*>(&hB));
}

__global__ void conv_w_h(const float* __restrict__ W, int ldW, int koff,
                         __half* __restrict__ hi)
{
    const int idx = blockIdx.x * blockDim.x + threadIdx.x;
    const int row = idx >> 9, k = idx & 511;
    hi[idx] = __float2half_rn(W[(size_t)row * ldW + koff + k]);
}

__global__ void conv_w_hl(const float* __restrict__ W, int ldW, int koff,
                          __half* __restrict__ hi, __half* __restrict__ lo)
{
    const int idx = blockIdx.x * blockDim.x + threadIdx.x;
    const int row = idx >> 9, k = idx & 511;
    const float x = W[(size_t)row * ldW + koff + k];
    const __half h = __float2half_rn(x);
    hi[idx] = h;
    lo[idx] = __float2half_rn(x - __half2float(h));
}

__global__ void init_pa(float* __restrict__ pa1, float* __restrict__ pa2,
                        const float* __restrict__ blo)
{
    const int i = blockIdx.x * blockDim.x + threadIdx.x;
    if (i < Rr) {
        const float v = blo[0];
        pa1[i] = v;
        pa2[i] = v;
    }
}

// msum[b,v,:] = sum_w sig(pa2[b,v,w]) * (Mh+Ml)[(b,v,w), :]  -> fp16 hi/lo
__global__ void msum2(const __half* __restrict__ Mh,
                      const __half* __restrict__ Ml,
                      const float* __restrict__ pa2,
                      __half* __restrict__ msh, __half* __restrict__ msl)
{
    const int bv = blockIdx.x;          // 0..1023
    const int t  = threadIdx.x;         // 128
    __shared__ float sg[64];
    if (t < 64) sg[t] = sigmoidf_(pa2[bv * 64 + t]);
    __syncthreads();
    const uint32_t* mh = reinterpret_cast<const uint32_t*>(Mh + (size_t)bv * 64 * 512);
    const uint32_t* ml = reinterpret_cast<const uint32_t*>(Ml + (size_t)bv * 64 * 512);
    const int c = t * 2;                // half2 index (cols 4t..4t+3)
    float a0 = 0.f, a1 = 0.f, a2 = 0.f, a3 = 0.f;
#pragma unroll 4
    for (int w = 0; w < 64; w++) {
        const float s = sg[w];
        const uint32_t h0 = mh[w * 256 + c],     l0 = ml[w * 256 + c];
        const uint32_t h1 = mh[w * 256 + c + 1], l1 = ml[w * 256 + c + 1];
        const __half2 H0 = *reinterpret_cast<const __half2*>(&h0);
        const __half2 L0 = *reinterpret_cast<const __half2*>(&l0);
        const __half2 H1 = *reinterpret_cast<const __half2*>(&h1);
        const __half2 L1 = *reinterpret_cast<const __half2*>(&l1);
        a0 = fmaf(s, __half2float(H0.x) + __half2float(L0.x), a0);
        a1 = fmaf(s, __half2float(H0.y) + __half2float(L0.y), a1);
        a2 = fmaf(s, __half2float(H1.x) + __half2float(L1.x), a2);
        a3 = fmaf(s, __half2float(H1.y) + __half2float(L1.y), a3);
    }
    __half2 h2a, h2b, l2a, l2b;
    h2a.x = __float2half_rn(a0); h2a.y = __float2half_rn(a1);
    h2b.x = __float2half_rn(a2); h2b.y = __float2half_rn(a3);
    l2a.x = __float2half_rn(a0 - __half2float(h2a.x));
    l2a.y = __float2half_rn(a1 - __half2float(h2a.y));
    l2b.x = __float2half_rn(a2 - __half2float(h2b.x));
    l2b.y = __float2half_rn(a3 - __half2float(h2b.y));
    uint2* oh = reinterpret_cast<uint2*>(msh + (size_t)bv * 512) + t;
    uint2* ol = reinterpret_cast<uint2*>(msl + (size_t)bv * 512) + t;
    *oh = make_uint2(*reinterpret_cast<uint32_t*>(&h2a), *reinterpret_cast<uint32_t*>(&h2b));
    *ol = make_uint2(*reinterpret_cast<uint32_t*>(&l2a), *reinterpret_cast<uint32_t*>(&l2b));
}

__global__ void gru_readout(const float* __restrict__ GI,
                            const float* __restrict__ GH,
                            const float* __restrict__ NF,
                            const float* __restrict__ Wr1, const float* __restrict__ br1,
                            const float* __restrict__ Wr2, const float* __restrict__ br2,
                            float* __restrict__ out)
{
    const int row = blockIdx.x;         // 0..1023
    __shared__ float hn[512];
    const int t = threadIdx.x;          // 256
    const float* gi = GI + (size_t)row * 1536;
    const float* gh = GH + (size_t)row * 1536;
    const float* h  = NF + (size_t)row * 512;
    for (int d = t; d < 512; d += 256) {
        const float r = sigmoidf_(gi[d] + gh[d]);
        const float z = sigmoidf_(gi[512 + d] + gh[512 + d]);
        const float n = tanhf(gi[1024 + d] + r * gh[1024 + d]);
        hn[d] = (1.0f - z) * n + z * h[d];
    }
    __syncthreads();
    const int warp = t >> 5, lane = t & 31;
    for (int o = warp; o < 28; o += 8) {
        const float* Wr = (o < 26) ? (Wr1 + o * 512) : (Wr2 + (o - 26) * 512);
        float acc = 0.0f;
        for (int k = lane; k < 512; k += 32) acc = fmaf(hn[k], Wr[k], acc);
#pragma unroll
        for (int off = 16; off; off >>= 1)
            acc += __shfl_down_sync(0xffffffffu, acc, off);
        if (lane == 0) {
            if (o < 26) out[65536 + row * 26 + o]               = acc + br1[o];
            else        out[65536 + 26624 + row * 2 + (o - 26)] = acc + br2[o - 26];
        }
    }
}

} // namespace

extern "C" void kernel_launch(void* const* d_in, const int* /*in_sizes*/, int /*n_in*/,
                              void* d_out, int /*out_size*/)
{
    const float* EF  = (const float*)d_in[0];
    const float* NF  = (const float*)d_in[1];
    const float* Wm  = (const float*)d_in[4];
    const float* bm  = (const float*)d_in[5];
    const float* Wl1 = (const float*)d_in[6];
    const float* bl1 = (const float*)d_in[7];
    const float* Wl2 = (const float*)d_in[8];
    const float* bl2 = (const float*)d_in[9];
    const float* Wlo = (const float*)d_in[10];
    const float* blo = (const float*)d_in[11];
    const float* Wih = (const float*)d_in[12];
    const float* bih = (const float*)d_in[13];
    const float* Whh = (const float*)d_in[14];
    const float* bhh = (const float*)d_in[15];
    const float* Wr1 = (const float*)d_in[16];
    const float* br1 = (const float*)d_in[17];
    const float* Wr2 = (const float*)d_in[18];
    const float* br2 = (const float*)d_in[19];
    float* out = (float*)d_out;

    __half *pEFh, *pMh, *pMl, *pTh;
    __half *pWmh, *pWmNh, *pWmNl, *pW1h, *pW2h;
    __half *pWihh, *pWihl, *pWhhh, *pWhhl, *pNFh, *pNFl, *pmsh, *pmsl;
    float *pHn, *pPa1, *pGI, *pGH;
    cudaGetSymbolAddress((void**)&pEFh,  g_EFh);
    cudaGetSymbolAddress((void**)&pMh,   g_Mh);
    cudaGetSymbolAddress((void**)&pMl,   g_Ml);
    cudaGetSymbolAddress((void**)&pTh,   g_Th);
    cudaGetSymbolAddress((void**)&pWmh,  g_Wmh);
    cudaGetSymbolAddress((void**)&pWmNh, g_WmNh);
    cudaGetSymbolAddress((void**)&pWmNl, g_WmNl);
    cudaGetSymbolAddress((void**)&pW1h,  g_W1h);
    cudaGetSymbolAddress((void**)&pW2h,  g_W2h);
    cudaGetSymbolAddress((void**)&pWihh, g_Wihh);
    cudaGetSymbolAddress((void**)&pWihl, g_Wihl);
    cudaGetSymbolAddress((void**)&pWhhh, g_Whhh);
    cudaGetSymbolAddress((void**)&pWhhl, g_Whhl);
    cudaGetSymbolAddress((void**)&pNFh,  g_NFh);
    cudaGetSymbolAddress((void**)&pNFl,  g_NFl);
    cudaGetSymbolAddress((void**)&pmsh,  g_msh);
    cudaGetSymbolAddress((void**)&pmsl,  g_msl);
    cudaGetSymbolAddress((void**)&pHn,   g_Hn);
    cudaGetSymbolAddress((void**)&pPa1,  g_pa1);
    cudaGetSymbolAddress((void**)&pGI,   g_GI);
    cudaGetSymbolAddress((void**)&pGH,   g_GH);

    // kernel variants
    auto kBIAS = hmma_gemm<TEPI_BIAS,  false, 3, false>;
    auto kMF   = hmma_gemm<TEPI_MFUSE, false, 1, true>;   // single-plane compute, hi/lo store
    auto kRE   = hmma_gemm<TEPI_RELU,  false, 1, false>;  // single-plane
    auto kRP   = hmma_gemm<TEPI_RELU,  true,  2, false>;  // 2-plane (Mh+Ml)
    auto kDOT  = hmma_gemm<TEPI_DOT,   false, 1, false>;
    cudaFuncSetAttribute(kBIAS, cudaFuncAttributeMaxDynamicSharedMemorySize, SMEM_BYTES);
    cudaFuncSetAttribute(kMF,   cudaFuncAttributeMaxDynamicSharedMemorySize, SMEM_BYTES);
    cudaFuncSetAttribute(kRE,   cudaFuncAttributeMaxDynamicSharedMemorySize, SMEM_BYTES);
    cudaFuncSetAttribute(kRP,   cudaFuncAttributeMaxDynamicSharedMemorySize, SMEM_BYTES);
    cudaFuncSetAttribute(kDOT,  cudaFuncAttributeMaxDynamicSharedMemorySize, SMEM_BYTES);

    const int n4ef = Rr * Cc / 4;
    const int n4nf = Bb * Nn * Cc / 4;
    conv_act<<<(n4ef + 255) / 256, 256>>>((const float4*)EF, (uint2*)pEFh, n4ef);
    split_f32<<<(n4nf + 255) / 256, 256>>>((const float4*)NF, (uint2*)pNFh, (uint2*)pNFl, n4nf);
    conv_w_h <<<1024, 256>>>(Wm, 1024, 512, pWmh);            // edge half, hi
    conv_w_hl<<<1024, 256>>>(Wm, 1024, 0, pWmNh, pWmNl);      // node half, hi/lo
    conv_w_h <<<1024, 256>>>(Wl1, 512, 0, pW1h);
    conv_w_h <<<1024, 256>>>(Wl2, 512, 0, pW2h);
    conv_w_hl<<<3072, 256>>>(Wih, 512, 0, pWihh, pWihl);
    conv_w_hl<<<3072, 256>>>(Whh, 512, 0, pWhhh, pWhhl);
    init_pa<<<(Rr + 255) / 256, 256>>>(pPa1, out, blo);

    // Hn = NF @ Wm[:, :512]^T + bm   (3-plane, fp32 out)
    kBIAS<<<dim3(4, 4), 512, SMEM_BYTES>>>(pNFh, pNFl, pWmNh, pWmNl, bm,
                                           nullptr, nullptr, nullptr, nullptr,
                                           pHn, 512, nullptr);

    const dim3 gTC(4, 256);   // 256-row x 128-col tiles, 65536 rows
    // M = relu(EF @ WmE^T + Hn)  -> Mh/Ml   (single plane compute)
    kMF<<<gTC, 512, SMEM_BYTES>>>(pEFh, nullptr, pWmh, nullptr, nullptr, pHn,
                                  nullptr, pMh, pMl, nullptr, 0, nullptr);
    // T1 = relu(EF @ Wl1^T + bl1) -> Th (hi only, single plane)
    kRE<<<gTC, 512, SMEM_BYTES>>>(pEFh, nullptr, pW1h, nullptr, bl1, nullptr,
                                  nullptr, pTh, nullptr, nullptr, 0, nullptr);
    // pa1 += dot(relu(T1 @ Wl2^T + bl2), Wlo)   (single plane, K=512)
    kDOT<<<gTC, 512, SMEM_BYTES>>>(pTh, nullptr, pW2h, nullptr, bl2, Wlo,
                                   nullptr, nullptr, nullptr, nullptr, 0, pPa1);
    // T1' = relu(sig(pa1[perm]) * M[perm] @ Wl1^T + bl1) -> Th   (2-plane)
    kRP<<<gTC, 512, SMEM_BYTES>>>(pMh, pMl, pW1h, nullptr, bl1, nullptr,
                                  pPa1, pTh, nullptr, nullptr, 0, nullptr);
    // pred_adj += dot(relu(T1' @ Wl2^T + bl2), Wlo)
    kDOT<<<gTC, 512, SMEM_BYTES>>>(pTh, nullptr, pW2h, nullptr, bl2, Wlo,
                                   nullptr, nullptr, nullptr, nullptr, 0, out);

    msum2<<<Bb * Nn, 128>>>(pMh, pMl, out, pmsh, pmsl);
    // GI = msum @ W_ih^T + b_ih   (3-plane)
    kBIAS<<<dim3(12, 4), 512, SMEM_BYTES>>>(pmsh, pmsl, pWihh, pWihl, bih,
                                            nullptr, nullptr, nullptr, nullptr,
                                            pGI, 1536, nullptr);
    // GH = NF @ W_hh^T + b_hh     (3-plane)
    kBIAS<<<dim3(12, 4), 512, SMEM_BYTES>>>(pNFh, pNFl, pWhhh, pWhhl, bhh,
                                            nullptr, nullptr, nullptr, nullptr,
                                            pGH, 1536, nullptr);
    gru_readout<<<Bb * Nn, 256>>>(pGI, pGH, NF, Wr1, br1, Wr2, br2, out);
}

// round 8
// speedup vs baseline: 5.9306x; 1.1583x over previous
#include <cuda_runtime.h>
#include <cuda_fp16.h>
#include <math.h>
#include <stdint.h>

// ---------------------------------------------------------------------------
// GPNN_VCOCO forward — fp16 split GEMMs on warp-level mma.sync.
// R8: all five big GEMMs single-plane (M lo plane eliminated end-to-end);
// msum accumulates fp32 and re-splits; GRU/Hn GEMMs 3-plane near-fp32;
// weight conversions merged into one launch.
// ---------------------------------------------------------------------------

namespace {

constexpr int Bb = 16;
constexpr int Nn = 64;
constexpr int Cc = 512;
constexpr int Rr = Bb * Nn * Nn;   // 65536

// ---------------- scratch (static device globals) ----------------
__device__ __half g_EFh[Rr * Cc];
__device__ __half g_Mh [Rr * Cc];
__device__ __half g_Th [Rr * Cc];
__device__ __half g_Wmh [Cc * Cc];                 // Wm edge half, hi
__device__ __half g_WmNh[Cc * Cc], g_WmNl[Cc * Cc];// Wm node half, hi/lo
__device__ __half g_W1h [Cc * Cc];
__device__ __half g_W2h [Cc * Cc];
__device__ __half g_Wihh[3 * Cc * Cc], g_Wihl[3 * Cc * Cc];
__device__ __half g_Whhh[3 * Cc * Cc], g_Whhl[3 * Cc * Cc];
__device__ __half g_NFh [Bb * Nn * Cc], g_NFl[Bb * Nn * Cc];
__device__ __half g_msh [Bb * Nn * Cc], g_msl[Bb * Nn * Cc];
__device__ float g_Hn [Bb * Nn * Cc];
__device__ float g_pa1[Rr];
__device__ float g_GI [Bb * Nn * 3 * Cc];
__device__ float g_GH [Bb * Nn * 3 * Cc];

__device__ __forceinline__ float sigmoidf_(float x) {
    return 1.0f / (1.0f + __expf(-x));
}
__device__ __forceinline__ int permrow(int gr) {
    return (gr & ~4095) | ((gr & 63) << 6) | ((gr >> 6) & 63);
}
__device__ __forceinline__ uint32_t smem_u32(const void* p) {
    uint32_t a;
    asm("{ .reg .u64 t; cvta.to.shared.u64 t, %1; cvt.u32.u64 %0, t; }"
        : "=r"(a) : "l"(p));
    return a;
}
__device__ __forceinline__ uint32_t swz(uint32_t o) {   // 128B-row xor swizzle
    return o ^ ((o >> 3) & 0x70);
}
__device__ __forceinline__ void cp16(uint32_t saddr, const void* g) {
    asm volatile("cp.async.cg.shared.global [%0], [%1], 16;"
                 :: "r"(saddr), "l"(g) : "memory");
}
__device__ __forceinline__ void cp_commit() {
    asm volatile("cp.async.commit_group;" ::: "memory");
}
template<int N>
__device__ __forceinline__ void cp_wait() {
    asm volatile("cp.async.wait_group %0;" :: "n"(N) : "memory");
}
__device__ __forceinline__ void ldm_x4(uint32_t* r, uint32_t addr) {
    asm volatile("ldmatrix.sync.aligned.m8n8.x4.shared.b16 {%0,%1,%2,%3}, [%4];"
                 : "=r"(r[0]), "=r"(r[1]), "=r"(r[2]), "=r"(r[3]) : "r"(addr));
}
__device__ __forceinline__ void mma16816(float* c, const uint32_t* a,
                                         uint32_t b0, uint32_t b1) {
    asm volatile(
        "mma.sync.aligned.m16n8k16.row.col.f32.f16.f16.f32 "
        "{%0,%1,%2,%3}, {%4,%5,%6,%7}, {%8,%9}, {%0,%1,%2,%3};"
        : "+f"(c[0]), "+f"(c[1]), "+f"(c[2]), "+f"(c[3])
        : "r"(a[0]), "r"(a[1]), "r"(a[2]), "r"(a[3]), "r"(b0), "r"(b1));
}

enum { TEPI_MFUSE = 0, TEPI_RELU = 1, TEPI_DOT = 2, TEPI_BIAS = 3 };

constexpr int STAGE_BYTES = 49152;           // 32KB A (256x64 fp16) + 16KB B
constexpr int SMEM_BYTES  = 3 * STAGE_BYTES; // 144KB

// ---------------------------------------------------------------------------
// HMMA GEMM: out[r,n] = epi( sum_{k<512} A[r,k]*W[n,k] ).
// PLANES: 1 = Ah*Bh; 2 = +Al*Bh; 3 = +Ah*Bl (near-fp32).
// CTA 256x128, 512 thr = 16 warps (4m x 4n), warp tile 64x32, K-chunk 64,
// 3-stage cp.async pipeline (one __syncthreads per chunk).
// ---------------------------------------------------------------------------
template<int EPI, bool PERM, int PLANES, bool WLO>
__global__ void __launch_bounds__(512, 1)
hmma_gemm(const __half* __restrict__ Ah, const __half* __restrict__ Al,
          const __half* __restrict__ Bh, const __half* __restrict__ Bl,
          const float* __restrict__ bias,   // bl1/bl2/bm/bih/bhh
          const float* __restrict__ extra,  // Hn (MFUSE) | Wlo (DOT)
          const float* __restrict__ pa,     // pa1 logits (PERM)
          __half* __restrict__ Ch, __half* __restrict__ Cl,
          float* __restrict__ Cf, int ldC,  // fp32 out (BIAS)
          float* __restrict__ dotOut)
{
    extern __shared__ __align__(128) uint8_t smem[];
    const uint32_t sBase = smem_u32(smem);
    constexpr int NCHUNK = PLANES * 8;

    const int tid = threadIdx.x;
    const int wid = tid >> 5, lane = tid & 31;
    const int warp_m = wid & 3, warp_n = wid >> 2;
    const int rowBase = blockIdx.y << 8;    // 256-row blocks
    const int colBase = blockIdx.x << 7;    // 128-col blocks

    // ---- loader: A = 4 sweeps of 64 rows, B = 2 sweeps (16B per cp)
    const int lrow = tid >> 3, lseg = tid & 7;
    uint32_t aOff[4], sAOff[4], bOff[2], sBOff[2];
#pragma unroll
    for (int i = 0; i < 4; i++) {
        const int row = lrow + i * 64;
        int sr = rowBase + row;
        if (PERM) sr = permrow(sr);
        aOff[i]  = (uint32_t)sr * 512u + lseg * 8;
        sAOff[i] = swz((uint32_t)row * 128 + lseg * 16);
    }
#pragma unroll
    for (int i = 0; i < 2; i++) {
        const int row = lrow + i * 64;
        bOff[i]  = (uint32_t)(colBase + row) * 512u + lseg * 8;
        sBOff[i] = swz((uint32_t)row * 128 + lseg * 16);
    }

    auto load_stage = [&](int st, int ch) {
        const int p  = ch >> 3;
        const int kb = (ch & 7) * 64;
        const __half* Ap = (p == 1) ? Al : Ah;
        const __half* Bp = (p == 2) ? Bl : Bh;
        const uint32_t sa = sBase + st * STAGE_BYTES;
        const uint32_t sb = sa + 32768;
#pragma unroll
        for (int i = 0; i < 4; i++) cp16(sa + sAOff[i], Ap + aOff[i] + kb);
#pragma unroll
        for (int i = 0; i < 2; i++) cp16(sb + sBOff[i], Bp + bOff[i] + kb);
        cp_commit();
    };

    load_stage(0, 0);
    load_stage(1, 1);

    float acc[4][4][4];
#pragma unroll
    for (int mt = 0; mt < 4; mt++)
#pragma unroll
        for (int nf = 0; nf < 4; nf++)
#pragma unroll
            for (int j = 0; j < 4; j++) acc[mt][nf][j] = 0.0f;

    // ldmatrix lane addressing
    const int aRow = warp_m * 64 + ((lane >> 3) & 1) * 8 + (lane & 7);
    const uint32_t aK = (uint32_t)(lane >> 4) * 16;
    const int bRow = warp_n * 32 + (lane >> 4) * 8 + (lane & 7);
    const uint32_t bK = (uint32_t)((lane >> 3) & 1) * 16;

#pragma unroll 1
    for (int ch = 0; ch < NCHUNK; ch++) {
        if (ch < NCHUNK - 1) cp_wait<1>(); else cp_wait<0>();
        __syncthreads();
        if (ch + 2 < NCHUNK) load_stage((ch + 2) % 3, ch + 2);

        const uint32_t sa = sBase + (ch % 3) * STAGE_BYTES;
        const uint32_t sb = sa + 32768;
#pragma unroll
        for (int ks = 0; ks < 4; ks++) {
            uint32_t a[4][4], b[2][4];
#pragma unroll
            for (int mt = 0; mt < 4; mt++)
                ldm_x4(a[mt], sa + swz((uint32_t)(aRow + mt * 16) * 128 + ks * 32 + aK));
#pragma unroll
            for (int pr = 0; pr < 2; pr++)
                ldm_x4(b[pr], sb + swz((uint32_t)(bRow + pr * 16) * 128 + ks * 32 + bK));
#pragma unroll
            for (int mt = 0; mt < 4; mt++)
#pragma unroll
                for (int nf = 0; nf < 4; nf++)
                    mma16816(acc[mt][nf], a[mt],
                             b[nf >> 1][(nf & 1) * 2], b[nf >> 1][(nf & 1) * 2 + 1]);
        }
    }

    // ---------------- epilogue ----------------
    // c-frag: c0:(m=l/4, n=2(l%4))  c1:n+1  c2:(m+8)  c3:(m+8,n+1)
    const int r0 = rowBase + warp_m * 64 + (lane >> 2);
    const int c0 = colBase + warp_n * 32 + (lane & 3) * 2;

    if (EPI == TEPI_DOT) {
        float dsum[4][2];
#pragma unroll
        for (int mt = 0; mt < 4; mt++) { dsum[mt][0] = 0.f; dsum[mt][1] = 0.f; }
#pragma unroll
        for (int mt = 0; mt < 4; mt++)
#pragma unroll
            for (int nf = 0; nf < 4; nf++) {
                const int gc = c0 + nf * 8;
                const float b0v = bias[gc], b1v = bias[gc + 1];
                const float w0v = extra[gc], w1v = extra[gc + 1];
                dsum[mt][0] += fmaxf(acc[mt][nf][0] + b0v, 0.f) * w0v
                             + fmaxf(acc[mt][nf][1] + b1v, 0.f) * w1v;
                dsum[mt][1] += fmaxf(acc[mt][nf][2] + b0v, 0.f) * w0v
                             + fmaxf(acc[mt][nf][3] + b1v, 0.f) * w1v;
            }
#pragma unroll
        for (int mt = 0; mt < 4; mt++)
#pragma unroll
            for (int h = 0; h < 2; h++) {
                float v = dsum[mt][h];
                v += __shfl_xor_sync(0xffffffffu, v, 1);
                v += __shfl_xor_sync(0xffffffffu, v, 2);
                if ((lane & 3) == 0)
                    atomicAdd(dotOut + r0 + mt * 16 + h * 8, v);
            }
    } else if (EPI == TEPI_BIAS) {
#pragma unroll
        for (int mt = 0; mt < 4; mt++)
#pragma unroll
            for (int h = 0; h < 2; h++) {
                const int row = r0 + mt * 16 + h * 8;
                float2* orow = reinterpret_cast<float2*>(Cf + (size_t)row * ldC);
#pragma unroll
                for (int nf = 0; nf < 4; nf++) {
                    const int gc = c0 + nf * 8;
                    orow[gc >> 1] = make_float2(acc[mt][nf][h * 2] + bias[gc],
                                                acc[mt][nf][h * 2 + 1] + bias[gc + 1]);
                }
            }
    } else {
#pragma unroll
        for (int mt = 0; mt < 4; mt++)
#pragma unroll
            for (int h = 0; h < 2; h++) {
                const int row = r0 + mt * 16 + h * 8;
                float s = 1.0f;
                const float* hnrow = nullptr;
                if (EPI == TEPI_MFUSE)
                    hnrow = extra + (size_t)(((row >> 12) << 6) | (row & 63)) * 512;
                if (PERM) s = sigmoidf_(pa[permrow(row)]);
                uint32_t* oh = reinterpret_cast<uint32_t*>(Ch) + ((size_t)row * 512 >> 1);
                uint32_t* ol = reinterpret_cast<uint32_t*>(Cl) + ((size_t)row * 512 >> 1);
#pragma unroll
                for (int nf = 0; nf < 4; nf++) {
                    const int gc = c0 + nf * 8;
                    const float x0 = acc[mt][nf][h * 2 + 0];
                    const float x1 = acc[mt][nf][h * 2 + 1];
                    float y0, y1;
                    if (EPI == TEPI_MFUSE) {
                        y0 = fmaxf(x0 + hnrow[gc],     0.0f);
                        y1 = fmaxf(x1 + hnrow[gc + 1], 0.0f);
                    } else {
                        y0 = fmaxf(fmaf(s, x0, bias[gc]),     0.0f);
                        y1 = fmaxf(fmaf(s, x1, bias[gc + 1]), 0.0f);
                    }
                    __half2 h2;
                    h2.x = __float2half_rn(y0);
                    h2.y = __float2half_rn(y1);
                    oh[gc >> 1] = *reinterpret_cast<uint32_t*>(&h2);
                    if (WLO) {
                        __half2 l2;
                        l2.x = __float2half_rn(y0 - __half2float(h2.x));
                        l2.y = __float2half_rn(y1 - __half2float(h2.y));
                        ol[gc >> 1] = *reinterpret_cast<uint32_t*>(&l2);
                    }
                }
            }
    }
}

// ---------------------------------------------------------------------------
// conversions
// ---------------------------------------------------------------------------
__global__ void split_f32(const float4* __restrict__ in,
                          uint2* __restrict__ hi, uint2* __restrict__ lo, int n4)
{
    const int i = blockIdx.x * blockDim.x + threadIdx.x;
    if (i >= n4) return;
    const float4 v = in[i];
    __half2 hA, hB, lA, lB;
    hA.x = __float2half_rn(v.x); hA.y = __float2half_rn(v.y);
    hB.x = __float2half_rn(v.z); hB.y = __float2half_rn(v.w);
    lA.x = __float2half_rn(v.x - __half2float(hA.x));
    lA.y = __float2half_rn(v.y - __half2float(hA.y));
    lB.x = __float2half_rn(v.z - __half2float(hB.x));
    lB.y = __float2half_rn(v.w - __half2float(hB.y));
    hi[i] = make_uint2(*reinterpret_cast<uint32_t*>(&hA), *reinterpret_cast<uint32_t*>(&hB));
    lo[i] = make_uint2(*reinterpret_cast<uint32_t*>(&lA), *reinterpret_cast<uint32_t*>(&lB));
}

// plain fp32 -> fp16 cast (hi plane only), vectorized
__global__ void conv_act(const float4* __restrict__ in,
                         uint2* __restrict__ hi, int n4)
{
    const int i = blockIdx.x * blockDim.x + threadIdx.x;
    if (i >= n4) return;
    const float4 v = in[i];
    __half2 hA, hB;
    hA.x = __float2half_rn(v.x); hA.y = __float2half_rn(v.y);
    hB.x = __float2half_rn(v.z); hB.y = __float2half_rn(v.w);
    hi[i] = make_uint2(*reinterpret_cast<uint32_t*>(&hA), *reinterpret_cast<uint32_t*>(&hB));
}

// All weight conversions in one launch. Segments by linear element index:
//   [0,256K)      Wm[:, 512:1024]  -> Wmh (hi)
//   [256K,512K)   Wm[:, 0:512]     -> WmNh/WmNl
//   [512K,768K)   Wl1              -> W1h (hi)
//   [768K,1M)     Wl2              -> W2h (hi)
//   [1M,1.75M)    Wih              -> Wihh/Wihl
//   [1.75M,2.5M)  Whh              -> Whhh/Whhl
__global__ void conv_weights(const float* __restrict__ Wm,
                             const float* __restrict__ Wl1,
                             const float* __restrict__ Wl2,
                             const float* __restrict__ Wih,
                             const float* __restrict__ Whh,
                             __half* __restrict__ Wmh,
                             __half* __restrict__ WmNh, __half* __restrict__ WmNl,
                             __half* __restrict__ W1h,  __half* __restrict__ W2h,
                             __half* __restrict__ Wihh, __half* __restrict__ Wihl,
                             __half* __restrict__ Whhh, __half* __restrict__ Whhl)
{
    const int idx = blockIdx.x * blockDim.x + threadIdx.x;   // < 2.5M
    constexpr int S = 512 * 512;   // 256K
    float x;
    __half* hi;
    __half* lo = nullptr;
    int off;
    if (idx < S) {                       // Wm edge hi
        off = idx;
        x = Wm[(size_t)(off >> 9) * 1024 + 512 + (off & 511)];
        hi = Wmh + off;
    } else if (idx < 2 * S) {            // Wm node hi/lo
        off = idx - S;
        x = Wm[(size_t)(off >> 9) * 1024 + (off & 511)];
        hi = WmNh + off; lo = WmNl + off;
    } else if (idx < 3 * S) {            // Wl1
        off = idx - 2 * S;
        x = Wl1[off];
        hi = W1h + off;
    } else if (idx < 4 * S) {            // Wl2
        off = idx - 3 * S;
        x = Wl2[off];
        hi = W2h + off;
    } else if (idx < 7 * S) {            // Wih
        off = idx - 4 * S;
        x = Wih[off];
        hi = Wihh + off; lo = Wihl + off;
    } else {                             // Whh
        off = idx - 7 * S;
        x = Whh[off];
        hi = Whhh + off; lo = Whhl + off;
    }
    const __half h = __float2half_rn(x);
    *hi = h;
    if (lo) *lo = __float2half_rn(x - __half2float(h));
}

__global__ void init_pa(float* __restrict__ pa1, float* __restrict__ pa2,
                        const float* __restrict__ blo)
{
    const int i = blockIdx.x * blockDim.x + threadIdx.x;
    if (i < Rr) {
        const float v = blo[0];
        pa1[i] = v;
        pa2[i] = v;
    }
}

// msum[b,v,:] = sum_w sig(pa2[b,v,w]) * Mh[(b,v,w), :]  -> fp16 hi/lo
__global__ void msum2(const __half* __restrict__ Mh,
                      const float* __restrict__ pa2,
                      __half* __restrict__ msh, __half* __restrict__ msl)
{
    const int bv = blockIdx.x;          // 0..1023
    const int t  = threadIdx.x;         // 128
    __shared__ float sg[64];
    if (t < 64) sg[t] = sigmoidf_(pa2[bv * 64 + t]);
    __syncthreads();
    const uint32_t* mh = reinterpret_cast<const uint32_t*>(Mh + (size_t)bv * 64 * 512);
    const int c = t * 2;                // half2 index (cols 4t..4t+3)
    float a0 = 0.f, a1 = 0.f, a2 = 0.f, a3 = 0.f;
#pragma unroll 4
    for (int w = 0; w < 64; w++) {
        const float s = sg[w];
        const uint32_t h0 = mh[w * 256 + c];
        const uint32_t h1 = mh[w * 256 + c + 1];
        const __half2 H0 = *reinterpret_cast<const __half2*>(&h0);
        const __half2 H1 = *reinterpret_cast<const __half2*>(&h1);
        a0 = fmaf(s, __half2float(H0.x), a0);
        a1 = fmaf(s, __half2float(H0.y), a1);
        a2 = fmaf(s, __half2float(H1.x), a2);
        a3 = fmaf(s, __half2float(H1.y), a3);
    }
    __half2 h2a, h2b, l2a, l2b;
    h2a.x = __float2half_rn(a0); h2a.y = __float2half_rn(a1);
    h2b.x = __float2half_rn(a2); h2b.y = __float2half_rn(a3);
    l2a.x = __float2half_rn(a0 - __half2float(h2a.x));
    l2a.y = __float2half_rn(a1 - __half2float(h2a.y));
    l2b.x = __float2half_rn(a2 - __half2float(h2b.x));
    l2b.y = __float2half_rn(a3 - __half2float(h2b.y));
    uint2* oh = reinterpret_cast<uint2*>(msh + (size_t)bv * 512) + t;
    uint2* ol = reinterpret_cast<uint2*>(msl + (size_t)bv * 512) + t;
    *oh = make_uint2(*reinterpret_cast<uint32_t*>(&h2a), *reinterpret_cast<uint32_t*>(&h2b));
    *ol = make_uint2(*reinterpret_cast<uint32_t*>(&l2a), *reinterpret_cast<uint32_t*>(&l2b));
}

__global__ void gru_readout(const float* __restrict__ GI,
                            const float* __restrict__ GH,
                            const float* __restrict__ NF,
                            const float* __restrict__ Wr1, const float* __restrict__ br1,
                            const float* __restrict__ Wr2, const float* __restrict__ br2,
                            float* __restrict__ out)
{
    const int row = blockIdx.x;         // 0..1023
    __shared__ float hn[512];
    const int t = threadIdx.x;          // 256
    const float* gi = GI + (size_t)row * 1536;
    const float* gh = GH + (size_t)row * 1536;
    const float* h  = NF + (size_t)row * 512;
    for (int d = t; d < 512; d += 256) {
        const float r = sigmoidf_(gi[d] + gh[d]);
        const float z = sigmoidf_(gi[512 + d] + gh[512 + d]);
        const float n = tanhf(gi[1024 + d] + r * gh[1024 + d]);
        hn[d] = (1.0f - z) * n + z * h[d];
    }
    __syncthreads();
    const int warp = t >> 5, lane = t & 31;
    for (int o = warp; o < 28; o += 8) {
        const float* Wr = (o < 26) ? (Wr1 + o * 512) : (Wr2 + (o - 26) * 512);
        float acc = 0.0f;
        for (int k = lane; k < 512; k += 32) acc = fmaf(hn[k], Wr[k], acc);
#pragma unroll
        for (int off = 16; off; off >>= 1)
            acc += __shfl_down_sync(0xffffffffu, acc, off);
        if (lane == 0) {
            if (o < 26) out[65536 + row * 26 + o]               = acc + br1[o];
            else        out[65536 + 26624 + row * 2 + (o - 26)] = acc + br2[o - 26];
        }
    }
}

} // namespace

extern "C" void kernel_launch(void* const* d_in, const int* /*in_sizes*/, int /*n_in*/,
                              void* d_out, int /*out_size*/)
{
    const float* EF  = (const float*)d_in[0];
    const float* NF  = (const float*)d_in[1];
    const float* Wm  = (const float*)d_in[4];
    const float* bm  = (const float*)d_in[5];
    const float* Wl1 = (const float*)d_in[6];
    const float* bl1 = (const float*)d_in[7];
    const float* Wl2 = (const float*)d_in[8];
    const float* bl2 = (const float*)d_in[9];
    const float* Wlo = (const float*)d_in[10];
    const float* blo = (const float*)d_in[11];
    const float* Wih = (const float*)d_in[12];
    const float* bih = (const float*)d_in[13];
    const float* Whh = (const float*)d_in[14];
    const float* bhh = (const float*)d_in[15];
    const float* Wr1 = (const float*)d_in[16];
    const float* br1 = (const float*)d_in[17];
    const float* Wr2 = (const float*)d_in[18];
    const float* br2 = (const float*)d_in[19];
    float* out = (float*)d_out;

    __half *pEFh, *pMh, *pTh;
    __half *pWmh, *pWmNh, *pWmNl, *pW1h, *pW2h;
    __half *pWihh, *pWihl, *pWhhh, *pWhhl, *pNFh, *pNFl, *pmsh, *pmsl;
    float *pHn, *pPa1, *pGI, *pGH;
    cudaGetSymbolAddress((void**)&pEFh,  g_EFh);
    cudaGetSymbolAddress((void**)&pMh,   g_Mh);
    cudaGetSymbolAddress((void**)&pTh,   g_Th);
    cudaGetSymbolAddress((void**)&pWmh,  g_Wmh);
    cudaGetSymbolAddress((void**)&pWmNh, g_WmNh);
    cudaGetSymbolAddress((void**)&pWmNl, g_WmNl);
    cudaGetSymbolAddress((void**)&pW1h,  g_W1h);
    cudaGetSymbolAddress((void**)&pW2h,  g_W2h);
    cudaGetSymbolAddress((void**)&pWihh, g_Wihh);
    cudaGetSymbolAddress((void**)&pWihl, g_Wihl);
    cudaGetSymbolAddress((void**)&pWhhh, g_Whhh);
    cudaGetSymbolAddress((void**)&pWhhl, g_Whhl);
    cudaGetSymbolAddress((void**)&pNFh,  g_NFh);
    cudaGetSymbolAddress((void**)&pNFl,  g_NFl);
    cudaGetSymbolAddress((void**)&pmsh,  g_msh);
    cudaGetSymbolAddress((void**)&pmsl,  g_msl);
    cudaGetSymbolAddress((void**)&pHn,   g_Hn);
    cudaGetSymbolAddress((void**)&pPa1,  g_pa1);
    cudaGetSymbolAddress((void**)&pGI,   g_GI);
    cudaGetSymbolAddress((void**)&pGH,   g_GH);

    // kernel variants
    auto kBIAS = hmma_gemm<TEPI_BIAS,  false, 3, false>;
    auto kMF   = hmma_gemm<TEPI_MFUSE, false, 1, false>;  // single-plane, hi store
    auto kRE   = hmma_gemm<TEPI_RELU,  false, 1, false>;  // single-plane
    auto kRP   = hmma_gemm<TEPI_RELU,  true,  1, false>;  // single-plane (Mh)
    auto kDOT  = hmma_gemm<TEPI_DOT,   false, 1, false>;
    cudaFuncSetAttribute(kBIAS, cudaFuncAttributeMaxDynamicSharedMemorySize, SMEM_BYTES);
    cudaFuncSetAttribute(kMF,   cudaFuncAttributeMaxDynamicSharedMemorySize, SMEM_BYTES);
    cudaFuncSetAttribute(kRE,   cudaFuncAttributeMaxDynamicSharedMemorySize, SMEM_BYTES);
    cudaFuncSetAttribute(kRP,   cudaFuncAttributeMaxDynamicSharedMemorySize, SMEM_BYTES);
    cudaFuncSetAttribute(kDOT,  cudaFuncAttributeMaxDynamicSharedMemorySize, SMEM_BYTES);

    const int n4ef = Rr * Cc / 4;
    const int n4nf = Bb * Nn * Cc / 4;
    conv_act<<<(n4ef + 255) / 256, 256>>>((const float4*)EF, (uint2*)pEFh, n4ef);
    split_f32<<<(n4nf + 255) / 256, 256>>>((const float4*)NF, (uint2*)pNFh, (uint2*)pNFl, n4nf);
    conv_weights<<<10240, 256>>>(Wm, Wl1, Wl2, Wih, Whh,
                                 pWmh, pWmNh, pWmNl, pW1h, pW2h,
                                 pWihh, pWihl, pWhhh, pWhhl);
    init_pa<<<(Rr + 255) / 256, 256>>>(pPa1, out, blo);

    // Hn = NF @ Wm[:, :512]^T + bm   (3-plane, fp32 out)
    kBIAS<<<dim3(4, 4), 512, SMEM_BYTES>>>(pNFh, pNFl, pWmNh, pWmNl, bm,
                                           nullptr, nullptr, nullptr, nullptr,
                                           pHn, 512, nullptr);

    const dim3 gTC(4, 256);   // 256-row x 128-col tiles, 65536 rows
    // M = relu(EF @ WmE^T + Hn)  -> Mh  (single plane)
    kMF<<<gTC, 512, SMEM_BYTES>>>(pEFh, nullptr, pWmh, nullptr, nullptr, pHn,
                                  nullptr, pMh, nullptr, nullptr, 0, nullptr);
    // T1 = relu(EF @ Wl1^T + bl1) -> Th (single plane)
    kRE<<<gTC, 512, SMEM_BYTES>>>(pEFh, nullptr, pW1h, nullptr, bl1, nullptr,
                                  nullptr, pTh, nullptr, nullptr, 0, nullptr);
    // pa1 += dot(relu(T1 @ Wl2^T + bl2), Wlo)
    kDOT<<<gTC, 512, SMEM_BYTES>>>(pTh, nullptr, pW2h, nullptr, bl2, Wlo,
                                   nullptr, nullptr, nullptr, nullptr, 0, pPa1);
    // T1' = relu(sig(pa1[perm]) * M[perm] @ Wl1^T + bl1) -> Th
    kRP<<<gTC, 512, SMEM_BYTES>>>(pMh, nullptr, pW1h, nullptr, bl1, nullptr,
                                  pPa1, pTh, nullptr, nullptr, 0, nullptr);
    // pred_adj += dot(relu(T1' @ Wl2^T + bl2), Wlo)
    kDOT<<<gTC, 512, SMEM_BYTES>>>(pTh, nullptr, pW2h, nullptr, bl2, Wlo,
                                   nullptr, nullptr, nullptr, nullptr, 0, out);

    msum2<<<Bb * Nn, 128>>>(pMh, out, pmsh, pmsl);
    // GI = msum @ W_ih^T + b_ih   (3-plane)
    kBIAS<<<dim3(12, 4), 512, SMEM_BYTES>>>(pmsh, pmsl, pWihh, pWihl, bih,
                                            nullptr, nullptr, nullptr, nullptr,
                                            pGI, 1536, nullptr);
    // GH = NF @ W_hh^T + b_hh     (3-plane)
    kBIAS<<<dim3(12, 4), 512, SMEM_BYTES>>>(pNFh, pNFl, pWhhh, pWhhl, bhh,
                                            nullptr, nullptr, nullptr, nullptr,
                                            pGH, 1536, nullptr);
    gru_readout<<<Bb * Nn, 256>>>(pGI, pGH, NF, Wr1, br1, Wr2, br2, out);
}

// round 9
// speedup vs baseline: 6.0342x; 1.0175x over previous
#include <cuda_runtime.h>
#include <cuda_fp16.h>
#include <math.h>
#include <stdint.h>

// ---------------------------------------------------------------------------
// GPNN_VCOCO forward — fp16 split GEMMs on warp-level mma.sync.
// R9: GEMM retiled to CTA 128x128 / 128 threads / warp tile 64x64
// (2 CTAs/SM, 25% less smem traffic per FLOP); GI+GH merged into one
// dual launch (blockIdx.z). Workload schedule unchanged from R8.
// ---------------------------------------------------------------------------

namespace {

constexpr int Bb = 16;
constexpr int Nn = 64;
constexpr int Cc = 512;
constexpr int Rr = Bb * Nn * Nn;   // 65536

// ---------------- scratch (static device globals) ----------------
__device__ __half g_EFh[Rr * Cc];
__device__ __half g_Mh [Rr * Cc];
__device__ __half g_Th [Rr * Cc];
__device__ __half g_Wmh [Cc * Cc];                 // Wm edge half, hi
__device__ __half g_WmNh[Cc * Cc], g_WmNl[Cc * Cc];// Wm node half, hi/lo
__device__ __half g_W1h [Cc * Cc];
__device__ __half g_W2h [Cc * Cc];
__device__ __half g_Wihh[3 * Cc * Cc], g_Wihl[3 * Cc * Cc];
__device__ __half g_Whhh[3 * Cc * Cc], g_Whhl[3 * Cc * Cc];
__device__ __half g_NFh [Bb * Nn * Cc], g_NFl[Bb * Nn * Cc];
__device__ __half g_msh [Bb * Nn * Cc], g_msl[Bb * Nn * Cc];
__device__ float g_Hn [Bb * Nn * Cc];
__device__ float g_pa1[Rr];
__device__ float g_GI [Bb * Nn * 3 * Cc];
__device__ float g_GH [Bb * Nn * 3 * Cc];

__device__ __forceinline__ float sigmoidf_(float x) {
    return 1.0f / (1.0f + __expf(-x));
}
__device__ __forceinline__ int permrow(int gr) {
    return (gr & ~4095) | ((gr & 63) << 6) | ((gr >> 6) & 63);
}
__device__ __forceinline__ uint32_t smem_u32(const void* p) {
    uint32_t a;
    asm("{ .reg .u64 t; cvta.to.shared.u64 t, %1; cvt.u32.u64 %0, t; }"
        : "=r"(a) : "l"(p));
    return a;
}
__device__ __forceinline__ uint32_t swz(uint32_t o) {   // 128B-row xor swizzle
    return o ^ ((o >> 3) & 0x70);
}
__device__ __forceinline__ void cp16(uint32_t saddr, const void* g) {
    asm volatile("cp.async.cg.shared.global [%0], [%1], 16;"
                 :: "r"(saddr), "l"(g) : "memory");
}
__device__ __forceinline__ void cp_commit() {
    asm volatile("cp.async.commit_group;" ::: "memory");
}
template<int N>
__device__ __forceinline__ void cp_wait() {
    asm volatile("cp.async.wait_group %0;" :: "n"(N) : "memory");
}
__device__ __forceinline__ void ldm_x4(uint32_t* r, uint32_t addr) {
    asm volatile("ldmatrix.sync.aligned.m8n8.x4.shared.b16 {%0,%1,%2,%3}, [%4];"
                 : "=r"(r[0]), "=r"(r[1]), "=r"(r[2]), "=r"(r[3]) : "r"(addr));
}
__device__ __forceinline__ void mma16816(float* c, const uint32_t* a,
                                         uint32_t b0, uint32_t b1) {
    asm volatile(
        "mma.sync.aligned.m16n8k16.row.col.f32.f16.f16.f32 "
        "{%0,%1,%2,%3}, {%4,%5,%6,%7}, {%8,%9}, {%0,%1,%2,%3};"
        : "+f"(c[0]), "+f"(c[1]), "+f"(c[2]), "+f"(c[3])
        : "r"(a[0]), "r"(a[1]), "r"(a[2]), "r"(a[3]), "r"(b0), "r"(b1));
}

enum { TEPI_MFUSE = 0, TEPI_RELU = 1, TEPI_DOT = 2, TEPI_BIAS = 3 };

constexpr int STAGE_BYTES = 32768;           // 16KB A (128x64 fp16) + 16KB B
constexpr int SMEM_BYTES  = 3 * STAGE_BYTES; // 96KB -> 2 CTAs/SM

// ---------------------------------------------------------------------------
// HMMA GEMM: out[r,n] = epi( sum_{k<512} A[r,k]*W[n,k] ).
// PLANES: 1 = Ah*Bh; 2 = +Al*Bh; 3 = +Ah*Bl (near-fp32).
// CTA 128x128, 128 thr = 4 warps (2m x 2n), warp tile 64x64, K-chunk 64,
// 3-stage cp.async pipeline. Dual mode: blockIdx.z==1 switches to the
// second operand set (A2/B2/bias2/Cf2) — used to fuse GI+GH.
// ---------------------------------------------------------------------------
template<int EPI, bool PERM, int PLANES>
__global__ void __launch_bounds__(128, 2)
hmma_gemm(const __half* AhP, const __half* AlP,
          const __half* BhP, const __half* BlP,
          const float* biasP,               // bl1/bl2/bm/bih
          const float* extra,               // Hn (MFUSE) | Wlo (DOT)
          const float* pa,                  // pa1 logits (PERM)
          __half* Ch,                       // fp16 out (RELU/MFUSE)
          float* CfP, int ldC,              // fp32 out (BIAS)
          float* dotOut,                    // atomic target (DOT)
          const __half* A2h, const __half* A2l,
          const __half* B2h, const __half* B2l,
          const float* bias2, float* Cf2)
{
    extern __shared__ __align__(128) uint8_t smem[];
    const uint32_t sBase = smem_u32(smem);
    constexpr int NCHUNK = PLANES * 8;

    const bool sec = (blockIdx.z == 1);
    const __half* Ah = sec ? A2h : AhP;
    const __half* Al = sec ? A2l : AlP;
    const __half* Bh = sec ? B2h : BhP;
    const __half* Bl = sec ? B2l : BlP;
    const float* bias = sec ? bias2 : biasP;
    float* Cf = sec ? Cf2 : CfP;

    const int tid = threadIdx.x;
    const int wid = tid >> 5, lane = tid & 31;
    const int warp_m = wid & 1, warp_n = wid >> 1;
    const int rowBase = blockIdx.y << 7;    // 128-row blocks
    const int colBase = blockIdx.x << 7;    // 128-col blocks

    // ---- loader: 8 threads per row, 16 rows per sweep, 8 sweeps
    const int lrow = tid >> 3, lseg = tid & 7;
    uint32_t aOff[8], bOff[8], sOff[8];
#pragma unroll
    for (int i = 0; i < 8; i++) {
        const int row = lrow + i * 16;
        int sr = rowBase + row;
        if (PERM) sr = permrow(sr);
        aOff[i] = (uint32_t)sr * 512u + lseg * 8;
        bOff[i] = (uint32_t)(colBase + row) * 512u + lseg * 8;
        sOff[i] = swz((uint32_t)row * 128 + lseg * 16);
    }

    auto load_stage = [&](int st, int ch) {
        const int p  = ch >> 3;
        const int kb = (ch & 7) * 64;
        const __half* Ap = (p == 1) ? Al : Ah;
        const __half* Bp = (p == 2) ? Bl : Bh;
        const uint32_t sa = sBase + st * STAGE_BYTES;
        const uint32_t sb = sa + 16384;
#pragma unroll
        for (int i = 0; i < 8; i++) {
            cp16(sa + sOff[i], Ap + aOff[i] + kb);
            cp16(sb + sOff[i], Bp + bOff[i] + kb);
        }
        cp_commit();
    };

    load_stage(0, 0);
    load_stage(1, 1);

    float acc[4][8][4];
#pragma unroll
    for (int mt = 0; mt < 4; mt++)
#pragma unroll
        for (int nf = 0; nf < 8; nf++)
#pragma unroll
            for (int j = 0; j < 4; j++) acc[mt][nf][j] = 0.0f;

    // ldmatrix lane addressing
    const int aRow = warp_m * 64 + ((lane >> 3) & 1) * 8 + (lane & 7);
    const uint32_t aK = (uint32_t)(lane >> 4) * 16;
    const int bRow = warp_n * 64 + (lane >> 4) * 8 + (lane & 7);
    const uint32_t bK = (uint32_t)((lane >> 3) & 1) * 16;

#pragma unroll 1
    for (int ch = 0; ch < NCHUNK; ch++) {
        if (ch < NCHUNK - 1) cp_wait<1>(); else cp_wait<0>();
        __syncthreads();
        if (ch + 2 < NCHUNK) load_stage((ch + 2) % 3, ch + 2);

        const uint32_t sa = sBase + (ch % 3) * STAGE_BYTES;
        const uint32_t sb = sa + 16384;
#pragma unroll
        for (int ks = 0; ks < 4; ks++) {
            uint32_t a[4][4], b[4][4];
#pragma unroll
            for (int mt = 0; mt < 4; mt++)
                ldm_x4(a[mt], sa + swz((uint32_t)(aRow + mt * 16) * 128 + ks * 32 + aK));
#pragma unroll
            for (int pr = 0; pr < 4; pr++)
                ldm_x4(b[pr], sb + swz((uint32_t)(bRow + pr * 16) * 128 + ks * 32 + bK));
#pragma unroll
            for (int mt = 0; mt < 4; mt++)
#pragma unroll
                for (int nf = 0; nf < 8; nf++)
                    mma16816(acc[mt][nf], a[mt],
                             b[nf >> 1][(nf & 1) * 2], b[nf >> 1][(nf & 1) * 2 + 1]);
        }
    }

    // ---------------- epilogue ----------------
    // c-frag: c0:(m=l/4, n=2(l%4))  c1:n+1  c2:(m+8)  c3:(m+8,n+1)
    const int r0 = rowBase + warp_m * 64 + (lane >> 2);
    const int c0 = colBase + warp_n * 64 + (lane & 3) * 2;

    if (EPI == TEPI_DOT) {
        float dsum[4][2];
#pragma unroll
        for (int mt = 0; mt < 4; mt++) { dsum[mt][0] = 0.f; dsum[mt][1] = 0.f; }
#pragma unroll
        for (int mt = 0; mt < 4; mt++)
#pragma unroll
            for (int nf = 0; nf < 8; nf++) {
                const int gc = c0 + nf * 8;
                const float b0v = bias[gc], b1v = bias[gc + 1];
                const float w0v = extra[gc], w1v = extra[gc + 1];
                dsum[mt][0] += fmaxf(acc[mt][nf][0] + b0v, 0.f) * w0v
                             + fmaxf(acc[mt][nf][1] + b1v, 0.f) * w1v;
                dsum[mt][1] += fmaxf(acc[mt][nf][2] + b0v, 0.f) * w0v
                             + fmaxf(acc[mt][nf][3] + b1v, 0.f) * w1v;
            }
#pragma unroll
        for (int mt = 0; mt < 4; mt++)
#pragma unroll
            for (int h = 0; h < 2; h++) {
                float v = dsum[mt][h];
                v += __shfl_xor_sync(0xffffffffu, v, 1);
                v += __shfl_xor_sync(0xffffffffu, v, 2);
                if ((lane & 3) == 0)
                    atomicAdd(dotOut + r0 + mt * 16 + h * 8, v);
            }
    } else if (EPI == TEPI_BIAS) {
#pragma unroll
        for (int mt = 0; mt < 4; mt++)
#pragma unroll
            for (int h = 0; h < 2; h++) {
                const int row = r0 + mt * 16 + h * 8;
                float2* orow = reinterpret_cast<float2*>(Cf + (size_t)row * ldC);
#pragma unroll
                for (int nf = 0; nf < 8; nf++) {
                    const int gc = c0 + nf * 8;
                    orow[gc >> 1] = make_float2(acc[mt][nf][h * 2] + bias[gc],
                                                acc[mt][nf][h * 2 + 1] + bias[gc + 1]);
                }
            }
    } else {
#pragma unroll
        for (int mt = 0; mt < 4; mt++)
#pragma unroll
            for (int h = 0; h < 2; h++) {
                const int row = r0 + mt * 16 + h * 8;
                float s = 1.0f;
                const float* hnrow = nullptr;
                if (EPI == TEPI_MFUSE)
                    hnrow = extra + (size_t)(((row >> 12) << 6) | (row & 63)) * 512;
                if (PERM) s = sigmoidf_(pa[permrow(row)]);
                uint32_t* oh = reinterpret_cast<uint32_t*>(Ch) + ((size_t)row * 512 >> 1);
#pragma unroll
                for (int nf = 0; nf < 8; nf++) {
                    const int gc = c0 + nf * 8;
                    const float x0 = acc[mt][nf][h * 2 + 0];
                    const float x1 = acc[mt][nf][h * 2 + 1];
                    float y0, y1;
                    if (EPI == TEPI_MFUSE) {
                        y0 = fmaxf(x0 + hnrow[gc],     0.0f);
                        y1 = fmaxf(x1 + hnrow[gc + 1], 0.0f);
                    } else {
                        y0 = fmaxf(fmaf(s, x0, bias[gc]),     0.0f);
                        y1 = fmaxf(fmaf(s, x1, bias[gc + 1]), 0.0f);
                    }
                    __half2 h2;
                    h2.x = __float2half_rn(y0);
                    h2.y = __float2half_rn(y1);
                    oh[gc >> 1] = *reinterpret_cast<uint32_t*>(&h2);
                }
            }
    }
}

// ---------------------------------------------------------------------------
// conversions
// ---------------------------------------------------------------------------
__global__ void split_f32(const float4* __restrict__ in,
                          uint2* __restrict__ hi, uint2* __restrict__ lo, int n4)
{
    const int i = blockIdx.x * blockDim.x + threadIdx.x;
    if (i >= n4) return;
    const float4 v = in[i];
    __half2 hA, hB, lA, lB;
    hA.x = __float2half_rn(v.x); hA.y = __float2half_rn(v.y);
    hB.x = __float2half_rn(v.z); hB.y = __float2half_rn(v.w);
    lA.x = __float2half_rn(v.x - __half2float(hA.x));
    lA.y = __float2half_rn(v.y - __half2float(hA.y));
    lB.x = __float2half_rn(v.z - __half2float(hB.x));
    lB.y = __float2half_rn(v.w - __half2float(hB.y));
    hi[i] = make_uint2(*reinterpret_cast<uint32_t*>(&hA), *reinterpret_cast<uint32_t*>(&hB));
    lo[i] = make_uint2(*reinterpret_cast<uint32_t*>(&lA), *reinterpret_cast<uint32_t*>(&lB));
}

// plain fp32 -> fp16 cast (hi plane only), vectorized
__global__ void conv_act(const float4* __restrict__ in,
                         uint2* __restrict__ hi, int n4)
{
    const int i = blockIdx.x * blockDim.x + threadIdx.x;
    if (i >= n4) return;
    const float4 v = in[i];
    __half2 hA, hB;
    hA.x = __float2half_rn(v.x); hA.y = __float2half_rn(v.y);
    hB.x = __float2half_rn(v.z); hB.y = __float2half_rn(v.w);
    hi[i] = make_uint2(*reinterpret_cast<uint32_t*>(&hA), *reinterpret_cast<uint32_t*>(&hB));
}

// All weight conversions in one launch (segments by linear element index).
__global__ void conv_weights(const float* __restrict__ Wm,
                             const float* __restrict__ Wl1,
                             const float* __restrict__ Wl2,
                             const float* __restrict__ Wih,
                             const float* __restrict__ Whh,
                             __half* __restrict__ Wmh,
                             __half* __restrict__ WmNh, __half* __restrict__ WmNl,
                             __half* __restrict__ W1h,  __half* __restrict__ W2h,
                             __half* __restrict__ Wihh, __half* __restrict__ Wihl,
                             __half* __restrict__ Whhh, __half* __restrict__ Whhl)
{
    const int idx = blockIdx.x * blockDim.x + threadIdx.x;   // < 2.5M
    constexpr int S = 512 * 512;
    float x;
    __half* hi;
    __half* lo = nullptr;
    int off;
    if (idx < S) {
        off = idx;
        x = Wm[(size_t)(off >> 9) * 1024 + 512 + (off & 511)];
        hi = Wmh + off;
    } else if (idx < 2 * S) {
        off = idx - S;
        x = Wm[(size_t)(off >> 9) * 1024 + (off & 511)];
        hi = WmNh + off; lo = WmNl + off;
    } else if (idx < 3 * S) {
        off = idx - 2 * S;
        x = Wl1[off];
        hi = W1h + off;
    } else if (idx < 4 * S) {
        off = idx - 3 * S;
        x = Wl2[off];
        hi = W2h + off;
    } else if (idx < 7 * S) {
        off = idx - 4 * S;
        x = Wih[off];
        hi = Wihh + off; lo = Wihl + off;
    } else {
        off = idx - 7 * S;
        x = Whh[off];
        hi = Whhh + off; lo = Whhl + off;
    }
    const __half h = __float2half_rn(x);
    *hi = h;
    if (lo) *lo = __float2half_rn(x - __half2float(h));
}

__global__ void init_pa(float* __restrict__ pa1, float* __restrict__ pa2,
                        const float* __restrict__ blo)
{
    const int i = blockIdx.x * blockDim.x + threadIdx.x;
    if (i < Rr) {
        const float v = blo[0];
        pa1[i] = v;
        pa2[i] = v;
    }
}

// msum[b,v,:] = sum_w sig(pa2[b,v,w]) * Mh[(b,v,w), :]  -> fp16 hi/lo
__global__ void msum2(const __half* __restrict__ Mh,
                      const float* __restrict__ pa2,
                      __half* __restrict__ msh, __half* __restrict__ msl)
{
    const int bv = blockIdx.x;          // 0..1023
    const int t  = threadIdx.x;         // 128
    __shared__ float sg[64];
    if (t < 64) sg[t] = sigmoidf_(pa2[bv * 64 + t]);
    __syncthreads();
    const uint32_t* mh = reinterpret_cast<const uint32_t*>(Mh + (size_t)bv * 64 * 512);
    const int c = t * 2;
    float a0 = 0.f, a1 = 0.f, a2 = 0.f, a3 = 0.f;
#pragma unroll 4
    for (int w = 0; w < 64; w++) {
        const float s = sg[w];
        const uint32_t h0 = mh[w * 256 + c];
        const uint32_t h1 = mh[w * 256 + c + 1];
        const __half2 H0 = *reinterpret_cast<const __half2*>(&h0);
        const __half2 H1 = *reinterpret_cast<const __half2*>(&h1);
        a0 = fmaf(s, __half2float(H0.x), a0);
        a1 = fmaf(s, __half2float(H0.y), a1);
        a2 = fmaf(s, __half2float(H1.x), a2);
        a3 = fmaf(s, __half2float(H1.y), a3);
    }
    __half2 h2a, h2b, l2a, l2b;
    h2a.x = __float2half_rn(a0); h2a.y = __float2half_rn(a1);
    h2b.x = __float2half_rn(a2); h2b.y = __float2half_rn(a3);
    l2a.x = __float2half_rn(a0 - __half2float(h2a.x));
    l2a.y = __float2half_rn(a1 - __half2float(h2a.y));
    l2b.x = __float2half_rn(a2 - __half2float(h2b.x));
    l2b.y = __float2half_rn(a3 - __half2float(h2b.y));
    uint2* oh = reinterpret_cast<uint2*>(msh + (size_t)bv * 512) + t;
    uint2* ol = reinterpret_cast<uint2*>(msl + (size_t)bv * 512) + t;
    *oh = make_uint2(*reinterpret_cast<uint32_t*>(&h2a), *reinterpret_cast<uint32_t*>(&h2b));
    *ol = make_uint2(*reinterpret_cast<uint32_t*>(&l2a), *reinterpret_cast<uint32_t*>(&l2b));
}

__global__ void gru_readout(const float* __restrict__ GI,
                            const float* __restrict__ GH,
                            const float* __restrict__ NF,
                            const float* __restrict__ Wr1, const float* __restrict__ br1,
                            const float* __restrict__ Wr2, const float* __restrict__ br2,
                            float* __restrict__ out)
{
    const int row = blockIdx.x;         // 0..1023
    __shared__ float hn[512];
    const int t = threadIdx.x;          // 256
    const float* gi = GI + (size_t)row * 1536;
    const float* gh = GH + (size_t)row * 1536;
    const float* h  = NF + (size_t)row * 512;
    for (int d = t; d < 512; d += 256) {
        const float r = sigmoidf_(gi[d] + gh[d]);
        const float z = sigmoidf_(gi[512 + d] + gh[512 + d]);
        const float n = tanhf(gi[1024 + d] + r * gh[1024 + d]);
        hn[d] = (1.0f - z) * n + z * h[d];
    }
    __syncthreads();
    const int warp = t >> 5, lane = t & 31;
    for (int o = warp; o < 28; o += 8) {
        const float* Wr = (o < 26) ? (Wr1 + o * 512) : (Wr2 + (o - 26) * 512);
        float acc = 0.0f;
        for (int k = lane; k < 512; k += 32) acc = fmaf(hn[k], Wr[k], acc);
#pragma unroll
        for (int off = 16; off; off >>= 1)
            acc += __shfl_down_sync(0xffffffffu, acc, off);
        if (lane == 0) {
            if (o < 26) out[65536 + row * 26 + o]               = acc + br1[o];
            else        out[65536 + 26624 + row * 2 + (o - 26)] = acc + br2[o - 26];
        }
    }
}

} // namespace

extern "C" void kernel_launch(void* const* d_in, const int* /*in_sizes*/, int /*n_in*/,
                              void* d_out, int /*out_size*/)
{
    const float* EF  = (const float*)d_in[0];
    const float* NF  = (const float*)d_in[1];
    const float* Wm  = (const float*)d_in[4];
    const float* bm  = (const float*)d_in[5];
    const float* Wl1 = (const float*)d_in[6];
    const float* bl1 = (const float*)d_in[7];
    const float* Wl2 = (const float*)d_in[8];
    const float* bl2 = (const float*)d_in[9];
    const float* Wlo = (const float*)d_in[10];
    const float* blo = (const float*)d_in[11];
    const float* Wih = (const float*)d_in[12];
    const float* bih = (const float*)d_in[13];
    const float* Whh = (const float*)d_in[14];
    const float* bhh = (const float*)d_in[15];
    const float* Wr1 = (const float*)d_in[16];
    const float* br1 = (const float*)d_in[17];
    const float* Wr2 = (const float*)d_in[18];
    const float* br2 = (const float*)d_in[19];
    float* out = (float*)d_out;

    __half *pEFh, *pMh, *pTh;
    __half *pWmh, *pWmNh, *pWmNl, *pW1h, *pW2h;
    __half *pWihh, *pWihl, *pWhhh, *pWhhl, *pNFh, *pNFl, *pmsh, *pmsl;
    float *pHn, *pPa1, *pGI, *pGH;
    cudaGetSymbolAddress((void**)&pEFh,  g_EFh);
    cudaGetSymbolAddress((void**)&pMh,   g_Mh);
    cudaGetSymbolAddress((void**)&pTh,   g_Th);
    cudaGetSymbolAddress((void**)&pWmh,  g_Wmh);
    cudaGetSymbolAddress((void**)&pWmNh, g_WmNh);
    cudaGetSymbolAddress((void**)&pWmNl, g_WmNl);
    cudaGetSymbolAddress((void**)&pW1h,  g_W1h);
    cudaGetSymbolAddress((void**)&pW2h,  g_W2h);
    cudaGetSymbolAddress((void**)&pWihh, g_Wihh);
    cudaGetSymbolAddress((void**)&pWihl, g_Wihl);
    cudaGetSymbolAddress((void**)&pWhhh, g_Whhh);
    cudaGetSymbolAddress((void**)&pWhhl, g_Whhl);
    cudaGetSymbolAddress((void**)&pNFh,  g_NFh);
    cudaGetSymbolAddress((void**)&pNFl,  g_NFl);
    cudaGetSymbolAddress((void**)&pmsh,  g_msh);
    cudaGetSymbolAddress((void**)&pmsl,  g_msl);
    cudaGetSymbolAddress((void**)&pHn,   g_Hn);
    cudaGetSymbolAddress((void**)&pPa1,  g_pa1);
    cudaGetSymbolAddress((void**)&pGI,   g_GI);
    cudaGetSymbolAddress((void**)&pGH,   g_GH);

    // kernel variants
    auto kBIAS = hmma_gemm<TEPI_BIAS,  false, 3>;
    auto kMF   = hmma_gemm<TEPI_MFUSE, false, 1>;
    auto kRE   = hmma_gemm<TEPI_RELU,  false, 1>;
    auto kRP   = hmma_gemm<TEPI_RELU,  true,  1>;
    auto kDOT  = hmma_gemm<TEPI_DOT,   false, 1>;
    cudaFuncSetAttribute(kBIAS, cudaFuncAttributeMaxDynamicSharedMemorySize, SMEM_BYTES);
    cudaFuncSetAttribute(kMF,   cudaFuncAttributeMaxDynamicSharedMemorySize, SMEM_BYTES);
    cudaFuncSetAttribute(kRE,   cudaFuncAttributeMaxDynamicSharedMemorySize, SMEM_BYTES);
    cudaFuncSetAttribute(kRP,   cudaFuncAttributeMaxDynamicSharedMemorySize, SMEM_BYTES);
    cudaFuncSetAttribute(kDOT,  cudaFuncAttributeMaxDynamicSharedMemorySize, SMEM_BYTES);

    const int n4ef = Rr * Cc / 4;
    const int n4nf = Bb * Nn * Cc / 4;
    conv_act<<<(n4ef + 255) / 256, 256>>>((const float4*)EF, (uint2*)pEFh, n4ef);
    split_f32<<<(n4nf + 255) / 256, 256>>>((const float4*)NF, (uint2*)pNFh, (uint2*)pNFl, n4nf);
    conv_weights<<<10240, 256>>>(Wm, Wl1, Wl2, Wih, Whh,
                                 pWmh, pWmNh, pWmNl, pW1h, pW2h,
                                 pWihh, pWihl, pWhhh, pWhhl);
    init_pa<<<(Rr + 255) / 256, 256>>>(pPa1, out, blo);

    // Hn = NF @ Wm[:, :512]^T + bm   (3-plane, fp32 out)
    kBIAS<<<dim3(4, 8, 1), 128, SMEM_BYTES>>>(pNFh, pNFl, pWmNh, pWmNl, bm,
                                              nullptr, nullptr, nullptr,
                                              pHn, 512, nullptr,
                                              nullptr, nullptr, nullptr, nullptr,
                                              nullptr, nullptr);

    const dim3 gTC(4, 512, 1);   // 128-row x 128-col tiles, 65536 rows
    // M = relu(EF @ WmE^T + Hn)  -> Mh
    kMF<<<gTC, 128, SMEM_BYTES>>>(pEFh, nullptr, pWmh, nullptr, nullptr, pHn,
                                  nullptr, pMh, nullptr, 0, nullptr,
                                  nullptr, nullptr, nullptr, nullptr,
                                  nullptr, nullptr);
    // T1 = relu(EF @ Wl1^T + bl1) -> Th
    kRE<<<gTC, 128, SMEM_BYTES>>>(pEFh, nullptr, pW1h, nullptr, bl1, nullptr,
                                  nullptr, pTh, nullptr, 0, nullptr,
                                  nullptr, nullptr, nullptr, nullptr,
                                  nullptr, nullptr);
    // pa1 += dot(relu(T1 @ Wl2^T + bl2), Wlo)
    kDOT<<<gTC, 128, SMEM_BYTES>>>(pTh, nullptr, pW2h, nullptr, bl2, Wlo,
                                   nullptr, nullptr, nullptr, 0, pPa1,
                                   nullptr, nullptr, nullptr, nullptr,
                                   nullptr, nullptr);
    // T1' = relu(sig(pa1[perm]) * M[perm] @ Wl1^T + bl1) -> Th
    kRP<<<gTC, 128, SMEM_BYTES>>>(pMh, nullptr, pW1h, nullptr, bl1, nullptr,
                                  pPa1, pTh, nullptr, 0, nullptr,
                                  nullptr, nullptr, nullptr, nullptr,
                                  nullptr, nullptr);
    // pred_adj += dot(relu(T1' @ Wl2^T + bl2), Wlo)
    kDOT<<<gTC, 128, SMEM_BYTES>>>(pTh, nullptr, pW2h, nullptr, bl2, Wlo,
                                   nullptr, nullptr, nullptr, 0, out,
                                   nullptr, nullptr, nullptr, nullptr,
                                   nullptr, nullptr);

    msum2<<<Bb * Nn, 128>>>(pMh, out, pmsh, pmsl);
    // GI = msum @ W_ih^T + b_ih  and  GH = NF @ W_hh^T + b_hh  (dual launch)
    kBIAS<<<dim3(12, 8, 2), 128, SMEM_BYTES>>>(pmsh, pmsl, pWihh, pWihl, bih,
                                               nullptr, nullptr, nullptr,
                                               pGI, 1536, nullptr,
                                               pNFh, pNFl, pWhhh, pWhhl,
                                               bhh, pGH);
    gru_readout<<<Bb * Nn, 256>>>(pGI, pGH, NF, Wr1, br1, Wr2, br2, out);
}

// round 10
// speedup vs baseline: 6.5380x; 1.0835x over previous
#include <cuda_runtime.h>
#include <cuda_fp16.h>
#include <math.h>
#include <stdint.h>

// ---------------------------------------------------------------------------
// GPNN_VCOCO forward — fp16 split GEMMs on warp-level mma.sync.
// R10: big GEMMs are at the legacy-HMMA issue ceiling (~294 TF/s); this
// round shaves overhead: kMF+kRE fused into one dual-output pass over EFh,
// Hn 2-plane, init_pa vectorized.
// ---------------------------------------------------------------------------

namespace {

constexpr int Bb = 16;
constexpr int Nn = 64;
constexpr int Cc = 512;
constexpr int Rr = Bb * Nn * Nn;   // 65536

// ---------------- scratch (static device globals) ----------------
__device__ __half g_EFh[Rr * Cc];
__device__ __half g_Mh [Rr * Cc];
__device__ __half g_Th [Rr * Cc];
__device__ __half g_Wmh [Cc * Cc];                 // Wm edge half, hi
__device__ __half g_WmNh[Cc * Cc], g_WmNl[Cc * Cc];// Wm node half, hi/lo
__device__ __half g_W1h [Cc * Cc];
__device__ __half g_W2h [Cc * Cc];
__device__ __half g_Wihh[3 * Cc * Cc], g_Wihl[3 * Cc * Cc];
__device__ __half g_Whhh[3 * Cc * Cc], g_Whhl[3 * Cc * Cc];
__device__ __half g_NFh [Bb * Nn * Cc], g_NFl[Bb * Nn * Cc];
__device__ __half g_msh [Bb * Nn * Cc], g_msl[Bb * Nn * Cc];
__device__ float g_Hn [Bb * Nn * Cc];
__device__ float g_pa1[Rr];
__device__ float g_GI [Bb * Nn * 3 * Cc];
__device__ float g_GH [Bb * Nn * 3 * Cc];

__device__ __forceinline__ float sigmoidf_(float x) {
    return 1.0f / (1.0f + __expf(-x));
}
__device__ __forceinline__ int permrow(int gr) {
    return (gr & ~4095) | ((gr & 63) << 6) | ((gr >> 6) & 63);
}
__device__ __forceinline__ uint32_t smem_u32(const void* p) {
    uint32_t a;
    asm("{ .reg .u64 t; cvta.to.shared.u64 t, %1; cvt.u32.u64 %0, t; }"
        : "=r"(a) : "l"(p));
    return a;
}
__device__ __forceinline__ uint32_t swz(uint32_t o) {   // 128B-row xor swizzle
    return o ^ ((o >> 3) & 0x70);
}
__device__ __forceinline__ void cp16(uint32_t saddr, const void* g) {
    asm volatile("cp.async.cg.shared.global [%0], [%1], 16;"
                 :: "r"(saddr), "l"(g) : "memory");
}
__device__ __forceinline__ void cp_commit() {
    asm volatile("cp.async.commit_group;" ::: "memory");
}
template<int N>
__device__ __forceinline__ void cp_wait() {
    asm volatile("cp.async.wait_group %0;" :: "n"(N) : "memory");
}
__device__ __forceinline__ void ldm_x4(uint32_t* r, uint32_t addr) {
    asm volatile("ldmatrix.sync.aligned.m8n8.x4.shared.b16 {%0,%1,%2,%3}, [%4];"
                 : "=r"(r[0]), "=r"(r[1]), "=r"(r[2]), "=r"(r[3]) : "r"(addr));
}
__device__ __forceinline__ void mma16816(float* c, const uint32_t* a,
                                         uint32_t b0, uint32_t b1) {
    asm volatile(
        "mma.sync.aligned.m16n8k16.row.col.f32.f16.f16.f32 "
        "{%0,%1,%2,%3}, {%4,%5,%6,%7}, {%8,%9}, {%0,%1,%2,%3};"
        : "+f"(c[0]), "+f"(c[1]), "+f"(c[2]), "+f"(c[3])
        : "r"(a[0]), "r"(a[1]), "r"(a[2]), "r"(a[3]), "r"(b0), "r"(b1));
}

enum { TEPI_MFUSE = 0, TEPI_RELU = 1, TEPI_DOT = 2, TEPI_BIAS = 3 };

constexpr int STAGE_BYTES = 32768;           // 16KB A + 16KB B
constexpr int SMEM_BYTES  = 3 * STAGE_BYTES; // 96KB -> 2 CTAs/SM

// ---------------------------------------------------------------------------
// Generic HMMA GEMM (unchanged from R9): CTA 128x128, 128 thr, warp 64x64,
// 3-stage cp.async. Dual mode via blockIdx.z for GI+GH.
// ---------------------------------------------------------------------------
template<int EPI, bool PERM, int PLANES>
__global__ void __launch_bounds__(128, 2)
hmma_gemm(const __half* AhP, const __half* AlP,
          const __half* BhP, const __half* BlP,
          const float* biasP,
          const float* extra,               // Wlo (DOT)
          const float* pa,                  // pa1 logits (PERM)
          __half* Ch,                       // fp16 out (RELU)
          float* CfP, int ldC,              // fp32 out (BIAS)
          float* dotOut,                    // atomic target (DOT)
          const __half* A2h, const __half* A2l,
          const __half* B2h, const __half* B2l,
          const float* bias2, float* Cf2)
{
    extern __shared__ __align__(128) uint8_t smem[];
    const uint32_t sBase = smem_u32(smem);
    constexpr int NCHUNK = PLANES * 8;

    const bool sec = (blockIdx.z == 1);
    const __half* Ah = sec ? A2h : AhP;
    const __half* Al = sec ? A2l : AlP;
    const __half* Bh = sec ? B2h : BhP;
    const __half* Bl = sec ? B2l : BlP;
    const float* bias = sec ? bias2 : biasP;
    float* Cf = sec ? Cf2 : CfP;

    const int tid = threadIdx.x;
    const int wid = tid >> 5, lane = tid & 31;
    const int warp_m = wid & 1, warp_n = wid >> 1;
    const int rowBase = blockIdx.y << 7;
    const int colBase = blockIdx.x << 7;

    const int lrow = tid >> 3, lseg = tid & 7;
    uint32_t aOff[8], bOff[8], sOff[8];
#pragma unroll
    for (int i = 0; i < 8; i++) {
        const int row = lrow + i * 16;
        int sr = rowBase + row;
        if (PERM) sr = permrow(sr);
        aOff[i] = (uint32_t)sr * 512u + lseg * 8;
        bOff[i] = (uint32_t)(colBase + row) * 512u + lseg * 8;
        sOff[i] = swz((uint32_t)row * 128 + lseg * 16);
    }

    auto load_stage = [&](int st, int ch) {
        const int p  = ch >> 3;
        const int kb = (ch & 7) * 64;
        const __half* Ap = (p == 1) ? Al : Ah;
        const __half* Bp = (p == 2) ? Bl : Bh;
        const uint32_t sa = sBase + st * STAGE_BYTES;
        const uint32_t sb = sa + 16384;
#pragma unroll
        for (int i = 0; i < 8; i++) {
            cp16(sa + sOff[i], Ap + aOff[i] + kb);
            cp16(sb + sOff[i], Bp + bOff[i] + kb);
        }
        cp_commit();
    };

    load_stage(0, 0);
    load_stage(1, 1);

    float acc[4][8][4];
#pragma unroll
    for (int mt = 0; mt < 4; mt++)
#pragma unroll
        for (int nf = 0; nf < 8; nf++)
#pragma unroll
            for (int j = 0; j < 4; j++) acc[mt][nf][j] = 0.0f;

    const int aRow = warp_m * 64 + ((lane >> 3) & 1) * 8 + (lane & 7);
    const uint32_t aK = (uint32_t)(lane >> 4) * 16;
    const int bRow = warp_n * 64 + (lane >> 4) * 8 + (lane & 7);
    const uint32_t bK = (uint32_t)((lane >> 3) & 1) * 16;

#pragma unroll 1
    for (int ch = 0; ch < NCHUNK; ch++) {
        if (ch < NCHUNK - 1) cp_wait<1>(); else cp_wait<0>();
        __syncthreads();
        if (ch + 2 < NCHUNK) load_stage((ch + 2) % 3, ch + 2);

        const uint32_t sa = sBase + (ch % 3) * STAGE_BYTES;
        const uint32_t sb = sa + 16384;
#pragma unroll
        for (int ks = 0; ks < 4; ks++) {
            uint32_t a[4][4], b[4][4];
#pragma unroll
            for (int mt = 0; mt < 4; mt++)
                ldm_x4(a[mt], sa + swz((uint32_t)(aRow + mt * 16) * 128 + ks * 32 + aK));
#pragma unroll
            for (int pr = 0; pr < 4; pr++)
                ldm_x4(b[pr], sb + swz((uint32_t)(bRow + pr * 16) * 128 + ks * 32 + bK));
#pragma unroll
            for (int mt = 0; mt < 4; mt++)
#pragma unroll
                for (int nf = 0; nf < 8; nf++)
                    mma16816(acc[mt][nf], a[mt],
                             b[nf >> 1][(nf & 1) * 2], b[nf >> 1][(nf & 1) * 2 + 1]);
        }
    }

    const int r0 = rowBase + warp_m * 64 + (lane >> 2);
    const int c0 = colBase + warp_n * 64 + (lane & 3) * 2;

    if (EPI == TEPI_DOT) {
        float dsum[4][2];
#pragma unroll
        for (int mt = 0; mt < 4; mt++) { dsum[mt][0] = 0.f; dsum[mt][1] = 0.f; }
#pragma unroll
        for (int mt = 0; mt < 4; mt++)
#pragma unroll
            for (int nf = 0; nf < 8; nf++) {
                const int gc = c0 + nf * 8;
                const float b0v = bias[gc], b1v = bias[gc + 1];
                const float w0v = extra[gc], w1v = extra[gc + 1];
                dsum[mt][0] += fmaxf(acc[mt][nf][0] + b0v, 0.f) * w0v
                             + fmaxf(acc[mt][nf][1] + b1v, 0.f) * w1v;
                dsum[mt][1] += fmaxf(acc[mt][nf][2] + b0v, 0.f) * w0v
                             + fmaxf(acc[mt][nf][3] + b1v, 0.f) * w1v;
            }
#pragma unroll
        for (int mt = 0; mt < 4; mt++)
#pragma unroll
            for (int h = 0; h < 2; h++) {
                float v = dsum[mt][h];
                v += __shfl_xor_sync(0xffffffffu, v, 1);
                v += __shfl_xor_sync(0xffffffffu, v, 2);
                if ((lane & 3) == 0)
                    atomicAdd(dotOut + r0 + mt * 16 + h * 8, v);
            }
    } else if (EPI == TEPI_BIAS) {
#pragma unroll
        for (int mt = 0; mt < 4; mt++)
#pragma unroll
            for (int h = 0; h < 2; h++) {
                const int row = r0 + mt * 16 + h * 8;
                float2* orow = reinterpret_cast<float2*>(Cf + (size_t)row * ldC);
#pragma unroll
                for (int nf = 0; nf < 8; nf++) {
                    const int gc = c0 + nf * 8;
                    orow[gc >> 1] = make_float2(acc[mt][nf][h * 2] + bias[gc],
                                                acc[mt][nf][h * 2 + 1] + bias[gc + 1]);
                }
            }
    } else {   // RELU (with optional PERM scale)
#pragma unroll
        for (int mt = 0; mt < 4; mt++)
#pragma unroll
            for (int h = 0; h < 2; h++) {
                const int row = r0 + mt * 16 + h * 8;
                float s = 1.0f;
                if (PERM) s = sigmoidf_(pa[permrow(row)]);
                uint32_t* oh = reinterpret_cast<uint32_t*>(Ch) + ((size_t)row * 512 >> 1);
#pragma unroll
                for (int nf = 0; nf < 8; nf++) {
                    const int gc = c0 + nf * 8;
                    const float y0 = fmaxf(fmaf(s, acc[mt][nf][h * 2],     bias[gc]),     0.0f);
                    const float y1 = fmaxf(fmaf(s, acc[mt][nf][h * 2 + 1], bias[gc + 1]), 0.0f);
                    __half2 h2;
                    h2.x = __float2half_rn(y0);
                    h2.y = __float2half_rn(y1);
                    oh[gc >> 1] = *reinterpret_cast<uint32_t*>(&h2);
                }
            }
    }
}

// ---------------------------------------------------------------------------
// Fused M + T1 kernel: one pass over EFh, two B streams (WmE, W1), two
// accumulator sets. CTA 128x128x(2 outputs), 256 thr = 8 warps (2m x 4n),
// warp tile 64x32 per output. 3 stages x 48KB = 144KB smem, 1 CTA/SM.
//   M  = relu(EF @ WmE^T + Hn[b,w])   -> Mh
//   T1 = relu(EF @ W1^T  + bl1)       -> Th
// ---------------------------------------------------------------------------
__global__ void __launch_bounds__(256, 1)
hmma_mf_re(const __half* __restrict__ EFh,
           const __half* __restrict__ WmE, const __half* __restrict__ W1,
           const float* __restrict__ Hn, const float* __restrict__ bl1,
           __half* __restrict__ Mh, __half* __restrict__ Th)
{
    extern __shared__ __align__(128) uint8_t smem[];
    const uint32_t sBase = smem_u32(smem);
    constexpr int STG = 49152;   // 16KB A + 16KB BM + 16KB BT

    const int tid = threadIdx.x;
    const int wid = tid >> 5, lane = tid & 31;
    const int warp_m = wid & 1, warp_n = wid >> 1;   // 2 x 4
    const int rowBase = blockIdx.y << 7;
    const int colBase = blockIdx.x << 7;

    const int lrow = tid >> 3, lseg = tid & 7;       // 32 rows/sweep
    uint32_t aOff[4], bOff[4], sOff[4];
#pragma unroll
    for (int i = 0; i < 4; i++) {
        const int row = lrow + i * 32;
        aOff[i] = (uint32_t)(rowBase + row) * 512u + lseg * 8;
        bOff[i] = (uint32_t)(colBase + row) * 512u + lseg * 8;
        sOff[i] = swz((uint32_t)row * 128 + lseg * 16);
    }

    auto load_stage = [&](int st, int ch) {
        const int kb = ch * 64;
        const uint32_t sa  = sBase + st * STG;
        const uint32_t sbM = sa + 16384;
        const uint32_t sbT = sa + 32768;
#pragma unroll
        for (int i = 0; i < 4; i++) {
            cp16(sa  + sOff[i], EFh + aOff[i] + kb);
            cp16(sbM + sOff[i], WmE + bOff[i] + kb);
            cp16(sbT + sOff[i], W1  + bOff[i] + kb);
        }
        cp_commit();
    };

    load_stage(0, 0);
    load_stage(1, 1);

    float accM[4][4][4], accT[4][4][4];
#pragma unroll
    for (int mt = 0; mt < 4; mt++)
#pragma unroll
        for (int nf = 0; nf < 4; nf++)
#pragma unroll
            for (int j = 0; j < 4; j++) { accM[mt][nf][j] = 0.0f; accT[mt][nf][j] = 0.0f; }

    const int aRow = warp_m * 64 + ((lane >> 3) & 1) * 8 + (lane & 7);
    const uint32_t aK = (uint32_t)(lane >> 4) * 16;
    const int bRow = warp_n * 32 + (lane >> 4) * 8 + (lane & 7);
    const uint32_t bK = (uint32_t)((lane >> 3) & 1) * 16;

#pragma unroll 1
    for (int ch = 0; ch < 8; ch++) {
        if (ch < 7) cp_wait<1>(); else cp_wait<0>();
        __syncthreads();
        if (ch + 2 < 8) load_stage((ch + 2) % 3, ch + 2);

        const uint32_t sa  = sBase + (ch % 3) * STG;
        const uint32_t sbM = sa + 16384;
        const uint32_t sbT = sa + 32768;
#pragma unroll
        for (int ks = 0; ks < 4; ks++) {
            uint32_t a[4][4], bM[2][4], bT[2][4];
#pragma unroll
            for (int mt = 0; mt < 4; mt++)
                ldm_x4(a[mt], sa + swz((uint32_t)(aRow + mt * 16) * 128 + ks * 32 + aK));
#pragma unroll
            for (int pr = 0; pr < 2; pr++) {
                const uint32_t off = swz((uint32_t)(bRow + pr * 16) * 128 + ks * 32 + bK);
                ldm_x4(bM[pr], sbM + off);
                ldm_x4(bT[pr], sbT + off);
            }
#pragma unroll
            for (int mt = 0; mt < 4; mt++)
#pragma unroll
                for (int nf = 0; nf < 4; nf++) {
                    mma16816(accM[mt][nf], a[mt],
                             bM[nf >> 1][(nf & 1) * 2], bM[nf >> 1][(nf & 1) * 2 + 1]);
                    mma16816(accT[mt][nf], a[mt],
                             bT[nf >> 1][(nf & 1) * 2], bT[nf >> 1][(nf & 1) * 2 + 1]);
                }
        }
    }

    const int r0 = rowBase + warp_m * 64 + (lane >> 2);
    const int c0 = colBase + warp_n * 32 + (lane & 3) * 2;
#pragma unroll
    for (int mt = 0; mt < 4; mt++)
#pragma unroll
        for (int h = 0; h < 2; h++) {
            const int row = r0 + mt * 16 + h * 8;
            const float* hnrow = Hn + (size_t)(((row >> 12) << 6) | (row & 63)) * 512;
            uint32_t* om = reinterpret_cast<uint32_t*>(Mh) + ((size_t)row * 512 >> 1);
            uint32_t* ot = reinterpret_cast<uint32_t*>(Th) + ((size_t)row * 512 >> 1);
#pragma unroll
            for (int nf = 0; nf < 4; nf++) {
                const int gc = c0 + nf * 8;
                const float m0 = fmaxf(accM[mt][nf][h * 2]     + hnrow[gc],     0.0f);
                const float m1 = fmaxf(accM[mt][nf][h * 2 + 1] + hnrow[gc + 1], 0.0f);
                const float t0 = fmaxf(accT[mt][nf][h * 2]     + bl1[gc],       0.0f);
                const float t1 = fmaxf(accT[mt][nf][h * 2 + 1] + bl1[gc + 1],   0.0f);
                __half2 hm, ht;
                hm.x = __float2half_rn(m0); hm.y = __float2half_rn(m1);
                ht.x = __float2half_rn(t0); ht.y = __float2half_rn(t1);
                om[gc >> 1] = *reinterpret_cast<uint32_t*>(&hm);
                ot[gc >> 1] = *reinterpret_cast<uint32_t*>(&ht);
            }
        }
}

// ---------------------------------------------------------------------------
// conversions
// ---------------------------------------------------------------------------
__global__ void split_f32(const float4* __restrict__ in,
                          uint2* __restrict__ hi, uint2* __restrict__ lo, int n4)
{
    const int i = blockIdx.x * blockDim.x + threadIdx.x;
    if (i >= n4) return;
    const float4 v = in[i];
    __half2 hA, hB, lA, lB;
    hA.x = __float2half_rn(v.x); hA.y = __float2half_rn(v.y);
    hB.x = __float2half_rn(v.z); hB.y = __float2half_rn(v.w);
    lA.x = __float2half_rn(v.x - __half2float(hA.x));
    lA.y = __float2half_rn(v.y - __half2float(hA.y));
    lB.x = __float2half_rn(v.z - __half2float(hB.x));
    lB.y = __float2half_rn(v.w - __half2float(hB.y));
    hi[i] = make_uint2(*reinterpret_cast<uint32_t*>(&hA), *reinterpret_cast<uint32_t*>(&hB));
    lo[i] = make_uint2(*reinterpret_cast<uint32_t*>(&lA), *reinterpret_cast<uint32_t*>(&lB));
}

__global__ void conv_act(const float4* __restrict__ in,
                         uint2* __restrict__ hi, int n4)
{
    const int i = blockIdx.x * blockDim.x + threadIdx.x;
    if (i >= n4) return;
    const float4 v = in[i];
    __half2 hA, hB;
    hA.x = __float2half_rn(v.x); hA.y = __float2half_rn(v.y);
    hB.x = __float2half_rn(v.z); hB.y = __float2half_rn(v.w);
    hi[i] = make_uint2(*reinterpret_cast<uint32_t*>(&hA), *reinterpret_cast<uint32_t*>(&hB));
}

__global__ void conv_weights(const float* __restrict__ Wm,
                             const float* __restrict__ Wl1,
                             const float* __restrict__ Wl2,
                             const float* __restrict__ Wih,
                             const float* __restrict__ Whh,
                             __half* __restrict__ Wmh,
                             __half* __restrict__ WmNh, __half* __restrict__ WmNl,
                             __half* __restrict__ W1h,  __half* __restrict__ W2h,
                             __half* __restrict__ Wihh, __half* __restrict__ Wihl,
                             __half* __restrict__ Whhh, __half* __restrict__ Whhl)
{
    const int idx = blockIdx.x * blockDim.x + threadIdx.x;   // < 2.5M
    constexpr int S = 512 * 512;
    float x;
    __half* hi;
    __half* lo = nullptr;
    int off;
    if (idx < S) {
        off = idx;
        x = Wm[(size_t)(off >> 9) * 1024 + 512 + (off & 511)];
        hi = Wmh + off;
    } else if (idx < 2 * S) {
        off = idx - S;
        x = Wm[(size_t)(off >> 9) * 1024 + (off & 511)];
        hi = WmNh + off; lo = WmNl + off;
    } else if (idx < 3 * S) {
        off = idx - 2 * S;
        x = Wl1[off];
        hi = W1h + off;
    } else if (idx < 4 * S) {
        off = idx - 3 * S;
        x = Wl2[off];
        hi = W2h + off;
    } else if (idx < 7 * S) {
        off = idx - 4 * S;
        x = Wih[off];
        hi = Wihh + off; lo = Wihl + off;
    } else {
        off = idx - 7 * S;
        x = Whh[off];
        hi = Whhh + off; lo = Whhl + off;
    }
    const __half h = __float2half_rn(x);
    *hi = h;
    if (lo) *lo = __float2half_rn(x - __half2float(h));
}

__global__ void init_pa(float4* __restrict__ pa1, float4* __restrict__ pa2,
                        const float* __restrict__ blo)
{
    const int i = blockIdx.x * blockDim.x + threadIdx.x;
    if (i < Rr / 4) {
        const float v = blo[0];
        const float4 f = make_float4(v, v, v, v);
        pa1[i] = f;
        pa2[i] = f;
    }
}

// msum[b,v,:] = sum_w sig(pa2[b,v,w]) * Mh[(b,v,w), :]  -> fp16 hi/lo
__global__ void msum2(const __half* __restrict__ Mh,
                      const float* __restrict__ pa2,
                      __half* __restrict__ msh, __half* __restrict__ msl)
{
    const int bv = blockIdx.x;
    const int t  = threadIdx.x;   // 128
    __shared__ float sg[64];
    if (t < 64) sg[t] = sigmoidf_(pa2[bv * 64 + t]);
    __syncthreads();
    const uint32_t* mh = reinterpret_cast<const uint32_t*>(Mh + (size_t)bv * 64 * 512);
    const int c = t * 2;
    float a0 = 0.f, a1 = 0.f, a2 = 0.f, a3 = 0.f;
#pragma unroll 4
    for (int w = 0; w < 64; w++) {
        const float s = sg[w];
        const uint32_t h0 = mh[w * 256 + c];
        const uint32_t h1 = mh[w * 256 + c + 1];
        const __half2 H0 = *reinterpret_cast<const __half2*>(&h0);
        const __half2 H1 = *reinterpret_cast<const __half2*>(&h1);
        a0 = fmaf(s, __half2float(H0.x), a0);
        a1 = fmaf(s, __half2float(H0.y), a1);
        a2 = fmaf(s, __half2float(H1.x), a2);
        a3 = fmaf(s, __half2float(H1.y), a3);
    }
    __half2 h2a, h2b, l2a, l2b;
    h2a.x = __float2half_rn(a0); h2a.y = __float2half_rn(a1);
    h2b.x = __float2half_rn(a2); h2b.y = __float2half_rn(a3);
    l2a.x = __float2half_rn(a0 - __half2float(h2a.x));
    l2a.y = __float2half_rn(a1 - __half2float(h2a.y));
    l2b.x = __float2half_rn(a2 - __half2float(h2b.x));
    l2b.y = __float2half_rn(a3 - __half2float(h2b.y));
    uint2* oh = reinterpret_cast<uint2*>(msh + (size_t)bv * 512) + t;
    uint2* ol = reinterpret_cast<uint2*>(msl + (size_t)bv * 512) + t;
    *oh = make_uint2(*reinterpret_cast<uint32_t*>(&h2a), *reinterpret_cast<uint32_t*>(&h2b));
    *ol = make_uint2(*reinterpret_cast<uint32_t*>(&l2a), *reinterpret_cast<uint32_t*>(&l2b));
}

__global__ void gru_readout(const float* __restrict__ GI,
                            const float* __restrict__ GH,
                            const float* __restrict__ NF,
                            const float* __restrict__ Wr1, const float* __restrict__ br1,
                            const float* __restrict__ Wr2, const float* __restrict__ br2,
                            float* __restrict__ out)
{
    const int row = blockIdx.x;
    __shared__ float hn[512];
    const int t = threadIdx.x;   // 256
    const float* gi = GI + (size_t)row * 1536;
    const float* gh = GH + (size_t)row * 1536;
    const float* h  = NF + (size_t)row * 512;
    for (int d = t; d < 512; d += 256) {
        const float r = sigmoidf_(gi[d] + gh[d]);
        const float z = sigmoidf_(gi[512 + d] + gh[512 + d]);
        const float n = tanhf(gi[1024 + d] + r * gh[1024 + d]);
        hn[d] = (1.0f - z) * n + z * h[d];
    }
    __syncthreads();
    const int warp = t >> 5, lane = t & 31;
    for (int o = warp; o < 28; o += 8) {
        const float* Wr = (o < 26) ? (Wr1 + o * 512) : (Wr2 + (o - 26) * 512);
        float acc = 0.0f;
        for (int k = lane; k < 512; k += 32) acc = fmaf(hn[k], Wr[k], acc);
#pragma unroll
        for (int off = 16; off; off >>= 1)
            acc += __shfl_down_sync(0xffffffffu, acc, off);
        if (lane == 0) {
            if (o < 26) out[65536 + row * 26 + o]               = acc + br1[o];
            else        out[65536 + 26624 + row * 2 + (o - 26)] = acc + br2[o - 26];
        }
    }
}

} // namespace

extern "C" void kernel_launch(void* const* d_in, const int* /*in_sizes*/, int /*n_in*/,
                              void* d_out, int /*out_size*/)
{
    const float* EF  = (const float*)d_in[0];
    const float* NF  = (const float*)d_in[1];
    const float* Wm  = (const float*)d_in[4];
    const float* bm  = (const float*)d_in[5];
    const float* Wl1 = (const float*)d_in[6];
    const float* bl1 = (const float*)d_in[7];
    const float* Wl2 = (const float*)d_in[8];
    const float* bl2 = (const float*)d_in[9];
    const float* Wlo = (const float*)d_in[10];
    const float* blo = (const float*)d_in[11];
    const float* Wih = (const float*)d_in[12];
    const float* bih = (const float*)d_in[13];
    const float* Whh = (const float*)d_in[14];
    const float* bhh = (const float*)d_in[15];
    const float* Wr1 = (const float*)d_in[16];
    const float* br1 = (const float*)d_in[17];
    const float* Wr2 = (const float*)d_in[18];
    const float* br2 = (const float*)d_in[19];
    float* out = (float*)d_out;

    __half *pEFh, *pMh, *pTh;
    __half *pWmh, *pWmNh, *pWmNl, *pW1h, *pW2h;
    __half *pWihh, *pWihl, *pWhhh, *pWhhl, *pNFh, *pNFl, *pmsh, *pmsl;
    float *pHn, *pPa1, *pGI, *pGH;
    cudaGetSymbolAddress((void**)&pEFh,  g_EFh);
    cudaGetSymbolAddress((void**)&pMh,   g_Mh);
    cudaGetSymbolAddress((void**)&pTh,   g_Th);
    cudaGetSymbolAddress((void**)&pWmh,  g_Wmh);
    cudaGetSymbolAddress((void**)&pWmNh, g_WmNh);
    cudaGetSymbolAddress((void**)&pWmNl, g_WmNl);
    cudaGetSymbolAddress((void**)&pW1h,  g_W1h);
    cudaGetSymbolAddress((void**)&pW2h,  g_W2h);
    cudaGetSymbolAddress((void**)&pWihh, g_Wihh);
    cudaGetSymbolAddress((void**)&pWihl, g_Wihl);
    cudaGetSymbolAddress((void**)&pWhhh, g_Whhh);
    cudaGetSymbolAddress((void**)&pWhhl, g_Whhl);
    cudaGetSymbolAddress((void**)&pNFh,  g_NFh);
    cudaGetSymbolAddress((void**)&pNFl,  g_NFl);
    cudaGetSymbolAddress((void**)&pmsh,  g_msh);
    cudaGetSymbolAddress((void**)&pmsl,  g_msl);
    cudaGetSymbolAddress((void**)&pHn,   g_Hn);
    cudaGetSymbolAddress((void**)&pPa1,  g_pa1);
    cudaGetSymbolAddress((void**)&pGI,   g_GI);
    cudaGetSymbolAddress((void**)&pGH,   g_GH);

    auto kBIAS3 = hmma_gemm<TEPI_BIAS, false, 3>;   // GI/GH
    auto kBIAS2 = hmma_gemm<TEPI_BIAS, false, 2>;   // Hn
    auto kRP    = hmma_gemm<TEPI_RELU, true,  1>;
    auto kDOT   = hmma_gemm<TEPI_DOT,  false, 1>;
    cudaFuncSetAttribute(kBIAS3, cudaFuncAttributeMaxDynamicSharedMemorySize, SMEM_BYTES);
    cudaFuncSetAttribute(kBIAS2, cudaFuncAttributeMaxDynamicSharedMemorySize, SMEM_BYTES);
    cudaFuncSetAttribute(kRP,    cudaFuncAttributeMaxDynamicSharedMemorySize, SMEM_BYTES);
    cudaFuncSetAttribute(kDOT,   cudaFuncAttributeMaxDynamicSharedMemorySize, SMEM_BYTES);
    cudaFuncSetAttribute(hmma_mf_re, cudaFuncAttributeMaxDynamicSharedMemorySize, 3 * 49152);

    const int n4ef = Rr * Cc / 4;
    const int n4nf = Bb * Nn * Cc / 4;
    conv_act<<<(n4ef + 255) / 256, 256>>>((const float4*)EF, (uint2*)pEFh, n4ef);
    split_f32<<<(n4nf + 255) / 256, 256>>>((const float4*)NF, (uint2*)pNFh, (uint2*)pNFl, n4nf);
    conv_weights<<<10240, 256>>>(Wm, Wl1, Wl2, Wih, Whh,
                                 pWmh, pWmNh, pWmNl, pW1h, pW2h,
                                 pWihh, pWihl, pWhhh, pWhhl);
    init_pa<<<64, 256>>>((float4*)pPa1, (float4*)out, blo);

    // Hn = NF @ Wm[:, :512]^T + bm   (2-plane; feeds fp16-rounded M)
    kBIAS2<<<dim3(4, 8, 1), 128, SMEM_BYTES>>>(pNFh, pNFl, pWmNh, pWmNl, bm,
                                               nullptr, nullptr, nullptr,
                                               pHn, 512, nullptr,
                                               nullptr, nullptr, nullptr, nullptr,
                                               nullptr, nullptr);

    // M + T1 in one fused pass over EFh
    hmma_mf_re<<<dim3(4, 512), 256, 3 * 49152>>>(pEFh, pWmh, pW1h, pHn, bl1, pMh, pTh);

    const dim3 gTC(4, 512, 1);
    // pa1 += dot(relu(T1 @ Wl2^T + bl2), Wlo)
    kDOT<<<gTC, 128, SMEM_BYTES>>>(pTh, nullptr, pW2h, nullptr, bl2, Wlo,
                                   nullptr, nullptr, nullptr, 0, pPa1,
                                   nullptr, nullptr, nullptr, nullptr,
                                   nullptr, nullptr);
    // T1' = relu(sig(pa1[perm]) * M[perm] @ Wl1^T + bl1) -> Th
    kRP<<<gTC, 128, SMEM_BYTES>>>(pMh, nullptr, pW1h, nullptr, bl1, nullptr,
                                  pPa1, pTh, nullptr, 0, nullptr,
                                  nullptr, nullptr, nullptr, nullptr,
                                  nullptr, nullptr);
    // pred_adj += dot(relu(T1' @ Wl2^T + bl2), Wlo)
    kDOT<<<gTC, 128, SMEM_BYTES>>>(pTh, nullptr, pW2h, nullptr, bl2, Wlo,
                                   nullptr, nullptr, nullptr, 0, out,
                                   nullptr, nullptr, nullptr, nullptr,
                                   nullptr, nullptr);

    msum2<<<Bb * Nn, 128>>>(pMh, out, pmsh, pmsl);
    // GI and GH in one dual launch (3-plane near-fp32)
    kBIAS3<<<dim3(12, 8, 2), 128, SMEM_BYTES>>>(pmsh, pmsl, pWihh, pWihl, bih,
                                                nullptr, nullptr, nullptr,
                                                pGI, 1536, nullptr,
                                                pNFh, pNFl, pWhhh, pWhhl,
                                                bhh, pGH);
    gru_readout<<<Bb * Nn, 256>>>(pGI, pGH, NF, Wr1, br1, Wr2, br2, out);
}

// round 11
// speedup vs baseline: 6.7274x; 1.0290x over previous
#include <cuda_runtime.h>
#include <cuda_fp16.h>
#include <math.h>
#include <stdint.h>

// ---------------------------------------------------------------------------
// GPNN_VCOCO forward — fp16 split GEMMs on warp-level mma.sync.
// R11: conv_act eliminated — the fused M+T1 kernel consumes fp32 EF
// directly (LDG+cvt+STS double-buffered A path); init_pa folded into
// conv_weights. GEMM schedule unchanged (HMMA issue ceiling).
// ---------------------------------------------------------------------------

namespace {

constexpr int Bb = 16;
constexpr int Nn = 64;
constexpr int Cc = 512;
constexpr int Rr = Bb * Nn * Nn;   // 65536

// ---------------- scratch (static device globals) ----------------
__device__ __half g_Mh [Rr * Cc];
__device__ __half g_Th [Rr * Cc];
__device__ __half g_Wmh [Cc * Cc];                 // Wm edge half, hi
__device__ __half g_WmNh[Cc * Cc], g_WmNl[Cc * Cc];// Wm node half, hi/lo
__device__ __half g_W1h [Cc * Cc];
__device__ __half g_W2h [Cc * Cc];
__device__ __half g_Wihh[3 * Cc * Cc], g_Wihl[3 * Cc * Cc];
__device__ __half g_Whhh[3 * Cc * Cc], g_Whhl[3 * Cc * Cc];
__device__ __half g_NFh [Bb * Nn * Cc], g_NFl[Bb * Nn * Cc];
__device__ __half g_msh [Bb * Nn * Cc], g_msl[Bb * Nn * Cc];
__device__ float g_Hn [Bb * Nn * Cc];
__device__ float g_pa1[Rr];
__device__ float g_GI [Bb * Nn * 3 * Cc];
__device__ float g_GH [Bb * Nn * 3 * Cc];

__device__ __forceinline__ float sigmoidf_(float x) {
    return 1.0f / (1.0f + __expf(-x));
}
__device__ __forceinline__ int permrow(int gr) {
    return (gr & ~4095) | ((gr & 63) << 6) | ((gr >> 6) & 63);
}
__device__ __forceinline__ uint32_t smem_u32(const void* p) {
    uint32_t a;
    asm("{ .reg .u64 t; cvta.to.shared.u64 t, %1; cvt.u32.u64 %0, t; }"
        : "=r"(a) : "l"(p));
    return a;
}
__device__ __forceinline__ uint32_t swz(uint32_t o) {   // 128B-row xor swizzle
    return o ^ ((o >> 3) & 0x70);
}
__device__ __forceinline__ void cp16(uint32_t saddr, const void* g) {
    asm volatile("cp.async.cg.shared.global [%0], [%1], 16;"
                 :: "r"(saddr), "l"(g) : "memory");
}
__device__ __forceinline__ void cp_commit() {
    asm volatile("cp.async.commit_group;" ::: "memory");
}
template<int N>
__device__ __forceinline__ void cp_wait() {
    asm volatile("cp.async.wait_group %0;" :: "n"(N) : "memory");
}
__device__ __forceinline__ void ldm_x4(uint32_t* r, uint32_t addr) {
    asm volatile("ldmatrix.sync.aligned.m8n8.x4.shared.b16 {%0,%1,%2,%3}, [%4];"
                 : "=r"(r[0]), "=r"(r[1]), "=r"(r[2]), "=r"(r[3]) : "r"(addr));
}
__device__ __forceinline__ void mma16816(float* c, const uint32_t* a,
                                         uint32_t b0, uint32_t b1) {
    asm volatile(
        "mma.sync.aligned.m16n8k16.row.col.f32.f16.f16.f32 "
        "{%0,%1,%2,%3}, {%4,%5,%6,%7}, {%8,%9}, {%0,%1,%2,%3};"
        : "+f"(c[0]), "+f"(c[1]), "+f"(c[2]), "+f"(c[3])
        : "r"(a[0]), "r"(a[1]), "r"(a[2]), "r"(a[3]), "r"(b0), "r"(b1));
}

enum { TEPI_MFUSE = 0, TEPI_RELU = 1, TEPI_DOT = 2, TEPI_BIAS = 3 };

constexpr int STAGE_BYTES = 32768;           // 16KB A + 16KB B
constexpr int SMEM_BYTES  = 3 * STAGE_BYTES; // 96KB -> 2 CTAs/SM

// ---------------------------------------------------------------------------
// Generic HMMA GEMM: CTA 128x128, 128 thr, warp 64x64, 3-stage cp.async.
// Dual mode via blockIdx.z for GI+GH.
// ---------------------------------------------------------------------------
template<int EPI, bool PERM, int PLANES>
__global__ void __launch_bounds__(128, 2)
hmma_gemm(const __half* AhP, const __half* AlP,
          const __half* BhP, const __half* BlP,
          const float* biasP,
          const float* extra,               // Wlo (DOT)
          const float* pa,                  // pa1 logits (PERM)
          __half* Ch,                       // fp16 out (RELU)
          float* CfP, int ldC,              // fp32 out (BIAS)
          float* dotOut,                    // atomic target (DOT)
          const __half* A2h, const __half* A2l,
          const __half* B2h, const __half* B2l,
          const float* bias2, float* Cf2)
{
    extern __shared__ __align__(128) uint8_t smem[];
    const uint32_t sBase = smem_u32(smem);
    constexpr int NCHUNK = PLANES * 8;

    const bool sec = (blockIdx.z == 1);
    const __half* Ah = sec ? A2h : AhP;
    const __half* Al = sec ? A2l : AlP;
    const __half* Bh = sec ? B2h : BhP;
    const __half* Bl = sec ? B2l : BlP;
    const float* bias = sec ? bias2 : biasP;
    float* Cf = sec ? Cf2 : CfP;

    const int tid = threadIdx.x;
    const int wid = tid >> 5, lane = tid & 31;
    const int warp_m = wid & 1, warp_n = wid >> 1;
    const int rowBase = blockIdx.y << 7;
    const int colBase = blockIdx.x << 7;

    const int lrow = tid >> 3, lseg = tid & 7;
    uint32_t aOff[8], bOff[8], sOff[8];
#pragma unroll
    for (int i = 0; i < 8; i++) {
        const int row = lrow + i * 16;
        int sr = rowBase + row;
        if (PERM) sr = permrow(sr);
        aOff[i] = (uint32_t)sr * 512u + lseg * 8;
        bOff[i] = (uint32_t)(colBase + row) * 512u + lseg * 8;
        sOff[i] = swz((uint32_t)row * 128 + lseg * 16);
    }

    auto load_stage = [&](int st, int ch) {
        const int p  = ch >> 3;
        const int kb = (ch & 7) * 64;
        const __half* Ap = (p == 1) ? Al : Ah;
        const __half* Bp = (p == 2) ? Bl : Bh;
        const uint32_t sa = sBase + st * STAGE_BYTES;
        const uint32_t sb = sa + 16384;
#pragma unroll
        for (int i = 0; i < 8; i++) {
            cp16(sa + sOff[i], Ap + aOff[i] + kb);
            cp16(sb + sOff[i], Bp + bOff[i] + kb);
        }
        cp_commit();
    };

    load_stage(0, 0);
    load_stage(1, 1);

    float acc[4][8][4];
#pragma unroll
    for (int mt = 0; mt < 4; mt++)
#pragma unroll
        for (int nf = 0; nf < 8; nf++)
#pragma unroll
            for (int j = 0; j < 4; j++) acc[mt][nf][j] = 0.0f;

    const int aRow = warp_m * 64 + ((lane >> 3) & 1) * 8 + (lane & 7);
    const uint32_t aK = (uint32_t)(lane >> 4) * 16;
    const int bRow = warp_n * 64 + (lane >> 4) * 8 + (lane & 7);
    const uint32_t bK = (uint32_t)((lane >> 3) & 1) * 16;

#pragma unroll 1
    for (int ch = 0; ch < NCHUNK; ch++) {
        if (ch < NCHUNK - 1) cp_wait<1>(); else cp_wait<0>();
        __syncthreads();
        if (ch + 2 < NCHUNK) load_stage((ch + 2) % 3, ch + 2);

        const uint32_t sa = sBase + (ch % 3) * STAGE_BYTES;
        const uint32_t sb = sa + 16384;
#pragma unroll
        for (int ks = 0; ks < 4; ks++) {
            uint32_t a[4][4], b[4][4];
#pragma unroll
            for (int mt = 0; mt < 4; mt++)
                ldm_x4(a[mt], sa + swz((uint32_t)(aRow + mt * 16) * 128 + ks * 32 + aK));
#pragma unroll
            for (int pr = 0; pr < 4; pr++)
                ldm_x4(b[pr], sb + swz((uint32_t)(bRow + pr * 16) * 128 + ks * 32 + bK));
#pragma unroll
            for (int mt = 0; mt < 4; mt++)
#pragma unroll
                for (int nf = 0; nf < 8; nf++)
                    mma16816(acc[mt][nf], a[mt],
                             b[nf >> 1][(nf & 1) * 2], b[nf >> 1][(nf & 1) * 2 + 1]);
        }
    }

    const int r0 = rowBase + warp_m * 64 + (lane >> 2);
    const int c0 = colBase + warp_n * 64 + (lane & 3) * 2;

    if (EPI == TEPI_DOT) {
        float dsum[4][2];
#pragma unroll
        for (int mt = 0; mt < 4; mt++) { dsum[mt][0] = 0.f; dsum[mt][1] = 0.f; }
#pragma unroll
        for (int mt = 0; mt < 4; mt++)
#pragma unroll
            for (int nf = 0; nf < 8; nf++) {
                const int gc = c0 + nf * 8;
                const float b0v = bias[gc], b1v = bias[gc + 1];
                const float w0v = extra[gc], w1v = extra[gc + 1];
                dsum[mt][0] += fmaxf(acc[mt][nf][0] + b0v, 0.f) * w0v
                             + fmaxf(acc[mt][nf][1] + b1v, 0.f) * w1v;
                dsum[mt][1] += fmaxf(acc[mt][nf][2] + b0v, 0.f) * w0v
                             + fmaxf(acc[mt][nf][3] + b1v, 0.f) * w1v;
            }
#pragma unroll
        for (int mt = 0; mt < 4; mt++)
#pragma unroll
            for (int h = 0; h < 2; h++) {
                float v = dsum[mt][h];
                v += __shfl_xor_sync(0xffffffffu, v, 1);
                v += __shfl_xor_sync(0xffffffffu, v, 2);
                if ((lane & 3) == 0)
                    atomicAdd(dotOut + r0 + mt * 16 + h * 8, v);
            }
    } else if (EPI == TEPI_BIAS) {
#pragma unroll
        for (int mt = 0; mt < 4; mt++)
#pragma unroll
            for (int h = 0; h < 2; h++) {
                const int row = r0 + mt * 16 + h * 8;
                float2* orow = reinterpret_cast<float2*>(Cf + (size_t)row * ldC);
#pragma unroll
                for (int nf = 0; nf < 8; nf++) {
                    const int gc = c0 + nf * 8;
                    orow[gc >> 1] = make_float2(acc[mt][nf][h * 2] + bias[gc],
                                                acc[mt][nf][h * 2 + 1] + bias[gc + 1]);
                }
            }
    } else {   // RELU (with optional PERM scale)
#pragma unroll
        for (int mt = 0; mt < 4; mt++)
#pragma unroll
            for (int h = 0; h < 2; h++) {
                const int row = r0 + mt * 16 + h * 8;
                float s = 1.0f;
                if (PERM) s = sigmoidf_(pa[permrow(row)]);
                uint32_t* oh = reinterpret_cast<uint32_t*>(Ch) + ((size_t)row * 512 >> 1);
#pragma unroll
                for (int nf = 0; nf < 8; nf++) {
                    const int gc = c0 + nf * 8;
                    const float y0 = fmaxf(fmaf(s, acc[mt][nf][h * 2],     bias[gc]),     0.0f);
                    const float y1 = fmaxf(fmaf(s, acc[mt][nf][h * 2 + 1], bias[gc + 1]), 0.0f);
                    __half2 h2;
                    h2.x = __float2half_rn(y0);
                    h2.y = __float2half_rn(y1);
                    oh[gc >> 1] = *reinterpret_cast<uint32_t*>(&h2);
                }
            }
    }
}

// ---------------------------------------------------------------------------
// Fused M + T1 kernel, fp32 A input (no pre-conversion pass):
//   M  = relu(EF @ WmE^T + Hn[b,w])   -> Mh
//   T1 = relu(EF @ W1^T  + bl1)       -> Th
// A path: LDG float4 -> cvt fp16 -> STS, double-buffered (2 x 16KB slots,
// one chunk ahead). B streams: 3-stage cp.async (3 x 32KB). 256 thr =
// 8 warps (2m x 4n), warp tile 64x32 per output. smem 128KB, 1 CTA/SM.
// ---------------------------------------------------------------------------
__global__ void __launch_bounds__(256, 1)
hmma_mf_re(const float* __restrict__ EF,
           const __half* __restrict__ WmE, const __half* __restrict__ W1,
           const float* __restrict__ Hn, const float* __restrict__ bl1,
           __half* __restrict__ Mh, __half* __restrict__ Th)
{
    extern __shared__ __align__(128) uint8_t smem[];
    const uint32_t sA0 = smem_u32(smem);     // 2 x 16KB A slots
    const uint32_t sB0 = sA0 + 32768;        // 3 x 32KB B stages (BM+BT)

    const int tid = threadIdx.x;
    const int wid = tid >> 5, lane = tid & 31;
    const int warp_m = wid & 1, warp_n = wid >> 1;   // 2 x 4
    const int rowBase = blockIdx.y << 7;
    const int colBase = blockIdx.x << 7;

    const int lrow = tid >> 3, lseg = tid & 7;       // 32 rows/sweep
    uint32_t aIdx[4], bOff[4], sOff[4];
#pragma unroll
    for (int i = 0; i < 4; i++) {
        const int row = lrow + i * 32;
        aIdx[i] = ((uint32_t)(rowBase + row) * 512u + lseg * 8) >> 2;  // float4 idx
        bOff[i] = (uint32_t)(colBase + row) * 512u + lseg * 8;
        sOff[i] = swz((uint32_t)row * 128 + lseg * 16);
    }
    const float4* EF4 = reinterpret_cast<const float4*>(EF);

    float4 rA[8];
    auto ldgA = [&](int ch) {
        const uint32_t kq = (uint32_t)(ch * 16);    // 64 halves = 16 float4
#pragma unroll
        for (int i = 0; i < 4; i++) {
            rA[i * 2 + 0] = EF4[aIdx[i] + kq + 0];
            rA[i * 2 + 1] = EF4[aIdx[i] + kq + 1];
        }
    };
    auto stsA = [&](int slot) {
#pragma unroll
        for (int i = 0; i < 4; i++) {
            __half2 p0, p1, p2, p3;
            p0.x = __float2half_rn(rA[i*2].x);   p0.y = __float2half_rn(rA[i*2].y);
            p1.x = __float2half_rn(rA[i*2].z);   p1.y = __float2half_rn(rA[i*2].w);
            p2.x = __float2half_rn(rA[i*2+1].x); p2.y = __float2half_rn(rA[i*2+1].y);
            p3.x = __float2half_rn(rA[i*2+1].z); p3.y = __float2half_rn(rA[i*2+1].w);
            const uint4 v = make_uint4(*reinterpret_cast<uint32_t*>(&p0),
                                       *reinterpret_cast<uint32_t*>(&p1),
                                       *reinterpret_cast<uint32_t*>(&p2),
                                       *reinterpret_cast<uint32_t*>(&p3));
            *reinterpret_cast<uint4*>(smem + slot * 16384 + sOff[i]) = v;
        }
    };
    auto loadB = [&](int st, int ch) {
        const int kb = ch * 64;
        const uint32_t sbM = sB0 + st * 32768;
        const uint32_t sbT = sbM + 16384;
#pragma unroll
        for (int i = 0; i < 4; i++) {
            cp16(sbM + sOff[i], WmE + bOff[i] + kb);
            cp16(sbT + sOff[i], W1  + bOff[i] + kb);
        }
        cp_commit();
    };

    ldgA(0); stsA(0);
    ldgA(1);
    loadB(0, 0); loadB(1, 1);

    float accM[4][4][4], accT[4][4][4];
#pragma unroll
    for (int mt = 0; mt < 4; mt++)
#pragma unroll
        for (int nf = 0; nf < 4; nf++)
#pragma unroll
            for (int j = 0; j < 4; j++) { accM[mt][nf][j] = 0.0f; accT[mt][nf][j] = 0.0f; }

    const int aRow = warp_m * 64 + ((lane >> 3) & 1) * 8 + (lane & 7);
    const uint32_t aK = (uint32_t)(lane >> 4) * 16;
    const int bRow = warp_n * 32 + (lane >> 4) * 8 + (lane & 7);
    const uint32_t bK = (uint32_t)((lane >> 3) & 1) * 16;

#pragma unroll 1
    for (int ch = 0; ch < 8; ch++) {
        if (ch < 7) cp_wait<1>(); else cp_wait<0>();
        __syncthreads();
        if (ch + 1 < 8) stsA((ch + 1) & 1);
        if (ch + 2 < 8) { ldgA(ch + 2); loadB((ch + 2) % 3, ch + 2); }

        const uint32_t sa  = sA0 + (ch & 1) * 16384;
        const uint32_t sbM = sB0 + (ch % 3) * 32768;
        const uint32_t sbT = sbM + 16384;
#pragma unroll
        for (int ks = 0; ks < 4; ks++) {
            uint32_t a[4][4], bM[2][4], bT[2][4];
#pragma unroll
            for (int mt = 0; mt < 4; mt++)
                ldm_x4(a[mt], sa + swz((uint32_t)(aRow + mt * 16) * 128 + ks * 32 + aK));
#pragma unroll
            for (int pr = 0; pr < 2; pr++) {
                const uint32_t off = swz((uint32_t)(bRow + pr * 16) * 128 + ks * 32 + bK);
                ldm_x4(bM[pr], sbM + off);
                ldm_x4(bT[pr], sbT + off);
            }
#pragma unroll
            for (int mt = 0; mt < 4; mt++)
#pragma unroll
                for (int nf = 0; nf < 4; nf++) {
                    mma16816(accM[mt][nf], a[mt],
                             bM[nf >> 1][(nf & 1) * 2], bM[nf >> 1][(nf & 1) * 2 + 1]);
                    mma16816(accT[mt][nf], a[mt],
                             bT[nf >> 1][(nf & 1) * 2], bT[nf >> 1][(nf & 1) * 2 + 1]);
                }
        }
    }

    const int r0 = rowBase + warp_m * 64 + (lane >> 2);
    const int c0 = colBase + warp_n * 32 + (lane & 3) * 2;
#pragma unroll
    for (int mt = 0; mt < 4; mt++)
#pragma unroll
        for (int h = 0; h < 2; h++) {
            const int row = r0 + mt * 16 + h * 8;
            const float* hnrow = Hn + (size_t)(((row >> 12) << 6) | (row & 63)) * 512;
            uint32_t* om = reinterpret_cast<uint32_t*>(Mh) + ((size_t)row * 512 >> 1);
            uint32_t* ot = reinterpret_cast<uint32_t*>(Th) + ((size_t)row * 512 >> 1);
#pragma unroll
            for (int nf = 0; nf < 4; nf++) {
                const int gc = c0 + nf * 8;
                const float m0 = fmaxf(accM[mt][nf][h * 2]     + hnrow[gc],     0.0f);
                const float m1 = fmaxf(accM[mt][nf][h * 2 + 1] + hnrow[gc + 1], 0.0f);
                const float t0 = fmaxf(accT[mt][nf][h * 2]     + bl1[gc],       0.0f);
                const float t1 = fmaxf(accT[mt][nf][h * 2 + 1] + bl1[gc + 1],   0.0f);
                __half2 hm, ht;
                hm.x = __float2half_rn(m0); hm.y = __float2half_rn(m1);
                ht.x = __float2half_rn(t0); ht.y = __float2half_rn(t1);
                om[gc >> 1] = *reinterpret_cast<uint32_t*>(&hm);
                ot[gc >> 1] = *reinterpret_cast<uint32_t*>(&ht);
            }
        }
}

// ---------------------------------------------------------------------------
// conversions
// ---------------------------------------------------------------------------
__global__ void split_f32(const float4* __restrict__ in,
                          uint2* __restrict__ hi, uint2* __restrict__ lo, int n4)
{
    const int i = blockIdx.x * blockDim.x + threadIdx.x;
    if (i >= n4) return;
    const float4 v = in[i];
    __half2 hA, hB, lA, lB;
    hA.x = __float2half_rn(v.x); hA.y = __float2half_rn(v.y);
    hB.x = __float2half_rn(v.z); hB.y = __float2half_rn(v.w);
    lA.x = __float2half_rn(v.x - __half2float(hA.x));
    lA.y = __float2half_rn(v.y - __half2float(hA.y));
    lB.x = __float2half_rn(v.z - __half2float(hB.x));
    lB.y = __float2half_rn(v.w - __half2float(hB.y));
    hi[i] = make_uint2(*reinterpret_cast<uint32_t*>(&hA), *reinterpret_cast<uint32_t*>(&hB));
    lo[i] = make_uint2(*reinterpret_cast<uint32_t*>(&lA), *reinterpret_cast<uint32_t*>(&lB));
}

// All weight conversions + pa-accumulator init in one launch.
// Segments (S = 256K elements):
//   [0,S)      Wm edge -> Wmh      [S,2S)   Wm node -> WmNh/WmNl
//   [2S,3S)    Wl1 -> W1h          [3S,4S)  Wl2 -> W2h
//   [4S,7S)    Wih -> Wihh/Wihl    [7S,10S) Whh -> Whhh/Whhl
//   [10S,10S+16384) pa1/out float4 fill with blo
__global__ void conv_weights(const float* __restrict__ Wm,
                             const float* __restrict__ Wl1,
                             const float* __restrict__ Wl2,
                             const float* __restrict__ Wih,
                             const float* __restrict__ Whh,
                             __half* __restrict__ Wmh,
                             __half* __restrict__ WmNh, __half* __restrict__ WmNl,
                             __half* __restrict__ W1h,  __half* __restrict__ W2h,
                             __half* __restrict__ Wihh, __half* __restrict__ Wihl,
                             __half* __restrict__ Whhh, __half* __restrict__ Whhl,
                             const float* __restrict__ blo,
                             float4* __restrict__ pa1, float4* __restrict__ pa2)
{
    const int idx = blockIdx.x * blockDim.x + threadIdx.x;
    constexpr int S = 512 * 512;
    if (idx >= 10 * S) {
        const int o = idx - 10 * S;
        if (o < Rr / 4) {
            const float v = blo[0];
            const float4 f = make_float4(v, v, v, v);
            pa1[o] = f;
            pa2[o] = f;
        }
        return;
    }
    float x;
    __half* hi;
    __half* lo = nullptr;
    int off;
    if (idx < S) {
        off = idx;
        x = Wm[(size_t)(off >> 9) * 1024 + 512 + (off & 511)];
        hi = Wmh + off;
    } else if (idx < 2 * S) {
        off = idx - S;
        x = Wm[(size_t)(off >> 9) * 1024 + (off & 511)];
        hi = WmNh + off; lo = WmNl + off;
    } else if (idx < 3 * S) {
        off = idx - 2 * S;
        x = Wl1[off];
        hi = W1h + off;
    } else if (idx < 4 * S) {
        off = idx - 3 * S;
        x = Wl2[off];
        hi = W2h + off;
    } else if (idx < 7 * S) {
        off = idx - 4 * S;
        x = Wih[off];
        hi = Wihh + off; lo = Wihl + off;
    } else {
        off = idx - 7 * S;
        x = Whh[off];
        hi = Whhh + off; lo = Whhl + off;
    }
    const __half h = __float2half_rn(x);
    *hi = h;
    if (lo) *lo = __float2half_rn(x - __half2float(h));
}

// msum[b,v,:] = sum_w sig(pa2[b,v,w]) * Mh[(b,v,w), :]  -> fp16 hi/lo
__global__ void msum2(const __half* __restrict__ Mh,
                      const float* __restrict__ pa2,
                      __half* __restrict__ msh, __half* __restrict__ msl)
{
    const int bv = blockIdx.x;
    const int t  = threadIdx.x;   // 128
    __shared__ float sg[64];
    if (t < 64) sg[t] = sigmoidf_(pa2[bv * 64 + t]);
    __syncthreads();
    const uint32_t* mh = reinterpret_cast<const uint32_t*>(Mh + (size_t)bv * 64 * 512);
    const int c = t * 2;
    float a0 = 0.f, a1 = 0.f, a2 = 0.f, a3 = 0.f;
#pragma unroll 4
    for (int w = 0; w < 64; w++) {
        const float s = sg[w];
        const uint32_t h0 = mh[w * 256 + c];
        const uint32_t h1 = mh[w * 256 + c + 1];
        const __half2 H0 = *reinterpret_cast<const __half2*>(&h0);
        const __half2 H1 = *reinterpret_cast<const __half2*>(&h1);
        a0 = fmaf(s, __half2float(H0.x), a0);
        a1 = fmaf(s, __half2float(H0.y), a1);
        a2 = fmaf(s, __half2float(H1.x), a2);
        a3 = fmaf(s, __half2float(H1.y), a3);
    }
    __half2 h2a, h2b, l2a, l2b;
    h2a.x = __float2half_rn(a0); h2a.y = __float2half_rn(a1);
    h2b.x = __float2half_rn(a2); h2b.y = __float2half_rn(a3);
    l2a.x = __float2half_rn(a0 - __half2float(h2a.x));
    l2a.y = __float2half_rn(a1 - __half2float(h2a.y));
    l2b.x = __float2half_rn(a2 - __half2float(h2b.x));
    l2b.y = __float2half_rn(a3 - __half2float(h2b.y));
    uint2* oh = reinterpret_cast<uint2*>(msh + (size_t)bv * 512) + t;
    uint2* ol = reinterpret_cast<uint2*>(msl + (size_t)bv * 512) + t;
    *oh = make_uint2(*reinterpret_cast<uint32_t*>(&h2a), *reinterpret_cast<uint32_t*>(&h2b));
    *ol = make_uint2(*reinterpret_cast<uint32_t*>(&l2a), *reinterpret_cast<uint32_t*>(&l2b));
}

__global__ void gru_readout(const float* __restrict__ GI,
                            const float* __restrict__ GH,
                            const float* __restrict__ NF,
                            const float* __restrict__ Wr1, const float* __restrict__ br1,
                            const float* __restrict__ Wr2, const float* __restrict__ br2,
                            float* __restrict__ out)
{
    const int row = blockIdx.x;
    __shared__ float hn[512];
    const int t = threadIdx.x;   // 256
    const float* gi = GI + (size_t)row * 1536;
    const float* gh = GH + (size_t)row * 1536;
    const float* h  = NF + (size_t)row * 512;
    for (int d = t; d < 512; d += 256) {
        const float r = sigmoidf_(gi[d] + gh[d]);
        const float z = sigmoidf_(gi[512 + d] + gh[512 + d]);
        const float n = tanhf(gi[1024 + d] + r * gh[1024 + d]);
        hn[d] = (1.0f - z) * n + z * h[d];
    }
    __syncthreads();
    const int warp = t >> 5, lane = t & 31;
    for (int o = warp; o < 28; o += 8) {
        const float* Wr = (o < 26) ? (Wr1 + o * 512) : (Wr2 + (o - 26) * 512);
        float acc = 0.0f;
        for (int k = lane; k < 512; k += 32) acc = fmaf(hn[k], Wr[k], acc);
#pragma unroll
        for (int off = 16; off; off >>= 1)
            acc += __shfl_down_sync(0xffffffffu, acc, off);
        if (lane == 0) {
            if (o < 26) out[65536 + row * 26 + o]               = acc + br1[o];
            else        out[65536 + 26624 + row * 2 + (o - 26)] = acc + br2[o - 26];
        }
    }
}

} // namespace

extern "C" void kernel_launch(void* const* d_in, const int* /*in_sizes*/, int /*n_in*/,
                              void* d_out, int /*out_size*/)
{
    const float* EF  = (const float*)d_in[0];
    const float* NF  = (const float*)d_in[1];
    const float* Wm  = (const float*)d_in[4];
    const float* bm  = (const float*)d_in[5];
    const float* Wl1 = (const float*)d_in[6];
    const float* bl1 = (const float*)d_in[7];
    const float* Wl2 = (const float*)d_in[8];
    const float* bl2 = (const float*)d_in[9];
    const float* Wlo = (const float*)d_in[10];
    const float* blo = (const float*)d_in[11];
    const float* Wih = (const float*)d_in[12];
    const float* bih = (const float*)d_in[13];
    const float* Whh = (const float*)d_in[14];
    const float* bhh = (const float*)d_in[15];
    const float* Wr1 = (const float*)d_in[16];
    const float* br1 = (const float*)d_in[17];
    const float* Wr2 = (const float*)d_in[18];
    const float* br2 = (const float*)d_in[19];
    float* out = (float*)d_out;

    __half *pMh, *pTh;
    __half *pWmh, *pWmNh, *pWmNl, *pW1h, *pW2h;
    __half *pWihh, *pWihl, *pWhhh, *pWhhl, *pNFh, *pNFl, *pmsh, *pmsl;
    float *pHn, *pPa1, *pGI, *pGH;
    cudaGetSymbolAddress((void**)&pMh,   g_Mh);
    cudaGetSymbolAddress((void**)&pTh,   g_Th);
    cudaGetSymbolAddress((void**)&pWmh,  g_Wmh);
    cudaGetSymbolAddress((void**)&pWmNh, g_WmNh);
    cudaGetSymbolAddress((void**)&pWmNl, g_WmNl);
    cudaGetSymbolAddress((void**)&pW1h,  g_W1h);
    cudaGetSymbolAddress((void**)&pW2h,  g_W2h);
    cudaGetSymbolAddress((void**)&pWihh, g_Wihh);
    cudaGetSymbolAddress((void**)&pWihl, g_Wihl);
    cudaGetSymbolAddress((void**)&pWhhh, g_Whhh);
    cudaGetSymbolAddress((void**)&pWhhl, g_Whhl);
    cudaGetSymbolAddress((void**)&pNFh,  g_NFh);
    cudaGetSymbolAddress((void**)&pNFl,  g_NFl);
    cudaGetSymbolAddress((void**)&pmsh,  g_msh);
    cudaGetSymbolAddress((void**)&pmsl,  g_msl);
    cudaGetSymbolAddress((void**)&pHn,   g_Hn);
    cudaGetSymbolAddress((void**)&pPa1,  g_pa1);
    cudaGetSymbolAddress((void**)&pGI,   g_GI);
    cudaGetSymbolAddress((void**)&pGH,   g_GH);

    auto kBIAS3 = hmma_gemm<TEPI_BIAS, false, 3>;   // GI/GH
    auto kBIAS2 = hmma_gemm<TEPI_BIAS, false, 2>;   // Hn
    auto kRP    = hmma_gemm<TEPI_RELU, true,  1>;
    auto kDOT   = hmma_gemm<TEPI_DOT,  false, 1>;
    cudaFuncSetAttribute(kBIAS3, cudaFuncAttributeMaxDynamicSharedMemorySize, SMEM_BYTES);
    cudaFuncSetAttribute(kBIAS2, cudaFuncAttributeMaxDynamicSharedMemorySize, SMEM_BYTES);
    cudaFuncSetAttribute(kRP,    cudaFuncAttributeMaxDynamicSharedMemorySize, SMEM_BYTES);
    cudaFuncSetAttribute(kDOT,   cudaFuncAttributeMaxDynamicSharedMemorySize, SMEM_BYTES);
    cudaFuncSetAttribute(hmma_mf_re, cudaFuncAttributeMaxDynamicSharedMemorySize, 131072);

    const int n4nf = Bb * Nn * Cc / 4;
    split_f32<<<(n4nf + 255) / 256, 256>>>((const float4*)NF, (uint2*)pNFh, (uint2*)pNFl, n4nf);
    conv_weights<<<10304, 256>>>(Wm, Wl1, Wl2, Wih, Whh,
                                 pWmh, pWmNh, pWmNl, pW1h, pW2h,
                                 pWihh, pWihl, pWhhh, pWhhl,
                                 blo, (float4*)pPa1, (float4*)out);

    // Hn = NF @ Wm[:, :512]^T + bm   (2-plane; feeds fp16-rounded M)
    kBIAS2<<<dim3(4, 8, 1), 128, SMEM_BYTES>>>(pNFh, pNFl, pWmNh, pWmNl, bm,
                                               nullptr, nullptr, nullptr,
                                               pHn, 512, nullptr,
                                               nullptr, nullptr, nullptr, nullptr,
                                               nullptr, nullptr);

    // M + T1 in one fused pass, consuming fp32 EF directly
    hmma_mf_re<<<dim3(4, 512), 256, 131072>>>(EF, pWmh, pW1h, pHn, bl1, pMh, pTh);

    const dim3 gTC(4, 512, 1);
    // pa1 += dot(relu(T1 @ Wl2^T + bl2), Wlo)
    kDOT<<<gTC, 128, SMEM_BYTES>>>(pTh, nullptr, pW2h, nullptr, bl2, Wlo,
                                   nullptr, nullptr, nullptr, 0, pPa1,
                                   nullptr, nullptr, nullptr, nullptr,
                                   nullptr, nullptr);
    // T1' = relu(sig(pa1[perm]) * M[perm] @ Wl1^T + bl1) -> Th
    kRP<<<gTC, 128, SMEM_BYTES>>>(pMh, nullptr, pW1h, nullptr, bl1, nullptr,
                                  pPa1, pTh, nullptr, 0, nullptr,
                                  nullptr, nullptr, nullptr, nullptr,
                                  nullptr, nullptr);
    // pred_adj += dot(relu(T1' @ Wl2^T + bl2), Wlo)
    kDOT<<<gTC, 128, SMEM_BYTES>>>(pTh, nullptr, pW2h, nullptr, bl2, Wlo,
                                   nullptr, nullptr, nullptr, 0, out,
                                   nullptr, nullptr, nullptr, nullptr,
                                   nullptr, nullptr);

    msum2<<<Bb * Nn, 128>>>(pMh, out, pmsh, pmsl);
    // GI and GH in one dual launch (3-plane near-fp32)
    kBIAS3<<<dim3(12, 8, 2), 128, SMEM_BYTES>>>(pmsh, pmsl, pWihh, pWihl, bih,
                                                nullptr, nullptr, nullptr,
                                                pGI, 1536, nullptr,
                                                pNFh, pNFl, pWhhh, pWhhl,
                                                bhh, pGH);
    gru_readout<<<Bb * Nn, 256>>>(pGI, pGH, NF, Wr1, br1, Wr2, br2, out);
}